// round 1
// baseline (speedup 1.0000x reference)
#include <cuda_runtime.h>
#include <math.h>

#define N_NODES 20000
#define E_EDGES 320000
#define ET      (E_EDGES + N_NODES)   /* 340000 with self loops */
#define IN_DIM  768
#define HID     256
#define H1      3
#define F1      (H1 * HID)            /* 768 */

/* ---------------- scratch (device globals, no allocs allowed) ------------- */
__device__ float g_xp1[(size_t)N_NODES * F1];    /* x @ W1            */
__device__ float g_h  [(size_t)N_NODES * F1];    /* elu(layer1 out)   */
__device__ float g_xp2[(size_t)N_NODES * HID];   /* h @ W2            */
__device__ float g_asrc1[N_NODES * H1];
__device__ float g_adst1[N_NODES * H1];
__device__ float g_asrc2[N_NODES];
__device__ float g_adst2[N_NODES];
__device__ int   g_deg[N_NODES];
__device__ int   g_rowptr[N_NODES + 1];
__device__ int   g_cursor[N_NODES];
__device__ int   g_col[ET];
__device__ float g_alpha[(size_t)ET * H1];
__device__ int   g_is64;

/* ---------------- small helpers ------------------------------------------ */
__device__ __forceinline__ float warpSum(float v) {
    #pragma unroll
    for (int o = 16; o; o >>= 1) v += __shfl_xor_sync(0xffffffffu, v, o);
    return v;
}
__device__ __forceinline__ float warpMax(float v) {
    #pragma unroll
    for (int o = 16; o; o >>= 1) v = fmaxf(v, __shfl_xor_sync(0xffffffffu, v, o));
    return v;
}

/* ---------------- edge dtype detection (int64 vs int32) ------------------- */
__global__ void detect_kernel(const int* ei32) {
    __shared__ int any;
    if (threadIdx.x == 0) any = 0;
    __syncthreads();
    int v = 0;
    for (int i = threadIdx.x; i < 1024; i += blockDim.x)
        v |= ei32[2 * i + 1];       /* high words if int64 -> all zero */
    if (v) atomicOr(&any, 1);
    __syncthreads();
    if (threadIdx.x == 0) g_is64 = (any == 0) ? 1 : 0;
}

__device__ __forceinline__ int edge_at(const void* ei, long long idx) {
    if (g_is64) return (int)((const long long*)ei)[idx];
    return ((const int*)ei)[idx];
}

/* ---------------- CSR build ----------------------------------------------- */
__global__ void zero_deg_kernel() {
    int i = blockIdx.x * blockDim.x + threadIdx.x;
    if (i < N_NODES) g_deg[i] = 0;
}

__global__ void count_kernel(const void* ei) {
    int e = blockIdx.x * blockDim.x + threadIdx.x;
    if (e >= ET) return;
    int d = (e < E_EDGES) ? edge_at(ei, (long long)E_EDGES + e) : (e - E_EDGES);
    atomicAdd(&g_deg[d], 1);
}

__global__ void scan_kernel() {   /* one block, 1024 threads */
    __shared__ int s[1024];
    const int CH = 20;            /* 1024*20 >= 20000 */
    int t = threadIdx.x;
    int base = t * CH;
    int sum = 0;
    for (int i = 0; i < CH; i++) {
        int idx = base + i;
        if (idx < N_NODES) sum += g_deg[idx];
    }
    s[t] = sum;
    __syncthreads();
    for (int off = 1; off < 1024; off <<= 1) {
        int v = (t >= off) ? s[t - off] : 0;
        __syncthreads();
        s[t] += v;
        __syncthreads();
    }
    int run = (t == 0) ? 0 : s[t - 1];
    for (int i = 0; i < CH; i++) {
        int idx = base + i;
        if (idx < N_NODES) {
            g_rowptr[idx] = run;
            g_cursor[idx] = run;
            run += g_deg[idx];
        }
    }
    if (t == 1023) g_rowptr[N_NODES] = s[1023];
}

__global__ void scatter_kernel(const void* ei) {
    int e = blockIdx.x * blockDim.x + threadIdx.x;
    if (e >= ET) return;
    int s, d;
    if (e < E_EDGES) {
        s = edge_at(ei, e);
        d = edge_at(ei, (long long)E_EDGES + e);
    } else {
        s = d = e - E_EDGES;
    }
    int slot = atomicAdd(&g_cursor[d], 1);
    g_col[slot] = s;
}

/* ---------------- SGEMM: C[M,N] = A[M,K] @ B[K,N] (fp32 tiled) ------------ */
/* BM=128 BN=128 BK=8, 256 threads, 8x8 per thread. N%128==0, K%8==0, M ragged */
__global__ __launch_bounds__(256)
void sgemm_kernel(const float* __restrict__ A, const float* __restrict__ B,
                  float* __restrict__ C, int M, int N, int K) {
    __shared__ float As[8][128];
    __shared__ float Bs[8][128];
    int t = threadIdx.x;
    int rowBase = blockIdx.y * 128;
    int colBase = blockIdx.x * 128;

    int arow = t >> 1;            /* 0..127 */
    int acol = (t & 1) * 4;       /* 0 or 4 */
    int brl  = t >> 5;            /* 0..7   */
    int bcl  = (t & 31) * 4;      /* 0..124 */

    int trow = (t >> 4) * 8;
    int tcol = (t & 15) * 8;

    float acc[8][8];
    #pragma unroll
    for (int i = 0; i < 8; i++)
        #pragma unroll
        for (int j = 0; j < 8; j++) acc[i][j] = 0.f;

    for (int k0 = 0; k0 < K; k0 += 8) {
        int gr = rowBase + arow;
        float4 av = make_float4(0.f, 0.f, 0.f, 0.f);
        if (gr < M) av = *(const float4*)(A + (size_t)gr * K + k0 + acol);
        As[acol + 0][arow] = av.x;
        As[acol + 1][arow] = av.y;
        As[acol + 2][arow] = av.z;
        As[acol + 3][arow] = av.w;
        float4 bv = *(const float4*)(B + (size_t)(k0 + brl) * N + colBase + bcl);
        *(float4*)(&Bs[brl][bcl]) = bv;
        __syncthreads();
        #pragma unroll
        for (int k = 0; k < 8; k++) {
            float ar[8], br[8];
            #pragma unroll
            for (int i = 0; i < 8; i++) ar[i] = As[k][trow + i];
            #pragma unroll
            for (int j = 0; j < 8; j++) br[j] = Bs[k][tcol + j];
            #pragma unroll
            for (int i = 0; i < 8; i++)
                #pragma unroll
                for (int j = 0; j < 8; j++) acc[i][j] += ar[i] * br[j];
        }
        __syncthreads();
    }

    #pragma unroll
    for (int i = 0; i < 8; i++) {
        int r = rowBase + trow + i;
        if (r < M) {
            float4 v0 = make_float4(acc[i][0], acc[i][1], acc[i][2], acc[i][3]);
            float4 v1 = make_float4(acc[i][4], acc[i][5], acc[i][6], acc[i][7]);
            *(float4*)(C + (size_t)r * N + colBase + tcol)     = v0;
            *(float4*)(C + (size_t)r * N + colBase + tcol + 4) = v1;
        }
    }
}

/* ---------------- attention coefficients: a_src/a_dst per (node, head) ---- */
__global__ void att_kernel(const float* __restrict__ xp,
                           const float* __restrict__ att_s,
                           const float* __restrict__ att_d,
                           float* __restrict__ as_out,
                           float* __restrict__ ad_out, int H) {
    int gw   = (blockIdx.x * blockDim.x + threadIdx.x) >> 5;
    int lane = threadIdx.x & 31;
    if (gw >= N_NODES * H) return;
    int n = gw / H, h = gw % H;
    const float* row = xp + (size_t)n * (H * HID) + h * HID;
    float s = 0.f, d = 0.f;
    for (int c = lane; c < HID; c += 32) {
        float v = row[c];
        s += v * att_s[h * HID + c];
        d += v * att_d[h * HID + c];
    }
    s = warpSum(s);
    d = warpSum(d);
    if (lane == 0) {
        as_out[n * H + h] = s;
        ad_out[n * H + h] = d;
    }
}

/* ---------------- segment softmax over incoming edges (warp per node) ----- */
__global__ void softmax_kernel(const float* __restrict__ asrc,
                               const float* __restrict__ adst,
                               float* __restrict__ alpha, int H) {
    int n    = (blockIdx.x * blockDim.x + threadIdx.x) >> 5;
    int lane = threadIdx.x & 31;
    if (n >= N_NODES) return;
    int st = g_rowptr[n], en = g_rowptr[n + 1];
    for (int h = 0; h < H; h++) {
        float ad = adst[n * H + h];
        float mx = -1e30f;
        for (int s = st + lane; s < en; s += 32) {
            float v = asrc[g_col[s] * H + h] + ad;
            v = (v > 0.f) ? v : 0.2f * v;          /* leaky_relu(0.2) */
            alpha[(size_t)s * H + h] = v;
            mx = fmaxf(mx, v);
        }
        mx = warpMax(mx);
        float sum = 0.f;
        for (int s = st + lane; s < en; s += 32) {
            float e = __expf(alpha[(size_t)s * H + h] - mx);
            alpha[(size_t)s * H + h] = e;
            sum += e;
        }
        sum = warpSum(sum);
        float inv = 1.f / sum;
        for (int s = st + lane; s < en; s += 32)
            alpha[(size_t)s * H + h] *= inv;
    }
}

/* ---------------- layer-1 aggregation + bias + ELU (block per node) ------- */
__global__ __launch_bounds__(256)
void agg1_kernel(const float* __restrict__ b1) {
    int n = blockIdx.x;
    int c = threadIdx.x;            /* channel within a head, 0..255 */
    int st = g_rowptr[n], en = g_rowptr[n + 1];
    float a0 = 0.f, a1 = 0.f, a2 = 0.f;
    for (int s = st; s < en; s++) {
        int src = g_col[s];
        float w0 = g_alpha[(size_t)s * 3 + 0];
        float w1 = g_alpha[(size_t)s * 3 + 1];
        float w2 = g_alpha[(size_t)s * 3 + 2];
        const float* r = g_xp1 + (size_t)src * F1;
        a0 += w0 * r[c];
        a1 += w1 * r[c + 256];
        a2 += w2 * r[c + 512];
    }
    a0 += b1[c];
    a1 += b1[c + 256];
    a2 += b1[c + 512];
    float* o = g_h + (size_t)n * F1;
    o[c]       = (a0 > 0.f) ? a0 : expm1f(a0);   /* ELU */
    o[c + 256] = (a1 > 0.f) ? a1 : expm1f(a1);
    o[c + 512] = (a2 > 0.f) ? a2 : expm1f(a2);
}

/* ---------------- layer-2 aggregation + bias -> output -------------------- */
__global__ __launch_bounds__(256)
void agg2_kernel(const float* __restrict__ b2, float* __restrict__ out) {
    int n = blockIdx.x;
    int c = threadIdx.x;
    int st = g_rowptr[n], en = g_rowptr[n + 1];
    float a = 0.f;
    for (int s = st; s < en; s++)
        a += g_alpha[s] * g_xp2[(size_t)g_col[s] * HID + c];
    out[(size_t)n * HID + c] = a + b2[c];
}

/* ---------------- launch -------------------------------------------------- */
extern "C" void kernel_launch(void* const* d_in, const int* in_sizes, int n_in,
                              void* d_out, int out_size) {
    const float* x   = (const float*)d_in[0];
    const void*  ei  = d_in[1];
    const float* W1  = (const float*)d_in[2];
    const float* as1 = (const float*)d_in[3];
    const float* ad1 = (const float*)d_in[4];
    const float* b1  = (const float*)d_in[5];
    const float* W2  = (const float*)d_in[6];
    const float* as2 = (const float*)d_in[7];
    const float* ad2 = (const float*)d_in[8];
    const float* b2  = (const float*)d_in[9];
    float* out = (float*)d_out;

    void *p_xp1, *p_h, *p_xp2, *p_as1, *p_ad1, *p_as2, *p_ad2, *p_alpha;
    cudaGetSymbolAddress(&p_xp1,   g_xp1);
    cudaGetSymbolAddress(&p_h,     g_h);
    cudaGetSymbolAddress(&p_xp2,   g_xp2);
    cudaGetSymbolAddress(&p_as1,   g_asrc1);
    cudaGetSymbolAddress(&p_ad1,   g_adst1);
    cudaGetSymbolAddress(&p_as2,   g_asrc2);
    cudaGetSymbolAddress(&p_ad2,   g_adst2);
    cudaGetSymbolAddress(&p_alpha, g_alpha);

    /* CSR build */
    detect_kernel<<<1, 256>>>((const int*)ei);
    zero_deg_kernel<<<(N_NODES + 255) / 256, 256>>>();
    count_kernel<<<(ET + 255) / 256, 256>>>(ei);
    scan_kernel<<<1, 1024>>>();
    scatter_kernel<<<(ET + 255) / 256, 256>>>(ei);

    /* layer 1 */
    sgemm_kernel<<<dim3(F1 / 128, (N_NODES + 127) / 128), 256>>>(
        x, W1, (float*)p_xp1, N_NODES, F1, IN_DIM);
    att_kernel<<<(N_NODES * H1 * 32 + 255) / 256, 256>>>(
        (const float*)p_xp1, as1, ad1, (float*)p_as1, (float*)p_ad1, H1);
    softmax_kernel<<<(N_NODES * 32 + 255) / 256, 256>>>(
        (const float*)p_as1, (const float*)p_ad1, (float*)p_alpha, H1);
    agg1_kernel<<<N_NODES, 256>>>(b1);

    /* layer 2 */
    sgemm_kernel<<<dim3(HID / 128, (N_NODES + 127) / 128), 256>>>(
        (const float*)p_h, W2, (float*)p_xp2, N_NODES, HID, F1);
    att_kernel<<<(N_NODES * 32 + 255) / 256, 256>>>(
        (const float*)p_xp2, as2, ad2, (float*)p_as2, (float*)p_ad2, 1);
    softmax_kernel<<<(N_NODES * 32 + 255) / 256, 256>>>(
        (const float*)p_as2, (const float*)p_ad2, (float*)p_alpha, 1);
    agg2_kernel<<<N_NODES, 256>>>(b2, out);
}

// round 3
// speedup vs baseline: 1.7356x; 1.7356x over previous
#include <cuda_runtime.h>
#include <cuda_bf16.h>
#include <math.h>
#include <stdint.h>

#define N_NODES 20000
#define E_EDGES 320000
#define ET      (E_EDGES + N_NODES)   /* 340000 with self loops */
#define IN_DIM  768
#define HID     256
#define H1      3
#define F1      (H1 * HID)            /* 768 */
#define KDIM    768                   /* K for both GEMMs */

/* ---------------- scratch (device globals, no allocs allowed) ------------- */
__device__ float g_xp1[(size_t)N_NODES * F1];
__device__ float g_h  [(size_t)N_NODES * F1];
__device__ float g_xp2[(size_t)N_NODES * HID];
__device__ float g_asrc1[N_NODES * H1];
__device__ float g_adst1[N_NODES * H1];
__device__ float g_asrc2[N_NODES];
__device__ float g_adst2[N_NODES];
__device__ int   g_deg[N_NODES];
__device__ int   g_rowptr[N_NODES + 1];
__device__ int   g_cursor[N_NODES];
__device__ int   g_col[ET];
__device__ float g_alpha[(size_t)ET * H1];
__device__ int   g_is64;

/* ---------------- warp helpers ------------------------------------------- */
__device__ __forceinline__ float warpSum(float v) {
    #pragma unroll
    for (int o = 16; o; o >>= 1) v += __shfl_xor_sync(0xffffffffu, v, o);
    return v;
}
__device__ __forceinline__ float warpMax(float v) {
    #pragma unroll
    for (int o = 16; o; o >>= 1) v = fmaxf(v, __shfl_xor_sync(0xffffffffu, v, o));
    return v;
}

__device__ __forceinline__ uint32_t smem_u32(const void* p) {
    uint32_t a;
    asm("{ .reg .u64 t; cvta.to.shared.u64 t, %1; cvt.u32.u64 %0, t; }"
        : "=r"(a) : "l"(p));
    return a;
}

__device__ __forceinline__ uint32_t pk(__nv_bfloat16 a, __nv_bfloat16 b) {
    uint16_t ua = *(uint16_t*)&a, ub = *(uint16_t*)&b;
    return (uint32_t)ua | ((uint32_t)ub << 16);
}

/* ---------------- mma.sync / ldmatrix wrappers (sm_80+ baseline PTX) ------ */
__device__ __forceinline__ void ldsm_x4(uint32_t* r, uint32_t addr) {
    asm volatile("ldmatrix.sync.aligned.m8n8.x4.shared.b16 {%0,%1,%2,%3}, [%4];"
        : "=r"(r[0]), "=r"(r[1]), "=r"(r[2]), "=r"(r[3]) : "r"(addr));
}
__device__ __forceinline__ void ldsm_x2(uint32_t* r, uint32_t addr) {
    asm volatile("ldmatrix.sync.aligned.m8n8.x2.shared.b16 {%0,%1}, [%2];"
        : "=r"(r[0]), "=r"(r[1]) : "r"(addr));
}
__device__ __forceinline__ void mma_bf16(float* c, const uint32_t* a, const uint32_t* b) {
    asm volatile(
        "mma.sync.aligned.m16n8k16.row.col.f32.bf16.bf16.f32 "
        "{%0,%1,%2,%3}, {%4,%5,%6,%7}, {%8,%9}, {%0,%1,%2,%3};"
        : "+f"(c[0]), "+f"(c[1]), "+f"(c[2]), "+f"(c[3])
        : "r"(a[0]), "r"(a[1]), "r"(a[2]), "r"(a[3]), "r"(b[0]), "r"(b[1]));
}

/* ======================================================================== */
/*  HMMA GEMM: C[M,N] = A[M,768] @ B[768,N], fp32 in/out, bf16x3 split      */
/*  CTA 128x128, BK=32, 8 warps (2x4), warp tile 64x32, ldmatrix frags      */
/* ======================================================================== */
#define LDA 40   /* padded bf16 row length: 80 B -> conflict-free ldmatrix */

__global__ __launch_bounds__(256, 2)
void mma_gemm_kernel(const float* __restrict__ A, const float* __restrict__ Bg,
                     float* __restrict__ C, int M, int N) {
    __shared__ __nv_bfloat16 sAhi[128 * LDA];
    __shared__ __nv_bfloat16 sAlo[128 * LDA];
    __shared__ __nv_bfloat16 sBhi[128 * LDA];
    __shared__ __nv_bfloat16 sBlo[128 * LDA];

    const int t = threadIdx.x;
    const int lane = t & 31;
    const int wid = t >> 5;
    const int wm = wid >> 2;          /* 0..1 : 64-row slab   */
    const int wn = wid & 3;           /* 0..3 : 32-col slab   */
    const int rowBase = blockIdx.y * 128;
    const int colBase = blockIdx.x * 128;
    const int g  = lane >> 2;         /* mma group row 0..7   */
    const int tq = lane & 3;          /* col pair 0..3        */

    float acc[4][4][4];
    #pragma unroll
    for (int i = 0; i < 4; i++)
        #pragma unroll
        for (int j = 0; j < 4; j++)
            #pragma unroll
            for (int q = 0; q < 4; q++) acc[i][j][q] = 0.f;

    /* A-load mapping: 2 threads per row, 16 k each */
    const int arow = t >> 1;
    const int aks  = (t & 1) * 16;
    const bool aval = (rowBase + arow) < M;
    const float* apBase = A + (size_t)(rowBase + arow) * KDIM + aks;

    for (int k0 = 0; k0 < KDIM; k0 += 32) {
        if (k0) __syncthreads();      /* previous MMA phase done reading smem */

        /* ---- A tile 128x32 fp32 -> bf16 hi/lo ---- */
        #pragma unroll
        for (int q = 0; q < 4; q++) {
            float4 v = make_float4(0.f, 0.f, 0.f, 0.f);
            if (aval) v = *(const float4*)(apBase + k0 + q * 4);
            __nv_bfloat16 h0 = __float2bfloat16(v.x);
            __nv_bfloat16 h1 = __float2bfloat16(v.y);
            __nv_bfloat16 h2 = __float2bfloat16(v.z);
            __nv_bfloat16 h3 = __float2bfloat16(v.w);
            __nv_bfloat16 l0 = __float2bfloat16(v.x - __bfloat162float(h0));
            __nv_bfloat16 l1 = __float2bfloat16(v.y - __bfloat162float(h1));
            __nv_bfloat16 l2 = __float2bfloat16(v.z - __bfloat162float(h2));
            __nv_bfloat16 l3 = __float2bfloat16(v.w - __bfloat162float(h3));
            int off = arow * LDA + aks + q * 4;
            *(uint2*)&sAhi[off] = make_uint2(pk(h0, h1), pk(h2, h3));
            *(uint2*)&sAlo[off] = make_uint2(pk(l0, l1), pk(l2, l3));
        }

        /* ---- B tile 32k x 128n -> [n][k] bf16 hi/lo ---- */
        #pragma unroll
        for (int i = 0; i < 8; i++) {
            int idx = t + i * 256;
            int n  = idx & 127;
            int kp = idx >> 7;                 /* 0..15, k = 2*kp */
            const float* bp = Bg + (size_t)(k0 + 2 * kp) * N + colBase + n;
            float f0 = bp[0];
            float f1 = bp[N];
            __nv_bfloat16 h0 = __float2bfloat16(f0);
            __nv_bfloat16 h1 = __float2bfloat16(f1);
            __nv_bfloat16 l0 = __float2bfloat16(f0 - __bfloat162float(h0));
            __nv_bfloat16 l1 = __float2bfloat16(f1 - __bfloat162float(h1));
            int off = n * LDA + 2 * kp;
            *(uint32_t*)&sBhi[off] = pk(h0, h1);
            *(uint32_t*)&sBlo[off] = pk(l0, l1);
        }

        __syncthreads();

        /* ---- MMA phase: 2 ksteps of 16 ---- */
        #pragma unroll
        for (int ks = 0; ks < 2; ks++) {
            const int kk = ks * 16;
            uint32_t ah[4][4], al[4][4];
            {
                const int r  = wm * 64 + (lane & 15);
                const int kc = kk + ((lane >> 4) << 3);
                #pragma unroll
                for (int mt = 0; mt < 4; mt++) {
                    int off = (r + mt * 16) * LDA + kc;
                    ldsm_x4(ah[mt], smem_u32(&sAhi[off]));
                    ldsm_x4(al[mt], smem_u32(&sAlo[off]));
                }
            }
            {
                const int nr = wn * 32 + (lane & 7);
                const int kc = kk + (((lane >> 3) & 1) << 3);
                #pragma unroll
                for (int nt = 0; nt < 4; nt++) {
                    uint32_t bh[2], bl[2];
                    int off = (nr + nt * 8) * LDA + kc;
                    ldsm_x2(bh, smem_u32(&sBhi[off]));
                    ldsm_x2(bl, smem_u32(&sBlo[off]));
                    #pragma unroll
                    for (int mt = 0; mt < 4; mt++) {
                        mma_bf16(acc[mt][nt], ah[mt], bh);
                        mma_bf16(acc[mt][nt], ah[mt], bl);
                        mma_bf16(acc[mt][nt], al[mt], bh);
                    }
                }
            }
        }
    }

    /* ---- epilogue ---- */
    #pragma unroll
    for (int mt = 0; mt < 4; mt++) {
        int r0 = rowBase + wm * 64 + mt * 16 + g;
        #pragma unroll
        for (int nt = 0; nt < 4; nt++) {
            int col = colBase + wn * 32 + nt * 8 + 2 * tq;
            if (r0 < M)
                *(float2*)&C[(size_t)r0 * N + col] =
                    make_float2(acc[mt][nt][0], acc[mt][nt][1]);
            if (r0 + 8 < M)
                *(float2*)&C[(size_t)(r0 + 8) * N + col] =
                    make_float2(acc[mt][nt][2], acc[mt][nt][3]);
        }
    }
}

/* ---------------- edge dtype detection (int64 vs int32) ------------------- */
__global__ void detect_kernel(const int* ei32) {
    __shared__ int any;
    if (threadIdx.x == 0) any = 0;
    __syncthreads();
    int v = 0;
    for (int i = threadIdx.x; i < 1024; i += blockDim.x)
        v |= ei32[2 * i + 1];
    if (v) atomicOr(&any, 1);
    __syncthreads();
    if (threadIdx.x == 0) g_is64 = (any == 0) ? 1 : 0;
}

__device__ __forceinline__ int edge_at(const void* ei, long long idx) {
    if (g_is64) return (int)((const long long*)ei)[idx];
    return ((const int*)ei)[idx];
}

/* ---------------- CSR build ----------------------------------------------- */
__global__ void zero_deg_kernel() {
    int i = blockIdx.x * blockDim.x + threadIdx.x;
    if (i < N_NODES) g_deg[i] = 0;
}

__global__ void count_kernel(const void* ei) {
    int e = blockIdx.x * blockDim.x + threadIdx.x;
    if (e >= ET) return;
    int d = (e < E_EDGES) ? edge_at(ei, (long long)E_EDGES + e) : (e - E_EDGES);
    atomicAdd(&g_deg[d], 1);
}

__global__ void scan_kernel() {
    __shared__ int s[1024];
    const int CH = 20;
    int t = threadIdx.x;
    int base = t * CH;
    int sum = 0;
    for (int i = 0; i < CH; i++) {
        int idx = base + i;
        if (idx < N_NODES) sum += g_deg[idx];
    }
    s[t] = sum;
    __syncthreads();
    for (int off = 1; off < 1024; off <<= 1) {
        int v = (t >= off) ? s[t - off] : 0;
        __syncthreads();
        s[t] += v;
        __syncthreads();
    }
    int run = (t == 0) ? 0 : s[t - 1];
    for (int i = 0; i < CH; i++) {
        int idx = base + i;
        if (idx < N_NODES) {
            g_rowptr[idx] = run;
            g_cursor[idx] = run;
            run += g_deg[idx];
        }
    }
    if (t == 1023) g_rowptr[N_NODES] = s[1023];
}

__global__ void scatter_kernel(const void* ei) {
    int e = blockIdx.x * blockDim.x + threadIdx.x;
    if (e >= ET) return;
    int s, d;
    if (e < E_EDGES) {
        s = edge_at(ei, e);
        d = edge_at(ei, (long long)E_EDGES + e);
    } else {
        s = d = e - E_EDGES;
    }
    int slot = atomicAdd(&g_cursor[d], 1);
    g_col[slot] = s;
}

/* ---------------- attention coefficients ---------------------------------- */
__global__ void att_kernel(const float* __restrict__ xp,
                           const float* __restrict__ att_s,
                           const float* __restrict__ att_d,
                           float* __restrict__ as_out,
                           float* __restrict__ ad_out, int H) {
    int gw   = (blockIdx.x * blockDim.x + threadIdx.x) >> 5;
    int lane = threadIdx.x & 31;
    if (gw >= N_NODES * H) return;
    int n = gw / H, h = gw % H;
    const float* row = xp + (size_t)n * (H * HID) + h * HID;
    float s = 0.f, d = 0.f;
    for (int c = lane; c < HID; c += 32) {
        float v = row[c];
        s += v * att_s[h * HID + c];
        d += v * att_d[h * HID + c];
    }
    s = warpSum(s);
    d = warpSum(d);
    if (lane == 0) {
        as_out[n * H + h] = s;
        ad_out[n * H + h] = d;
    }
}

/* ---------------- segment softmax (warp per node) -------------------------- */
__global__ void softmax_kernel(const float* __restrict__ asrc,
                               const float* __restrict__ adst,
                               float* __restrict__ alpha, int H) {
    int n    = (blockIdx.x * blockDim.x + threadIdx.x) >> 5;
    int lane = threadIdx.x & 31;
    if (n >= N_NODES) return;
    int st = g_rowptr[n], en = g_rowptr[n + 1];
    for (int h = 0; h < H; h++) {
        float ad = adst[n * H + h];
        float mx = -1e30f;
        for (int s = st + lane; s < en; s += 32) {
            float v = asrc[g_col[s] * H + h] + ad;
            v = (v > 0.f) ? v : 0.2f * v;
            alpha[(size_t)s * H + h] = v;
            mx = fmaxf(mx, v);
        }
        mx = warpMax(mx);
        float sum = 0.f;
        for (int s = st + lane; s < en; s += 32) {
            float e = __expf(alpha[(size_t)s * H + h] - mx);
            alpha[(size_t)s * H + h] = e;
            sum += e;
        }
        sum = warpSum(sum);
        float inv = 1.f / sum;
        for (int s = st + lane; s < en; s += 32)
            alpha[(size_t)s * H + h] *= inv;
    }
}

/* ---------------- layer-1 aggregation + bias + ELU ------------------------- */
__global__ __launch_bounds__(256)
void agg1_kernel(const float* __restrict__ b1) {
    int n = blockIdx.x;
    int c = threadIdx.x;
    int st = g_rowptr[n], en = g_rowptr[n + 1];
    float a0 = 0.f, a1 = 0.f, a2 = 0.f;
    for (int s = st; s < en; s++) {
        int src = g_col[s];
        float w0 = g_alpha[(size_t)s * 3 + 0];
        float w1 = g_alpha[(size_t)s * 3 + 1];
        float w2 = g_alpha[(size_t)s * 3 + 2];
        const float* r = g_xp1 + (size_t)src * F1;
        a0 += w0 * r[c];
        a1 += w1 * r[c + 256];
        a2 += w2 * r[c + 512];
    }
    a0 += b1[c];
    a1 += b1[c + 256];
    a2 += b1[c + 512];
    float* o = g_h + (size_t)n * F1;
    o[c]       = (a0 > 0.f) ? a0 : expm1f(a0);
    o[c + 256] = (a1 > 0.f) ? a1 : expm1f(a1);
    o[c + 512] = (a2 > 0.f) ? a2 : expm1f(a2);
}

/* ---------------- layer-2 aggregation + bias ------------------------------- */
__global__ __launch_bounds__(256)
void agg2_kernel(const float* __restrict__ b2, float* __restrict__ out) {
    int n = blockIdx.x;
    int c = threadIdx.x;
    int st = g_rowptr[n], en = g_rowptr[n + 1];
    float a = 0.f;
    for (int s = st; s < en; s++)
        a += g_alpha[s] * g_xp2[(size_t)g_col[s] * HID + c];
    out[(size_t)n * HID + c] = a + b2[c];
}

/* ---------------- launch --------------------------------------------------- */
extern "C" void kernel_launch(void* const* d_in, const int* in_sizes, int n_in,
                              void* d_out, int out_size) {
    const float* x   = (const float*)d_in[0];
    const void*  ei  = d_in[1];
    const float* W1  = (const float*)d_in[2];
    const float* as1 = (const float*)d_in[3];
    const float* ad1 = (const float*)d_in[4];
    const float* b1  = (const float*)d_in[5];
    const float* W2  = (const float*)d_in[6];
    const float* as2 = (const float*)d_in[7];
    const float* ad2 = (const float*)d_in[8];
    const float* b2  = (const float*)d_in[9];
    float* out = (float*)d_out;

    void *p_xp1, *p_h, *p_xp2, *p_as1, *p_ad1, *p_as2, *p_ad2, *p_alpha;
    cudaGetSymbolAddress(&p_xp1,   g_xp1);
    cudaGetSymbolAddress(&p_h,     g_h);
    cudaGetSymbolAddress(&p_xp2,   g_xp2);
    cudaGetSymbolAddress(&p_as1,   g_asrc1);
    cudaGetSymbolAddress(&p_ad1,   g_adst1);
    cudaGetSymbolAddress(&p_as2,   g_asrc2);
    cudaGetSymbolAddress(&p_ad2,   g_adst2);
    cudaGetSymbolAddress(&p_alpha, g_alpha);

    /* CSR build */
    detect_kernel<<<1, 256>>>((const int*)ei);
    zero_deg_kernel<<<(N_NODES + 255) / 256, 256>>>();
    count_kernel<<<(ET + 255) / 256, 256>>>(ei);
    scan_kernel<<<1, 1024>>>();
    scatter_kernel<<<(ET + 255) / 256, 256>>>(ei);

    /* layer 1 */
    mma_gemm_kernel<<<dim3(F1 / 128, (N_NODES + 127) / 128), 256>>>(
        x, W1, (float*)p_xp1, N_NODES, F1);
    att_kernel<<<(N_NODES * H1 * 32 + 255) / 256, 256>>>(
        (const float*)p_xp1, as1, ad1, (float*)p_as1, (float*)p_ad1, H1);
    softmax_kernel<<<(N_NODES * 32 + 255) / 256, 256>>>(
        (const float*)p_as1, (const float*)p_ad1, (float*)p_alpha, H1);
    agg1_kernel<<<N_NODES, 256>>>(b1);

    /* layer 2 */
    mma_gemm_kernel<<<dim3(HID / 128, (N_NODES + 127) / 128), 256>>>(
        (const float*)p_h, W2, (float*)p_xp2, N_NODES, HID);
    att_kernel<<<(N_NODES * 32 + 255) / 256, 256>>>(
        (const float*)p_xp2, as2, ad2, (float*)p_as2, (float*)p_ad2, 1);
    softmax_kernel<<<(N_NODES * 32 + 255) / 256, 256>>>(
        (const float*)p_as2, (const float*)p_ad2, (float*)p_alpha, 1);
    agg2_kernel<<<N_NODES, 256>>>(b2, out);
}

// round 4
// speedup vs baseline: 2.1215x; 1.2224x over previous
#include <cuda_runtime.h>
#include <cuda_bf16.h>
#include <math.h>
#include <stdint.h>

#define N_NODES 20000
#define E_EDGES 320000
#define ET      (E_EDGES + N_NODES)   /* 340000 with self loops */
#define IN_DIM  768
#define HID     256
#define H1      3
#define F1      (H1 * HID)            /* 768 */
#define KDIM    768
#define NBLK    ((N_NODES + 255) / 256)   /* 79 */

/* ---------------- scratch (device globals, no allocs allowed) ------------- */
__device__ float g_xp1[(size_t)N_NODES * F1];
__device__ float g_xp2[(size_t)N_NODES * HID];
__device__ __nv_bfloat16 gx_hi[(size_t)N_NODES * IN_DIM];
__device__ __nv_bfloat16 gx_lo[(size_t)N_NODES * IN_DIM];
__device__ __nv_bfloat16 gh_hi[(size_t)N_NODES * F1];
__device__ __nv_bfloat16 gh_lo[(size_t)N_NODES * F1];
__device__ __nv_bfloat16 gw1t_hi[F1 * KDIM];     /* [n][k] */
__device__ __nv_bfloat16 gw1t_lo[F1 * KDIM];
__device__ __nv_bfloat16 gw2t_hi[HID * KDIM];
__device__ __nv_bfloat16 gw2t_lo[HID * KDIM];
__device__ float g_asrc1[N_NODES * H1];
__device__ float g_adst1[N_NODES * H1];
__device__ float g_asrc2[N_NODES];
__device__ float g_adst2[N_NODES];
__device__ int   g_deg[N_NODES];
__device__ int   g_rowptr[N_NODES + 1];
__device__ int   g_cursor[N_NODES];
__device__ int   g_col[ET];
__device__ float g_alpha[(size_t)ET * H1];
__device__ int   g_bsum[128];
__device__ int   g_boff[128];
__device__ int   g_is64;

/* ---------------- helpers ------------------------------------------------- */
__device__ __forceinline__ float warpSum(float v) {
    #pragma unroll
    for (int o = 16; o; o >>= 1) v += __shfl_xor_sync(0xffffffffu, v, o);
    return v;
}
__device__ __forceinline__ float warpMax(float v) {
    #pragma unroll
    for (int o = 16; o; o >>= 1) v = fmaxf(v, __shfl_xor_sync(0xffffffffu, v, o));
    return v;
}
__device__ __forceinline__ uint32_t smem_u32(const void* p) {
    uint32_t a;
    asm("{ .reg .u64 t; cvta.to.shared.u64 t, %1; cvt.u32.u64 %0, t; }"
        : "=r"(a) : "l"(p));
    return a;
}
__device__ __forceinline__ uint32_t pk(__nv_bfloat16 a, __nv_bfloat16 b) {
    uint16_t ua = *(uint16_t*)&a, ub = *(uint16_t*)&b;
    return (uint32_t)ua | ((uint32_t)ub << 16);
}
__device__ __forceinline__ void split2(float v, __nv_bfloat16& h, __nv_bfloat16& l) {
    h = __float2bfloat16(v);
    l = __float2bfloat16(v - __bfloat162float(h));
}

/* ---------------- mma.sync / ldmatrix / cp.async wrappers ----------------- */
__device__ __forceinline__ void ldsm_x4(uint32_t* r, uint32_t addr) {
    asm volatile("ldmatrix.sync.aligned.m8n8.x4.shared.b16 {%0,%1,%2,%3}, [%4];"
        : "=r"(r[0]), "=r"(r[1]), "=r"(r[2]), "=r"(r[3]) : "r"(addr));
}
__device__ __forceinline__ void ldsm_x2(uint32_t* r, uint32_t addr) {
    asm volatile("ldmatrix.sync.aligned.m8n8.x2.shared.b16 {%0,%1}, [%2];"
        : "=r"(r[0]), "=r"(r[1]) : "r"(addr));
}
__device__ __forceinline__ void mma_bf16(float* c, const uint32_t* a, const uint32_t* b) {
    asm volatile(
        "mma.sync.aligned.m16n8k16.row.col.f32.bf16.bf16.f32 "
        "{%0,%1,%2,%3}, {%4,%5,%6,%7}, {%8,%9}, {%0,%1,%2,%3};"
        : "+f"(c[0]), "+f"(c[1]), "+f"(c[2]), "+f"(c[3])
        : "r"(a[0]), "r"(a[1]), "r"(a[2]), "r"(a[3]), "r"(b[0]), "r"(b[1]));
}
__device__ __forceinline__ void cp16(uint32_t dst, const void* src, int sz) {
    asm volatile("cp.async.cg.shared.global [%0], [%1], 16, %2;"
        :: "r"(dst), "l"(src), "r"(sz) : "memory");
}
__device__ __forceinline__ void cp_commit() {
    asm volatile("cp.async.commit_group;" ::: "memory");
}
template <int W> __device__ __forceinline__ void cp_wait() {
    asm volatile("cp.async.wait_group %0;" :: "n"(W) : "memory");
}

/* ======================================================================== */
/*  HMMA GEMM: C[M,N] = A[M,768] @ Bt[N,768]^T, bf16x3, cp.async 2-stage    */
/* ======================================================================== */
#define LDA 40
#define ARR_B (128 * LDA * 2)     /* 10240 B per array */
#define STG_B (4 * ARR_B)         /* 40960 B per stage */
#define GSMEM (2 * STG_B)         /* 81920 B */
#define NCHUNK (KDIM / 32)        /* 24 */

__global__ __launch_bounds__(256, 2)
void mma_gemm_kernel(const __nv_bfloat16* __restrict__ Ahi,
                     const __nv_bfloat16* __restrict__ Alo,
                     const __nv_bfloat16* __restrict__ Bhi,
                     const __nv_bfloat16* __restrict__ Blo,
                     float* __restrict__ C, int M, int N) {
    extern __shared__ char smem[];
    const int t = threadIdx.x, lane = t & 31, wid = t >> 5;
    const int wm = wid >> 2, wn = wid & 3;
    const int rowBase = blockIdx.y * 128;
    const int colBase = blockIdx.x * 128;
    const uint32_t sb = smem_u32(smem);

    /* load mapping: per array, thread t owns chunks 2t, 2t+1 (16 B each) */
    const int r0 = (2 * t) >> 2,     s0 = ((2 * t) & 3) * 8;
    const int r1 = (2 * t + 1) >> 2, s1 = ((2 * t + 1) & 3) * 8;
    const int av0 = (rowBase + r0) < M ? 16 : 0;
    const int av1 = (rowBase + r1) < M ? 16 : 0;
    const __nv_bfloat16* pAhi0 = Ahi + (size_t)(rowBase + r0) * KDIM + s0;
    const __nv_bfloat16* pAhi1 = Ahi + (size_t)(rowBase + r1) * KDIM + s1;
    const __nv_bfloat16* pAlo0 = Alo + (size_t)(rowBase + r0) * KDIM + s0;
    const __nv_bfloat16* pAlo1 = Alo + (size_t)(rowBase + r1) * KDIM + s1;
    const __nv_bfloat16* pBhi0 = Bhi + (size_t)(colBase + r0) * KDIM + s0;
    const __nv_bfloat16* pBhi1 = Bhi + (size_t)(colBase + r1) * KDIM + s1;
    const __nv_bfloat16* pBlo0 = Blo + (size_t)(colBase + r0) * KDIM + s0;
    const __nv_bfloat16* pBlo1 = Blo + (size_t)(colBase + r1) * KDIM + s1;
    const uint32_t d0 = (uint32_t)(r0 * LDA + s0) * 2;
    const uint32_t d1 = (uint32_t)(r1 * LDA + s1) * 2;

    float acc[4][4][4];
    #pragma unroll
    for (int i = 0; i < 4; i++)
        #pragma unroll
        for (int j = 0; j < 4; j++)
            #pragma unroll
            for (int q = 0; q < 4; q++) acc[i][j][q] = 0.f;

    /* prologue: stage 0 <- chunk 0 */
    {
        const uint32_t b = sb;
        cp16(b + d0, pAhi0, av0);               cp16(b + d1, pAhi1, av1);
        cp16(b + ARR_B + d0, pAlo0, av0);       cp16(b + ARR_B + d1, pAlo1, av1);
        cp16(b + 2 * ARR_B + d0, pBhi0, 16);    cp16(b + 2 * ARR_B + d1, pBhi1, 16);
        cp16(b + 3 * ARR_B + d0, pBlo0, 16);    cp16(b + 3 * ARR_B + d1, pBlo1, 16);
        cp_commit();
    }

    for (int c = 0; c < NCHUNK; c++) {
        const int st = c & 1;
        if (c + 1 < NCHUNK) {
            const int k0 = (c + 1) * 32;
            const uint32_t b = sb + ((c + 1) & 1) * STG_B;
            cp16(b + d0, pAhi0 + k0, av0);               cp16(b + d1, pAhi1 + k0, av1);
            cp16(b + ARR_B + d0, pAlo0 + k0, av0);       cp16(b + ARR_B + d1, pAlo1 + k0, av1);
            cp16(b + 2 * ARR_B + d0, pBhi0 + k0, 16);    cp16(b + 2 * ARR_B + d1, pBhi1 + k0, 16);
            cp16(b + 3 * ARR_B + d0, pBlo0 + k0, 16);    cp16(b + 3 * ARR_B + d1, pBlo1 + k0, 16);
            cp_commit();
            cp_wait<1>();
        } else {
            cp_wait<0>();
        }
        __syncthreads();

        const uint32_t sAhi = sb + st * STG_B;
        const uint32_t sAlo = sAhi + ARR_B;
        const uint32_t sBhi = sAhi + 2 * ARR_B;
        const uint32_t sBlo = sAhi + 3 * ARR_B;

        #pragma unroll
        for (int ks = 0; ks < 2; ks++) {
            const int kk = ks * 16;
            uint32_t ah[4][4], al[4][4];
            {
                const int r  = wm * 64 + (lane & 15);
                const int kc = kk + ((lane >> 4) << 3);
                #pragma unroll
                for (int mt = 0; mt < 4; mt++) {
                    uint32_t off = (uint32_t)((r + mt * 16) * LDA + kc) * 2;
                    ldsm_x4(ah[mt], sAhi + off);
                    ldsm_x4(al[mt], sAlo + off);
                }
            }
            {
                const int nr = wn * 32 + (lane & 7);
                const int kc = kk + (((lane >> 3) & 1) << 3);
                #pragma unroll
                for (int nt = 0; nt < 4; nt++) {
                    uint32_t bh[2], bl[2];
                    uint32_t off = (uint32_t)((nr + nt * 8) * LDA + kc) * 2;
                    ldsm_x2(bh, sBhi + off);
                    ldsm_x2(bl, sBlo + off);
                    #pragma unroll
                    for (int mt = 0; mt < 4; mt++) {
                        mma_bf16(acc[mt][nt], ah[mt], bh);
                        mma_bf16(acc[mt][nt], ah[mt], bl);
                        mma_bf16(acc[mt][nt], al[mt], bh);
                    }
                }
            }
        }
        __syncthreads();
    }

    /* epilogue */
    const int g = lane >> 2, tq = lane & 3;
    #pragma unroll
    for (int mt = 0; mt < 4; mt++) {
        int r0g = rowBase + wm * 64 + mt * 16 + g;
        #pragma unroll
        for (int nt = 0; nt < 4; nt++) {
            int col = colBase + wn * 32 + nt * 8 + 2 * tq;
            if (r0g < M)
                *(float2*)&C[(size_t)r0g * N + col] =
                    make_float2(acc[mt][nt][0], acc[mt][nt][1]);
            if (r0g + 8 < M)
                *(float2*)&C[(size_t)(r0g + 8) * N + col] =
                    make_float2(acc[mt][nt][2], acc[mt][nt][3]);
        }
    }
}

/* ---------------- fp32 -> bf16 hi/lo elementwise split --------------------- */
__global__ void conv_split_kernel(const float* __restrict__ src,
                                  __nv_bfloat16* __restrict__ hi,
                                  __nv_bfloat16* __restrict__ lo, int n4) {
    int i = blockIdx.x * blockDim.x + threadIdx.x;
    if (i >= n4) return;
    float4 v = ((const float4*)src)[i];
    __nv_bfloat16 h0, h1, h2, h3, l0, l1, l2, l3;
    split2(v.x, h0, l0); split2(v.y, h1, l1);
    split2(v.z, h2, l2); split2(v.w, h3, l3);
    ((uint2*)hi)[i] = make_uint2(pk(h0, h1), pk(h2, h3));
    ((uint2*)lo)[i] = make_uint2(pk(l0, l1), pk(l2, l3));
}

/* ---------------- W[k][n] -> Wt[n][k] transpose + split -------------------- */
__global__ void trans_split_kernel(const float* __restrict__ W,
                                   __nv_bfloat16* __restrict__ Th,
                                   __nv_bfloat16* __restrict__ Tl,
                                   int K, int N) {
    __shared__ float tile[32][33];
    int k0 = blockIdx.y * 32, n0 = blockIdx.x * 32;
    int tx = threadIdx.x, ty = threadIdx.y;   /* 32 x 8 */
    #pragma unroll
    for (int i = 0; i < 32; i += 8)
        tile[ty + i][tx] = W[(size_t)(k0 + ty + i) * N + n0 + tx];
    __syncthreads();
    #pragma unroll
    for (int i = 0; i < 32; i += 8) {
        float v = tile[tx][ty + i];
        __nv_bfloat16 h, l;
        split2(v, h, l);
        size_t o = (size_t)(n0 + ty + i) * K + k0 + tx;
        Th[o] = h;
        Tl[o] = l;
    }
}

/* ---------------- edge dtype detection ------------------------------------ */
__global__ void detect_kernel(const int* ei32) {
    __shared__ int any;
    if (threadIdx.x == 0) any = 0;
    __syncthreads();
    int v = 0;
    for (int i = threadIdx.x; i < 1024; i += blockDim.x)
        v |= ei32[2 * i + 1];
    if (v) atomicOr(&any, 1);
    __syncthreads();
    if (threadIdx.x == 0) g_is64 = (any == 0) ? 1 : 0;
}
__device__ __forceinline__ int edge_at(const void* ei, long long idx) {
    if (g_is64) return (int)((const long long*)ei)[idx];
    return ((const int*)ei)[idx];
}

/* ---------------- CSR build ------------------------------------------------ */
__global__ void zero_deg_kernel() {
    int i = blockIdx.x * blockDim.x + threadIdx.x;
    if (i < N_NODES) g_deg[i] = 0;
}
__global__ void count_kernel(const void* ei) {
    int e = blockIdx.x * blockDim.x + threadIdx.x;
    if (e >= ET) return;
    int d = (e < E_EDGES) ? edge_at(ei, (long long)E_EDGES + e) : (e - E_EDGES);
    atomicAdd(&g_deg[d], 1);
}
__global__ void bsum_kernel() {
    __shared__ int s[256];
    int i = blockIdx.x * 256 + threadIdx.x;
    s[threadIdx.x] = (i < N_NODES) ? g_deg[i] : 0;
    __syncthreads();
    for (int o = 128; o; o >>= 1) {
        if (threadIdx.x < o) s[threadIdx.x] += s[threadIdx.x + o];
        __syncthreads();
    }
    if (threadIdx.x == 0) g_bsum[blockIdx.x] = s[0];
}
__global__ void bscan_kernel() {
    __shared__ int s[128];
    int t = threadIdx.x;
    int v = (t < NBLK) ? g_bsum[t] : 0;
    s[t] = v;
    __syncthreads();
    for (int o = 1; o < 128; o <<= 1) {
        int u = (t >= o) ? s[t - o] : 0;
        __syncthreads();
        s[t] += u;
        __syncthreads();
    }
    g_boff[t] = s[t] - v;     /* exclusive */
    if (t == 0) g_rowptr[N_NODES] = ET;
}
__global__ void fscan_kernel() {
    __shared__ int s[256];
    int t = threadIdx.x;
    int i = blockIdx.x * 256 + t;
    int d = (i < N_NODES) ? g_deg[i] : 0;
    s[t] = d;
    __syncthreads();
    for (int o = 1; o < 256; o <<= 1) {
        int u = (t >= o) ? s[t - o] : 0;
        __syncthreads();
        s[t] += u;
        __syncthreads();
    }
    if (i < N_NODES) {
        int off = s[t] - d + g_boff[blockIdx.x];
        g_rowptr[i] = off;
        g_cursor[i] = off;
    }
}
__global__ void scatter_kernel(const void* ei) {
    int e = blockIdx.x * blockDim.x + threadIdx.x;
    if (e >= ET) return;
    int s, d;
    if (e < E_EDGES) {
        s = edge_at(ei, e);
        d = edge_at(ei, (long long)E_EDGES + e);
    } else {
        s = d = e - E_EDGES;
    }
    int slot = atomicAdd(&g_cursor[d], 1);
    g_col[slot] = s;
}

/* ---------------- attention coefficients ----------------------------------- */
__global__ void att_kernel(const float* __restrict__ xp,
                           const float* __restrict__ att_s,
                           const float* __restrict__ att_d,
                           float* __restrict__ as_out,
                           float* __restrict__ ad_out, int H) {
    int gw   = (blockIdx.x * blockDim.x + threadIdx.x) >> 5;
    int lane = threadIdx.x & 31;
    if (gw >= N_NODES * H) return;
    int n = gw / H, h = gw % H;
    const float* row = xp + (size_t)n * (H * HID) + h * HID;
    float s = 0.f, d = 0.f;
    for (int c = lane; c < HID; c += 32) {
        float v = row[c];
        s += v * att_s[h * HID + c];
        d += v * att_d[h * HID + c];
    }
    s = warpSum(s);
    d = warpSum(d);
    if (lane == 0) {
        as_out[n * H + h] = s;
        ad_out[n * H + h] = d;
    }
}

/* ---------------- segment softmax (warp per node) -------------------------- */
__global__ void softmax_kernel(const float* __restrict__ asrc,
                               const float* __restrict__ adst,
                               float* __restrict__ alpha, int H) {
    int n    = (blockIdx.x * blockDim.x + threadIdx.x) >> 5;
    int lane = threadIdx.x & 31;
    if (n >= N_NODES) return;
    int st = g_rowptr[n], en = g_rowptr[n + 1];
    for (int h = 0; h < H; h++) {
        float ad = adst[n * H + h];
        float mx = -1e30f;
        for (int s = st + lane; s < en; s += 32) {
            float v = asrc[g_col[s] * H + h] + ad;
            v = (v > 0.f) ? v : 0.2f * v;
            alpha[(size_t)s * H + h] = v;
            mx = fmaxf(mx, v);
        }
        mx = warpMax(mx);
        float sum = 0.f;
        for (int s = st + lane; s < en; s += 32) {
            float e = __expf(alpha[(size_t)s * H + h] - mx);
            alpha[(size_t)s * H + h] = e;
            sum += e;
        }
        sum = warpSum(sum);
        float inv = 1.f / sum;
        for (int s = st + lane; s < en; s += 32)
            alpha[(size_t)s * H + h] *= inv;
    }
}

/* ---------------- layer-1 aggregation + bias + ELU -> bf16 hi/lo ----------- */
__global__ __launch_bounds__(192)
void agg1_kernel(const float* __restrict__ b1) {
    int n = blockIdx.x;
    int t = threadIdx.x;
    int head = t >> 6;
    int base = head * 256 + (t & 63) * 4;
    int st = g_rowptr[n], en = g_rowptr[n + 1];
    float4 a = make_float4(0.f, 0.f, 0.f, 0.f);
    for (int s = st; s < en; s++) {
        float w = g_alpha[(size_t)s * 3 + head];
        float4 r = *(const float4*)(g_xp1 + (size_t)g_col[s] * F1 + base);
        a.x += w * r.x; a.y += w * r.y; a.z += w * r.z; a.w += w * r.w;
    }
    float4 b = *(const float4*)(b1 + base);
    a.x += b.x; a.y += b.y; a.z += b.z; a.w += b.w;
    a.x = (a.x > 0.f) ? a.x : expm1f(a.x);
    a.y = (a.y > 0.f) ? a.y : expm1f(a.y);
    a.z = (a.z > 0.f) ? a.z : expm1f(a.z);
    a.w = (a.w > 0.f) ? a.w : expm1f(a.w);
    __nv_bfloat16 h0, h1, h2, h3, l0, l1, l2, l3;
    split2(a.x, h0, l0); split2(a.y, h1, l1);
    split2(a.z, h2, l2); split2(a.w, h3, l3);
    size_t o4 = ((size_t)n * F1 + base) / 4;
    ((uint2*)gh_hi)[o4] = make_uint2(pk(h0, h1), pk(h2, h3));
    ((uint2*)gh_lo)[o4] = make_uint2(pk(l0, l1), pk(l2, l3));
}

/* ---------------- layer-2 aggregation + bias -> output --------------------- */
__global__ __launch_bounds__(64)
void agg2_kernel(const float* __restrict__ b2, float* __restrict__ out) {
    int n = blockIdx.x;
    int c4 = threadIdx.x * 4;
    int st = g_rowptr[n], en = g_rowptr[n + 1];
    float4 a = make_float4(0.f, 0.f, 0.f, 0.f);
    for (int s = st; s < en; s++) {
        float w = g_alpha[s];
        float4 r = *(const float4*)(g_xp2 + (size_t)g_col[s] * HID + c4);
        a.x += w * r.x; a.y += w * r.y; a.z += w * r.z; a.w += w * r.w;
    }
    float4 b = *(const float4*)(b2 + c4);
    a.x += b.x; a.y += b.y; a.z += b.z; a.w += b.w;
    *(float4*)(out + (size_t)n * HID + c4) = a;
}

/* ---------------- launch --------------------------------------------------- */
extern "C" void kernel_launch(void* const* d_in, const int* in_sizes, int n_in,
                              void* d_out, int out_size) {
    const float* x   = (const float*)d_in[0];
    const void*  ei  = d_in[1];
    const float* W1  = (const float*)d_in[2];
    const float* as1 = (const float*)d_in[3];
    const float* ad1 = (const float*)d_in[4];
    const float* b1  = (const float*)d_in[5];
    const float* W2  = (const float*)d_in[6];
    const float* as2 = (const float*)d_in[7];
    const float* ad2 = (const float*)d_in[8];
    const float* b2  = (const float*)d_in[9];
    float* out = (float*)d_out;

    void *p_xp1, *p_xp2, *p_as1, *p_ad1, *p_as2, *p_ad2, *p_alpha;
    void *p_xhi, *p_xlo, *p_hhi, *p_hlo;
    void *p_w1h, *p_w1l, *p_w2h, *p_w2l;
    cudaGetSymbolAddress(&p_xp1,   g_xp1);
    cudaGetSymbolAddress(&p_xp2,   g_xp2);
    cudaGetSymbolAddress(&p_as1,   g_asrc1);
    cudaGetSymbolAddress(&p_ad1,   g_adst1);
    cudaGetSymbolAddress(&p_as2,   g_asrc2);
    cudaGetSymbolAddress(&p_ad2,   g_adst2);
    cudaGetSymbolAddress(&p_alpha, g_alpha);
    cudaGetSymbolAddress(&p_xhi,   gx_hi);
    cudaGetSymbolAddress(&p_xlo,   gx_lo);
    cudaGetSymbolAddress(&p_hhi,   gh_hi);
    cudaGetSymbolAddress(&p_hlo,   gh_lo);
    cudaGetSymbolAddress(&p_w1h,   gw1t_hi);
    cudaGetSymbolAddress(&p_w1l,   gw1t_lo);
    cudaGetSymbolAddress(&p_w2h,   gw2t_hi);
    cudaGetSymbolAddress(&p_w2l,   gw2t_lo);

    cudaFuncSetAttribute(mma_gemm_kernel,
                         cudaFuncAttributeMaxDynamicSharedMemorySize, GSMEM);

    /* pre-conversion */
    {
        int n4 = N_NODES * IN_DIM / 4;
        conv_split_kernel<<<(n4 + 255) / 256, 256>>>(
            x, (__nv_bfloat16*)p_xhi, (__nv_bfloat16*)p_xlo, n4);
        trans_split_kernel<<<dim3(F1 / 32, KDIM / 32), dim3(32, 8)>>>(
            W1, (__nv_bfloat16*)p_w1h, (__nv_bfloat16*)p_w1l, KDIM, F1);
        trans_split_kernel<<<dim3(HID / 32, KDIM / 32), dim3(32, 8)>>>(
            W2, (__nv_bfloat16*)p_w2h, (__nv_bfloat16*)p_w2l, KDIM, HID);
    }

    /* CSR build */
    detect_kernel<<<1, 256>>>((const int*)ei);
    zero_deg_kernel<<<NBLK, 256>>>();
    count_kernel<<<(ET + 255) / 256, 256>>>(ei);
    bsum_kernel<<<NBLK, 256>>>();
    bscan_kernel<<<1, 128>>>();
    fscan_kernel<<<NBLK, 256>>>();
    scatter_kernel<<<(ET + 255) / 256, 256>>>(ei);

    /* layer 1 */
    mma_gemm_kernel<<<dim3(F1 / 128, (N_NODES + 127) / 128), 256, GSMEM>>>(
        (const __nv_bfloat16*)p_xhi, (const __nv_bfloat16*)p_xlo,
        (const __nv_bfloat16*)p_w1h, (const __nv_bfloat16*)p_w1l,
        (float*)p_xp1, N_NODES, F1);
    att_kernel<<<(N_NODES * H1 * 32 + 255) / 256, 256>>>(
        (const float*)p_xp1, as1, ad1, (float*)p_as1, (float*)p_ad1, H1);
    softmax_kernel<<<(N_NODES * 32 + 255) / 256, 256>>>(
        (const float*)p_as1, (const float*)p_ad1, (float*)p_alpha, H1);
    agg1_kernel<<<N_NODES, 192>>>(b1);

    /* layer 2 */
    mma_gemm_kernel<<<dim3(HID / 128, (N_NODES + 127) / 128), 256, GSMEM>>>(
        (const __nv_bfloat16*)p_hhi, (const __nv_bfloat16*)p_hlo,
        (const __nv_bfloat16*)p_w2h, (const __nv_bfloat16*)p_w2l,
        (float*)p_xp2, N_NODES, HID);
    att_kernel<<<(N_NODES * 32 + 255) / 256, 256>>>(
        (const float*)p_xp2, as2, ad2, (float*)p_as2, (float*)p_ad2, 1);
    softmax_kernel<<<(N_NODES * 32 + 255) / 256, 256>>>(
        (const float*)p_as2, (const float*)p_ad2, (float*)p_alpha, 1);
    agg2_kernel<<<N_NODES, 64>>>(b2, out);
}

// round 5
// speedup vs baseline: 2.1821x; 1.0286x over previous
#include <cuda_runtime.h>
#include <cuda_bf16.h>
#include <cuda_fp16.h>
#include <math.h>
#include <stdint.h>

#define N_NODES 20000
#define E_EDGES 320000
#define ET      (E_EDGES + N_NODES)   /* 340000 with self loops */
#define IN_DIM  768
#define HID     256
#define H1      3
#define F1      (H1 * HID)            /* 768 */
#define KDIM    768
#define NBLK    ((N_NODES + 255) / 256)   /* 79 */

/* ---------------- scratch (device globals, no allocs allowed) ------------- */
__device__ float g_xp1[(size_t)N_NODES * F1];
__device__ float g_xp2[(size_t)N_NODES * HID];
__device__ __half g_xp1h[(size_t)N_NODES * F1];
__device__ __half g_xp2h[(size_t)N_NODES * HID];
__device__ __nv_bfloat16 gx_hi[(size_t)N_NODES * IN_DIM];
__device__ __nv_bfloat16 gx_lo[(size_t)N_NODES * IN_DIM];
__device__ __nv_bfloat16 gh_hi[(size_t)N_NODES * F1];
__device__ __nv_bfloat16 gh_lo[(size_t)N_NODES * F1];
__device__ __nv_bfloat16 gw1t_hi[F1 * KDIM];     /* [n][k] */
__device__ __nv_bfloat16 gw1t_lo[F1 * KDIM];
__device__ __nv_bfloat16 gw2t_hi[HID * KDIM];
__device__ __nv_bfloat16 gw2t_lo[HID * KDIM];
__device__ float g_asrc1[N_NODES * H1];
__device__ float g_adst1[N_NODES * H1];
__device__ float g_asrc2[N_NODES];
__device__ float g_adst2[N_NODES];
__device__ float g_inv1[N_NODES * H1];
__device__ float g_inv2[N_NODES];
__device__ int   g_deg[N_NODES];
__device__ int   g_rowptr[N_NODES + 1];
__device__ int   g_cursor[N_NODES];
__device__ int   g_col[ET];
__device__ float g_alpha[(size_t)ET * H1];
__device__ int   g_bsum[128];
__device__ int   g_boff[128];
__device__ int   g_is64;

/* ---------------- helpers ------------------------------------------------- */
__device__ __forceinline__ float warpSum(float v) {
    #pragma unroll
    for (int o = 16; o; o >>= 1) v += __shfl_xor_sync(0xffffffffu, v, o);
    return v;
}
__device__ __forceinline__ float warpMax(float v) {
    #pragma unroll
    for (int o = 16; o; o >>= 1) v = fmaxf(v, __shfl_xor_sync(0xffffffffu, v, o));
    return v;
}
__device__ __forceinline__ uint32_t smem_u32(const void* p) {
    uint32_t a;
    asm("{ .reg .u64 t; cvta.to.shared.u64 t, %1; cvt.u32.u64 %0, t; }"
        : "=r"(a) : "l"(p));
    return a;
}
__device__ __forceinline__ uint32_t pk(__nv_bfloat16 a, __nv_bfloat16 b) {
    uint16_t ua = *(uint16_t*)&a, ub = *(uint16_t*)&b;
    return (uint32_t)ua | ((uint32_t)ub << 16);
}
__device__ __forceinline__ void split2(float v, __nv_bfloat16& h, __nv_bfloat16& l) {
    h = __float2bfloat16(v);
    l = __float2bfloat16(v - __bfloat162float(h));
}

/* ---------------- mma.sync / ldmatrix / cp.async wrappers ----------------- */
__device__ __forceinline__ void ldsm_x4(uint32_t* r, uint32_t addr) {
    asm volatile("ldmatrix.sync.aligned.m8n8.x4.shared.b16 {%0,%1,%2,%3}, [%4];"
        : "=r"(r[0]), "=r"(r[1]), "=r"(r[2]), "=r"(r[3]) : "r"(addr));
}
__device__ __forceinline__ void ldsm_x2(uint32_t* r, uint32_t addr) {
    asm volatile("ldmatrix.sync.aligned.m8n8.x2.shared.b16 {%0,%1}, [%2];"
        : "=r"(r[0]), "=r"(r[1]) : "r"(addr));
}
__device__ __forceinline__ void mma_bf16(float* c, const uint32_t* a, const uint32_t* b) {
    asm volatile(
        "mma.sync.aligned.m16n8k16.row.col.f32.bf16.bf16.f32 "
        "{%0,%1,%2,%3}, {%4,%5,%6,%7}, {%8,%9}, {%0,%1,%2,%3};"
        : "+f"(c[0]), "+f"(c[1]), "+f"(c[2]), "+f"(c[3])
        : "r"(a[0]), "r"(a[1]), "r"(a[2]), "r"(a[3]), "r"(b[0]), "r"(b[1]));
}
__device__ __forceinline__ void cp16(uint32_t dst, const void* src, int sz) {
    asm volatile("cp.async.cg.shared.global [%0], [%1], 16, %2;"
        :: "r"(dst), "l"(src), "r"(sz) : "memory");
}
__device__ __forceinline__ void cp_commit() {
    asm volatile("cp.async.commit_group;" ::: "memory");
}
template <int W> __device__ __forceinline__ void cp_wait() {
    asm volatile("cp.async.wait_group %0;" :: "n"(W) : "memory");
}

/* ======================================================================== */
/*  HMMA GEMM: C[M,N] = A[M,768] @ Bt[N,768]^T, bf16x3, cp.async 2-stage    */
/*  Dual-store epilogue: fp32 C + fp16 Ch                                   */
/* ======================================================================== */
#define LDA 40
#define ARR_B (128 * LDA * 2)     /* 10240 B per array */
#define STG_B (4 * ARR_B)         /* 40960 B per stage */
#define GSMEM (2 * STG_B)         /* 81920 B */
#define NCHUNK (KDIM / 32)        /* 24 */

__global__ __launch_bounds__(256, 2)
void mma_gemm_kernel(const __nv_bfloat16* __restrict__ Ahi,
                     const __nv_bfloat16* __restrict__ Alo,
                     const __nv_bfloat16* __restrict__ Bhi,
                     const __nv_bfloat16* __restrict__ Blo,
                     float* __restrict__ C, __half* __restrict__ Ch,
                     int M, int N) {
    extern __shared__ char smem[];
    const int t = threadIdx.x, lane = t & 31, wid = t >> 5;
    const int wm = wid >> 2, wn = wid & 3;
    const int rowBase = blockIdx.y * 128;
    const int colBase = blockIdx.x * 128;
    const uint32_t sb = smem_u32(smem);

    const int r0 = (2 * t) >> 2,     s0 = ((2 * t) & 3) * 8;
    const int r1 = (2 * t + 1) >> 2, s1 = ((2 * t + 1) & 3) * 8;
    const int av0 = (rowBase + r0) < M ? 16 : 0;
    const int av1 = (rowBase + r1) < M ? 16 : 0;
    const __nv_bfloat16* pAhi0 = Ahi + (size_t)(rowBase + r0) * KDIM + s0;
    const __nv_bfloat16* pAhi1 = Ahi + (size_t)(rowBase + r1) * KDIM + s1;
    const __nv_bfloat16* pAlo0 = Alo + (size_t)(rowBase + r0) * KDIM + s0;
    const __nv_bfloat16* pAlo1 = Alo + (size_t)(rowBase + r1) * KDIM + s1;
    const __nv_bfloat16* pBhi0 = Bhi + (size_t)(colBase + r0) * KDIM + s0;
    const __nv_bfloat16* pBhi1 = Bhi + (size_t)(colBase + r1) * KDIM + s1;
    const __nv_bfloat16* pBlo0 = Blo + (size_t)(colBase + r0) * KDIM + s0;
    const __nv_bfloat16* pBlo1 = Blo + (size_t)(colBase + r1) * KDIM + s1;
    const uint32_t d0 = (uint32_t)(r0 * LDA + s0) * 2;
    const uint32_t d1 = (uint32_t)(r1 * LDA + s1) * 2;

    float acc[4][4][4];
    #pragma unroll
    for (int i = 0; i < 4; i++)
        #pragma unroll
        for (int j = 0; j < 4; j++)
            #pragma unroll
            for (int q = 0; q < 4; q++) acc[i][j][q] = 0.f;

    {
        const uint32_t b = sb;
        cp16(b + d0, pAhi0, av0);               cp16(b + d1, pAhi1, av1);
        cp16(b + ARR_B + d0, pAlo0, av0);       cp16(b + ARR_B + d1, pAlo1, av1);
        cp16(b + 2 * ARR_B + d0, pBhi0, 16);    cp16(b + 2 * ARR_B + d1, pBhi1, 16);
        cp16(b + 3 * ARR_B + d0, pBlo0, 16);    cp16(b + 3 * ARR_B + d1, pBlo1, 16);
        cp_commit();
    }

    for (int c = 0; c < NCHUNK; c++) {
        const int st = c & 1;
        if (c + 1 < NCHUNK) {
            const int k0 = (c + 1) * 32;
            const uint32_t b = sb + ((c + 1) & 1) * STG_B;
            cp16(b + d0, pAhi0 + k0, av0);               cp16(b + d1, pAhi1 + k0, av1);
            cp16(b + ARR_B + d0, pAlo0 + k0, av0);       cp16(b + ARR_B + d1, pAlo1 + k0, av1);
            cp16(b + 2 * ARR_B + d0, pBhi0 + k0, 16);    cp16(b + 2 * ARR_B + d1, pBhi1 + k0, 16);
            cp16(b + 3 * ARR_B + d0, pBlo0 + k0, 16);    cp16(b + 3 * ARR_B + d1, pBlo1 + k0, 16);
            cp_commit();
            cp_wait<1>();
        } else {
            cp_wait<0>();
        }
        __syncthreads();

        const uint32_t sAhi = sb + st * STG_B;
        const uint32_t sAlo = sAhi + ARR_B;
        const uint32_t sBhi = sAhi + 2 * ARR_B;
        const uint32_t sBlo = sAhi + 3 * ARR_B;

        #pragma unroll
        for (int ks = 0; ks < 2; ks++) {
            const int kk = ks * 16;
            uint32_t ah[4][4], al[4][4];
            {
                const int r  = wm * 64 + (lane & 15);
                const int kc = kk + ((lane >> 4) << 3);
                #pragma unroll
                for (int mt = 0; mt < 4; mt++) {
                    uint32_t off = (uint32_t)((r + mt * 16) * LDA + kc) * 2;
                    ldsm_x4(ah[mt], sAhi + off);
                    ldsm_x4(al[mt], sAlo + off);
                }
            }
            {
                const int nr = wn * 32 + (lane & 7);
                const int kc = kk + (((lane >> 3) & 1) << 3);
                #pragma unroll
                for (int nt = 0; nt < 4; nt++) {
                    uint32_t bh[2], bl[2];
                    uint32_t off = (uint32_t)((nr + nt * 8) * LDA + kc) * 2;
                    ldsm_x2(bh, sBhi + off);
                    ldsm_x2(bl, sBlo + off);
                    #pragma unroll
                    for (int mt = 0; mt < 4; mt++) {
                        mma_bf16(acc[mt][nt], ah[mt], bh);
                        mma_bf16(acc[mt][nt], ah[mt], bl);
                        mma_bf16(acc[mt][nt], al[mt], bh);
                    }
                }
            }
        }
        __syncthreads();
    }

    /* dual epilogue: fp32 + fp16 */
    const int g = lane >> 2, tq = lane & 3;
    #pragma unroll
    for (int mt = 0; mt < 4; mt++) {
        int r0g = rowBase + wm * 64 + mt * 16 + g;
        #pragma unroll
        for (int nt = 0; nt < 4; nt++) {
            int col = colBase + wn * 32 + nt * 8 + 2 * tq;
            if (r0g < M) {
                *(float2*)&C[(size_t)r0g * N + col] =
                    make_float2(acc[mt][nt][0], acc[mt][nt][1]);
                *(__half2*)&Ch[(size_t)r0g * N + col] =
                    __floats2half2_rn(acc[mt][nt][0], acc[mt][nt][1]);
            }
            if (r0g + 8 < M) {
                *(float2*)&C[(size_t)(r0g + 8) * N + col] =
                    make_float2(acc[mt][nt][2], acc[mt][nt][3]);
                *(__half2*)&Ch[(size_t)(r0g + 8) * N + col] =
                    __floats2half2_rn(acc[mt][nt][2], acc[mt][nt][3]);
            }
        }
    }
}

/* ---------------- fp32 -> bf16 hi/lo elementwise split --------------------- */
__global__ void conv_split_kernel(const float* __restrict__ src,
                                  __nv_bfloat16* __restrict__ hi,
                                  __nv_bfloat16* __restrict__ lo, int n4) {
    int i = blockIdx.x * blockDim.x + threadIdx.x;
    if (i >= n4) return;
    float4 v = ((const float4*)src)[i];
    __nv_bfloat16 h0, h1, h2, h3, l0, l1, l2, l3;
    split2(v.x, h0, l0); split2(v.y, h1, l1);
    split2(v.z, h2, l2); split2(v.w, h3, l3);
    ((uint2*)hi)[i] = make_uint2(pk(h0, h1), pk(h2, h3));
    ((uint2*)lo)[i] = make_uint2(pk(l0, l1), pk(l2, l3));
}

/* ---------------- W[k][n] -> Wt[n][k] transpose + split -------------------- */
__global__ void trans_split_kernel(const float* __restrict__ W,
                                   __nv_bfloat16* __restrict__ Th,
                                   __nv_bfloat16* __restrict__ Tl,
                                   int K, int N) {
    __shared__ float tile[32][33];
    int k0 = blockIdx.y * 32, n0 = blockIdx.x * 32;
    int tx = threadIdx.x, ty = threadIdx.y;   /* 32 x 8 */
    #pragma unroll
    for (int i = 0; i < 32; i += 8)
        tile[ty + i][tx] = W[(size_t)(k0 + ty + i) * N + n0 + tx];
    __syncthreads();
    #pragma unroll
    for (int i = 0; i < 32; i += 8) {
        float v = tile[tx][ty + i];
        __nv_bfloat16 h, l;
        split2(v, h, l);
        size_t o = (size_t)(n0 + ty + i) * K + k0 + tx;
        Th[o] = h;
        Tl[o] = l;
    }
}

/* ---------------- init: zero deg + detect dtype (block 0) ------------------ */
__global__ void init_kernel(const int* ei32) {
    int i = blockIdx.x * 256 + threadIdx.x;
    if (i < N_NODES) g_deg[i] = 0;
    if (blockIdx.x == 0) {
        __shared__ int any;
        if (threadIdx.x == 0) any = 0;
        __syncthreads();
        int v = 0;
        for (int j = threadIdx.x; j < 1024; j += 256)
            v |= ei32[2 * j + 1];
        if (v) atomicOr(&any, 1);
        __syncthreads();
        if (threadIdx.x == 0) g_is64 = (any == 0) ? 1 : 0;
    }
}
__device__ __forceinline__ int edge_at(const void* ei, long long idx) {
    if (g_is64) return (int)((const long long*)ei)[idx];
    return ((const int*)ei)[idx];
}

/* ---------------- CSR build ------------------------------------------------ */
__global__ void count_kernel(const void* ei) {
    int e = blockIdx.x * blockDim.x + threadIdx.x;
    if (e >= ET) return;
    int d = (e < E_EDGES) ? edge_at(ei, (long long)E_EDGES + e) : (e - E_EDGES);
    atomicAdd(&g_deg[d], 1);
}
__global__ void bsum_kernel() {
    __shared__ int s[256];
    int i = blockIdx.x * 256 + threadIdx.x;
    s[threadIdx.x] = (i < N_NODES) ? g_deg[i] : 0;
    __syncthreads();
    for (int o = 128; o; o >>= 1) {
        if (threadIdx.x < o) s[threadIdx.x] += s[threadIdx.x + o];
        __syncthreads();
    }
    if (threadIdx.x == 0) g_bsum[blockIdx.x] = s[0];
}
__global__ void bscan_kernel() {
    __shared__ int s[128];
    int t = threadIdx.x;
    int v = (t < NBLK) ? g_bsum[t] : 0;
    s[t] = v;
    __syncthreads();
    for (int o = 1; o < 128; o <<= 1) {
        int u = (t >= o) ? s[t - o] : 0;
        __syncthreads();
        s[t] += u;
        __syncthreads();
    }
    g_boff[t] = s[t] - v;
    if (t == 0) g_rowptr[N_NODES] = ET;
}
__global__ void fscan_kernel() {
    __shared__ int s[256];
    int t = threadIdx.x;
    int i = blockIdx.x * 256 + t;
    int d = (i < N_NODES) ? g_deg[i] : 0;
    s[t] = d;
    __syncthreads();
    for (int o = 1; o < 256; o <<= 1) {
        int u = (t >= o) ? s[t - o] : 0;
        __syncthreads();
        s[t] += u;
        __syncthreads();
    }
    if (i < N_NODES) {
        int off = s[t] - d + g_boff[blockIdx.x];
        g_rowptr[i] = off;
        g_cursor[i] = off;
    }
}
__global__ void scatter_kernel(const void* ei) {
    int e = blockIdx.x * blockDim.x + threadIdx.x;
    if (e >= ET) return;
    int s, d;
    if (e < E_EDGES) {
        s = edge_at(ei, e);
        d = edge_at(ei, (long long)E_EDGES + e);
    } else {
        s = d = e - E_EDGES;
    }
    int slot = atomicAdd(&g_cursor[d], 1);
    g_col[slot] = s;
}

/* ---------------- attention coefficients ----------------------------------- */
__global__ void att_kernel(const float* __restrict__ xp,
                           const float* __restrict__ att_s,
                           const float* __restrict__ att_d,
                           float* __restrict__ as_out,
                           float* __restrict__ ad_out, int H) {
    int gw   = (blockIdx.x * blockDim.x + threadIdx.x) >> 5;
    int lane = threadIdx.x & 31;
    if (gw >= N_NODES * H) return;
    int n = gw / H, h = gw % H;
    const float* row = xp + (size_t)n * (H * HID) + h * HID;
    float s = 0.f, d = 0.f;
    #pragma unroll
    for (int c = lane; c < HID; c += 32) {
        float v = row[c];
        s += v * att_s[h * HID + c];
        d += v * att_d[h * HID + c];
    }
    s = warpSum(s);
    d = warpSum(d);
    if (lane == 0) {
        as_out[n * H + h] = s;
        ad_out[n * H + h] = d;
    }
}

/* ---------------- segment softmax, 3 heads fused (warp per node) ----------- */
/* stores UNNORMALIZED exp in alpha and 1/sum in g_inv1                       */
__global__ void softmax3_kernel(const float* __restrict__ asrc,
                                const float* __restrict__ adst) {
    int n    = (blockIdx.x * blockDim.x + threadIdx.x) >> 5;
    int lane = threadIdx.x & 31;
    if (n >= N_NODES) return;
    int st = g_rowptr[n], en = g_rowptr[n + 1];
    float ad0 = adst[n * 3 + 0], ad1 = adst[n * 3 + 1], ad2 = adst[n * 3 + 2];
    float m0 = -1e30f, m1 = -1e30f, m2 = -1e30f;
    for (int s = st + lane; s < en; s += 32) {
        int col = g_col[s];
        float v0 = asrc[col * 3 + 0] + ad0;
        float v1 = asrc[col * 3 + 1] + ad1;
        float v2 = asrc[col * 3 + 2] + ad2;
        v0 = (v0 > 0.f) ? v0 : 0.2f * v0;
        v1 = (v1 > 0.f) ? v1 : 0.2f * v1;
        v2 = (v2 > 0.f) ? v2 : 0.2f * v2;
        g_alpha[(size_t)s * 3 + 0] = v0;
        g_alpha[(size_t)s * 3 + 1] = v1;
        g_alpha[(size_t)s * 3 + 2] = v2;
        m0 = fmaxf(m0, v0); m1 = fmaxf(m1, v1); m2 = fmaxf(m2, v2);
    }
    m0 = warpMax(m0); m1 = warpMax(m1); m2 = warpMax(m2);
    float s0 = 0.f, s1 = 0.f, s2 = 0.f;
    for (int s = st + lane; s < en; s += 32) {
        float e0 = __expf(g_alpha[(size_t)s * 3 + 0] - m0);
        float e1 = __expf(g_alpha[(size_t)s * 3 + 1] - m1);
        float e2 = __expf(g_alpha[(size_t)s * 3 + 2] - m2);
        g_alpha[(size_t)s * 3 + 0] = e0;
        g_alpha[(size_t)s * 3 + 1] = e1;
        g_alpha[(size_t)s * 3 + 2] = e2;
        s0 += e0; s1 += e1; s2 += e2;
    }
    s0 = warpSum(s0); s1 = warpSum(s1); s2 = warpSum(s2);
    if (lane == 0) {
        g_inv1[n * 3 + 0] = 1.f / s0;
        g_inv1[n * 3 + 1] = 1.f / s1;
        g_inv1[n * 3 + 2] = 1.f / s2;
    }
}

/* single-head version for layer 2 */
__global__ void softmax1_kernel(const float* __restrict__ asrc,
                                const float* __restrict__ adst) {
    int n    = (blockIdx.x * blockDim.x + threadIdx.x) >> 5;
    int lane = threadIdx.x & 31;
    if (n >= N_NODES) return;
    int st = g_rowptr[n], en = g_rowptr[n + 1];
    float ad = adst[n];
    float mx = -1e30f;
    for (int s = st + lane; s < en; s += 32) {
        float v = asrc[g_col[s]] + ad;
        v = (v > 0.f) ? v : 0.2f * v;
        g_alpha[s] = v;
        mx = fmaxf(mx, v);
    }
    mx = warpMax(mx);
    float sum = 0.f;
    for (int s = st + lane; s < en; s += 32) {
        float e = __expf(g_alpha[s] - mx);
        g_alpha[s] = e;
        sum += e;
    }
    sum = warpSum(sum);
    if (lane == 0) g_inv2[n] = 1.f / sum;
}

/* ---------------- layer-1 aggregation (fp16 reads) + bias + ELU ------------ */
__global__ __launch_bounds__(192)
void agg1_kernel(const float* __restrict__ b1) {
    int n = blockIdx.x;
    int t = threadIdx.x;
    int head = t >> 6;
    int base = head * 256 + (t & 63) * 4;
    int st = g_rowptr[n], en = g_rowptr[n + 1];
    float4 a = make_float4(0.f, 0.f, 0.f, 0.f);
    #pragma unroll 2
    for (int s = st; s < en; s++) {
        float w = g_alpha[(size_t)s * 3 + head];
        uint2 u = *(const uint2*)(g_xp1h + (size_t)g_col[s] * F1 + base);
        float2 c0 = __half22float2(*(__half2*)&u.x);
        float2 c1 = __half22float2(*(__half2*)&u.y);
        a.x += w * c0.x; a.y += w * c0.y; a.z += w * c1.x; a.w += w * c1.y;
    }
    float inv = g_inv1[n * 3 + head];
    float4 b = *(const float4*)(b1 + base);
    a.x = a.x * inv + b.x; a.y = a.y * inv + b.y;
    a.z = a.z * inv + b.z; a.w = a.w * inv + b.w;
    a.x = (a.x > 0.f) ? a.x : expm1f(a.x);
    a.y = (a.y > 0.f) ? a.y : expm1f(a.y);
    a.z = (a.z > 0.f) ? a.z : expm1f(a.z);
    a.w = (a.w > 0.f) ? a.w : expm1f(a.w);
    __nv_bfloat16 h0, h1, h2, h3, l0, l1, l2, l3;
    split2(a.x, h0, l0); split2(a.y, h1, l1);
    split2(a.z, h2, l2); split2(a.w, h3, l3);
    size_t o4 = ((size_t)n * F1 + base) / 4;
    ((uint2*)gh_hi)[o4] = make_uint2(pk(h0, h1), pk(h2, h3));
    ((uint2*)gh_lo)[o4] = make_uint2(pk(l0, l1), pk(l2, l3));
}

/* ---------------- layer-2 aggregation (fp16 reads) + bias -> out ----------- */
__global__ __launch_bounds__(64)
void agg2_kernel(const float* __restrict__ b2, float* __restrict__ out) {
    int n = blockIdx.x;
    int c4 = threadIdx.x * 4;
    int st = g_rowptr[n], en = g_rowptr[n + 1];
    float4 a = make_float4(0.f, 0.f, 0.f, 0.f);
    #pragma unroll 2
    for (int s = st; s < en; s++) {
        float w = g_alpha[s];
        uint2 u = *(const uint2*)(g_xp2h + (size_t)g_col[s] * HID + c4);
        float2 c0 = __half22float2(*(__half2*)&u.x);
        float2 c1 = __half22float2(*(__half2*)&u.y);
        a.x += w * c0.x; a.y += w * c0.y; a.z += w * c1.x; a.w += w * c1.y;
    }
    float inv = g_inv2[n];
    float4 b = *(const float4*)(b2 + c4);
    a.x = a.x * inv + b.x; a.y = a.y * inv + b.y;
    a.z = a.z * inv + b.z; a.w = a.w * inv + b.w;
    *(float4*)(out + (size_t)n * HID + c4) = a;
}

/* ---------------- launch --------------------------------------------------- */
extern "C" void kernel_launch(void* const* d_in, const int* in_sizes, int n_in,
                              void* d_out, int out_size) {
    const float* x   = (const float*)d_in[0];
    const void*  ei  = d_in[1];
    const float* W1  = (const float*)d_in[2];
    const float* as1 = (const float*)d_in[3];
    const float* ad1 = (const float*)d_in[4];
    const float* b1  = (const float*)d_in[5];
    const float* W2  = (const float*)d_in[6];
    const float* as2 = (const float*)d_in[7];
    const float* ad2 = (const float*)d_in[8];
    const float* b2  = (const float*)d_in[9];
    float* out = (float*)d_out;

    void *p_xp1, *p_xp2, *p_x1h, *p_x2h, *p_as1, *p_ad1, *p_as2, *p_ad2;
    void *p_xhi, *p_xlo, *p_hhi, *p_hlo;
    void *p_w1h, *p_w1l, *p_w2h, *p_w2l;
    cudaGetSymbolAddress(&p_xp1,   g_xp1);
    cudaGetSymbolAddress(&p_xp2,   g_xp2);
    cudaGetSymbolAddress(&p_x1h,   g_xp1h);
    cudaGetSymbolAddress(&p_x2h,   g_xp2h);
    cudaGetSymbolAddress(&p_as1,   g_asrc1);
    cudaGetSymbolAddress(&p_ad1,   g_adst1);
    cudaGetSymbolAddress(&p_as2,   g_asrc2);
    cudaGetSymbolAddress(&p_ad2,   g_adst2);
    cudaGetSymbolAddress(&p_xhi,   gx_hi);
    cudaGetSymbolAddress(&p_xlo,   gx_lo);
    cudaGetSymbolAddress(&p_hhi,   gh_hi);
    cudaGetSymbolAddress(&p_hlo,   gh_lo);
    cudaGetSymbolAddress(&p_w1h,   gw1t_hi);
    cudaGetSymbolAddress(&p_w1l,   gw1t_lo);
    cudaGetSymbolAddress(&p_w2h,   gw2t_hi);
    cudaGetSymbolAddress(&p_w2l,   gw2t_lo);

    cudaFuncSetAttribute(mma_gemm_kernel,
                         cudaFuncAttributeMaxDynamicSharedMemorySize, GSMEM);

    /* launches 1-5: conversion + CSR start (GEMM1 is launch #6 for ncu) */
    {
        int n4 = N_NODES * IN_DIM / 4;
        conv_split_kernel<<<(n4 + 255) / 256, 256>>>(
            x, (__nv_bfloat16*)p_xhi, (__nv_bfloat16*)p_xlo, n4);
        trans_split_kernel<<<dim3(F1 / 32, KDIM / 32), dim3(32, 8)>>>(
            W1, (__nv_bfloat16*)p_w1h, (__nv_bfloat16*)p_w1l, KDIM, F1);
        trans_split_kernel<<<dim3(HID / 32, KDIM / 32), dim3(32, 8)>>>(
            W2, (__nv_bfloat16*)p_w2h, (__nv_bfloat16*)p_w2l, KDIM, HID);
    }
    init_kernel<<<NBLK, 256>>>((const int*)ei);
    count_kernel<<<(ET + 255) / 256, 256>>>(ei);

    /* launch #6: GEMM1 */
    mma_gemm_kernel<<<dim3(F1 / 128, (N_NODES + 127) / 128), 256, GSMEM>>>(
        (const __nv_bfloat16*)p_xhi, (const __nv_bfloat16*)p_xlo,
        (const __nv_bfloat16*)p_w1h, (const __nv_bfloat16*)p_w1l,
        (float*)p_xp1, (__half*)p_x1h, N_NODES, F1);

    /* rest of CSR build */
    bsum_kernel<<<NBLK, 256>>>();
    bscan_kernel<<<1, 128>>>();
    fscan_kernel<<<NBLK, 256>>>();
    scatter_kernel<<<(ET + 255) / 256, 256>>>(ei);

    /* layer 1 edge phase */
    att_kernel<<<(N_NODES * H1 * 32 + 255) / 256, 256>>>(
        (const float*)p_xp1, as1, ad1, (float*)p_as1, (float*)p_ad1, H1);
    softmax3_kernel<<<(N_NODES * 32 + 255) / 256, 256>>>(
        (const float*)p_as1, (const float*)p_ad1);
    agg1_kernel<<<N_NODES, 192>>>(b1);

    /* layer 2 */
    mma_gemm_kernel<<<dim3(HID / 128, (N_NODES + 127) / 128), 256, GSMEM>>>(
        (const __nv_bfloat16*)p_hhi, (const __nv_bfloat16*)p_hlo,
        (const __nv_bfloat16*)p_w2h, (const __nv_bfloat16*)p_w2l,
        (float*)p_xp2, (__half*)p_x2h, N_NODES, HID);
    att_kernel<<<(N_NODES * 32 + 255) / 256, 256>>>(
        (const float*)p_xp2, as2, ad2, (float*)p_as2, (float*)p_ad2, 1);
    softmax1_kernel<<<(N_NODES * 32 + 255) / 256, 256>>>(
        (const float*)p_as2, (const float*)p_ad2);
    agg2_kernel<<<N_NODES, 64>>>(b2, out);
}

// round 7
// speedup vs baseline: 2.3319x; 1.0686x over previous
#include <cuda_runtime.h>
#include <cuda_bf16.h>
#include <cuda_fp16.h>
#include <math.h>
#include <stdint.h>

#define N_NODES 20000
#define E_EDGES 320000
#define ET      (E_EDGES + N_NODES)   /* 340000 with self loops */
#define IN_DIM  768
#define HID     256
#define H1      3
#define F1      (H1 * HID)            /* 768 */
#define KDIM    768
#define NBLK    ((N_NODES + 255) / 256)   /* 79 */

/* ---------------- scratch (device globals, no allocs allowed) ------------- */
__device__ __half g_xp1h[(size_t)N_NODES * F1];
__device__ __half g_xp2h[(size_t)N_NODES * HID];
__device__ __nv_bfloat16 gx_hi[(size_t)N_NODES * IN_DIM];
__device__ __nv_bfloat16 gx_lo[(size_t)N_NODES * IN_DIM];
__device__ __nv_bfloat16 gh_hi[(size_t)N_NODES * F1];
__device__ __nv_bfloat16 gh_lo[(size_t)N_NODES * F1];
__device__ __nv_bfloat16 gw1t_hi[F1 * KDIM];     /* [n][k] */
__device__ __nv_bfloat16 gw1t_lo[F1 * KDIM];
__device__ __nv_bfloat16 gw2t_hi[HID * KDIM];
__device__ __nv_bfloat16 gw2t_lo[HID * KDIM];
__device__ float g_asrc1[N_NODES * H1];
__device__ float g_adst1[N_NODES * H1];
__device__ float g_asrc2[N_NODES];
__device__ float g_adst2[N_NODES];
__device__ float g_inv1[N_NODES * H1];
__device__ float g_inv2[N_NODES];
__device__ int   g_deg[N_NODES];
__device__ int   g_rowptr[N_NODES + 1];
__device__ int   g_cursor[N_NODES];
__device__ int   g_col[ET];
__device__ float g_alpha[(size_t)ET * H1];
__device__ int   g_bsum[128];
__device__ int   g_boff[128];
__device__ int   g_is64;

/* ---------------- helpers ------------------------------------------------- */
__device__ __forceinline__ float warpSum(float v) {
    #pragma unroll
    for (int o = 16; o; o >>= 1) v += __shfl_xor_sync(0xffffffffu, v, o);
    return v;
}
__device__ __forceinline__ float warpMax(float v) {
    #pragma unroll
    for (int o = 16; o; o >>= 1) v = fmaxf(v, __shfl_xor_sync(0xffffffffu, v, o));
    return v;
}
__device__ __forceinline__ uint32_t smem_u32(const void* p) {
    uint32_t a;
    asm("{ .reg .u64 t; cvta.to.shared.u64 t, %1; cvt.u32.u64 %0, t; }"
        : "=r"(a) : "l"(p));
    return a;
}
__device__ __forceinline__ uint32_t pk(__nv_bfloat16 a, __nv_bfloat16 b) {
    uint16_t ua = *(uint16_t*)&a, ub = *(uint16_t*)&b;
    return (uint32_t)ua | ((uint32_t)ub << 16);
}
__device__ __forceinline__ void split2(float v, __nv_bfloat16& h, __nv_bfloat16& l) {
    h = __float2bfloat16(v);
    l = __float2bfloat16(v - __bfloat162float(h));
}

/* ---------------- mma.sync / ldmatrix / cp.async wrappers ----------------- */
__device__ __forceinline__ void ldsm_x4(uint32_t* r, uint32_t addr) {
    asm volatile("ldmatrix.sync.aligned.m8n8.x4.shared.b16 {%0,%1,%2,%3}, [%4];"
        : "=r"(r[0]), "=r"(r[1]), "=r"(r[2]), "=r"(r[3]) : "r"(addr));
}
__device__ __forceinline__ void ldsm_x2(uint32_t* r, uint32_t addr) {
    asm volatile("ldmatrix.sync.aligned.m8n8.x2.shared.b16 {%0,%1}, [%2];"
        : "=r"(r[0]), "=r"(r[1]) : "r"(addr));
}
__device__ __forceinline__ void mma_bf16(float* c, const uint32_t* a, const uint32_t* b) {
    asm volatile(
        "mma.sync.aligned.m16n8k16.row.col.f32.bf16.bf16.f32 "
        "{%0,%1,%2,%3}, {%4,%5,%6,%7}, {%8,%9}, {%0,%1,%2,%3};"
        : "+f"(c[0]), "+f"(c[1]), "+f"(c[2]), "+f"(c[3])
        : "r"(a[0]), "r"(a[1]), "r"(a[2]), "r"(a[3]), "r"(b[0]), "r"(b[1]));
}
__device__ __forceinline__ void cp16(uint32_t dst, const void* src, int sz) {
    asm volatile("cp.async.cg.shared.global [%0], [%1], 16, %2;"
        :: "r"(dst), "l"(src), "r"(sz) : "memory");
}
__device__ __forceinline__ void cp_commit() {
    asm volatile("cp.async.commit_group;" ::: "memory");
}
template <int W> __device__ __forceinline__ void cp_wait() {
    asm volatile("cp.async.wait_group %0;" :: "n"(W) : "memory");
}

/* ======================================================================== */
/*  HMMA GEMM: Ch[M,N](fp16) = A[M,768] @ Bt[N,768]^T, bf16x3, cp.async     */
/*  Fused epilogue: a_src/a_dst attention dot-products via atomics          */
/* ======================================================================== */
#define LDA 40
#define ARR_B (128 * LDA * 2)     /* 10240 B per array */
#define STG_B (4 * ARR_B)         /* 40960 B per stage */
#define GSMEM (2 * STG_B)         /* 81920 B */
#define NCHUNK (KDIM / 32)        /* 24 */

__global__ __launch_bounds__(256, 2)
void mma_gemm_kernel(const __nv_bfloat16* __restrict__ Ahi,
                     const __nv_bfloat16* __restrict__ Alo,
                     const __nv_bfloat16* __restrict__ Bhi,
                     const __nv_bfloat16* __restrict__ Blo,
                     __half* __restrict__ Ch,
                     const float* __restrict__ att_s,
                     const float* __restrict__ att_d,
                     float* __restrict__ asrc,
                     float* __restrict__ adst,
                     int H, int M, int N) {
    extern __shared__ char smem[];
    const int t = threadIdx.x, lane = t & 31, wid = t >> 5;
    const int wm = wid >> 2, wn = wid & 3;
    const int rowBase = blockIdx.y * 128;
    const int colBase = blockIdx.x * 128;
    const uint32_t sb = smem_u32(smem);

    const int r0 = (2 * t) >> 2,     s0 = ((2 * t) & 3) * 8;
    const int r1 = (2 * t + 1) >> 2, s1 = ((2 * t + 1) & 3) * 8;
    const int av0 = (rowBase + r0) < M ? 16 : 0;
    const int av1 = (rowBase + r1) < M ? 16 : 0;
    const __nv_bfloat16* pAhi0 = Ahi + (size_t)(rowBase + r0) * KDIM + s0;
    const __nv_bfloat16* pAhi1 = Ahi + (size_t)(rowBase + r1) * KDIM + s1;
    const __nv_bfloat16* pAlo0 = Alo + (size_t)(rowBase + r0) * KDIM + s0;
    const __nv_bfloat16* pAlo1 = Alo + (size_t)(rowBase + r1) * KDIM + s1;
    const __nv_bfloat16* pBhi0 = Bhi + (size_t)(colBase + r0) * KDIM + s0;
    const __nv_bfloat16* pBhi1 = Bhi + (size_t)(colBase + r1) * KDIM + s1;
    const __nv_bfloat16* pBlo0 = Blo + (size_t)(colBase + r0) * KDIM + s0;
    const __nv_bfloat16* pBlo1 = Blo + (size_t)(colBase + r1) * KDIM + s1;
    const uint32_t d0 = (uint32_t)(r0 * LDA + s0) * 2;
    const uint32_t d1 = (uint32_t)(r1 * LDA + s1) * 2;

    float acc[4][4][4];
    #pragma unroll
    for (int i = 0; i < 4; i++)
        #pragma unroll
        for (int j = 0; j < 4; j++)
            #pragma unroll
            for (int q = 0; q < 4; q++) acc[i][j][q] = 0.f;

    {
        const uint32_t b = sb;
        cp16(b + d0, pAhi0, av0);               cp16(b + d1, pAhi1, av1);
        cp16(b + ARR_B + d0, pAlo0, av0);       cp16(b + ARR_B + d1, pAlo1, av1);
        cp16(b + 2 * ARR_B + d0, pBhi0, 16);    cp16(b + 2 * ARR_B + d1, pBhi1, 16);
        cp16(b + 3 * ARR_B + d0, pBlo0, 16);    cp16(b + 3 * ARR_B + d1, pBlo1, 16);
        cp_commit();
    }

    for (int c = 0; c < NCHUNK; c++) {
        const int st = c & 1;
        if (c + 1 < NCHUNK) {
            const int k0 = (c + 1) * 32;
            const uint32_t b = sb + ((c + 1) & 1) * STG_B;
            cp16(b + d0, pAhi0 + k0, av0);               cp16(b + d1, pAhi1 + k0, av1);
            cp16(b + ARR_B + d0, pAlo0 + k0, av0);       cp16(b + ARR_B + d1, pAlo1 + k0, av1);
            cp16(b + 2 * ARR_B + d0, pBhi0 + k0, 16);    cp16(b + 2 * ARR_B + d1, pBhi1 + k0, 16);
            cp16(b + 3 * ARR_B + d0, pBlo0 + k0, 16);    cp16(b + 3 * ARR_B + d1, pBlo1 + k0, 16);
            cp_commit();
            cp_wait<1>();
        } else {
            cp_wait<0>();
        }
        __syncthreads();

        const uint32_t sAhi = sb + st * STG_B;
        const uint32_t sAlo = sAhi + ARR_B;
        const uint32_t sBhi = sAhi + 2 * ARR_B;
        const uint32_t sBlo = sAhi + 3 * ARR_B;

        #pragma unroll
        for (int ks = 0; ks < 2; ks++) {
            const int kk = ks * 16;
            uint32_t ah[4][4], al[4][4];
            {
                const int r  = wm * 64 + (lane & 15);
                const int kc = kk + ((lane >> 4) << 3);
                #pragma unroll
                for (int mt = 0; mt < 4; mt++) {
                    uint32_t off = (uint32_t)((r + mt * 16) * LDA + kc) * 2;
                    ldsm_x4(ah[mt], sAhi + off);
                    ldsm_x4(al[mt], sAlo + off);
                }
            }
            {
                const int nr = wn * 32 + (lane & 7);
                const int kc = kk + (((lane >> 3) & 1) << 3);
                #pragma unroll
                for (int nt = 0; nt < 4; nt++) {
                    uint32_t bh[2], bl[2];
                    uint32_t off = (uint32_t)((nr + nt * 8) * LDA + kc) * 2;
                    ldsm_x2(bh, sBhi + off);
                    ldsm_x2(bl, sBlo + off);
                    #pragma unroll
                    for (int mt = 0; mt < 4; mt++) {
                        mma_bf16(acc[mt][nt], ah[mt], bh);
                        mma_bf16(acc[mt][nt], ah[mt], bl);
                        mma_bf16(acc[mt][nt], al[mt], bh);
                    }
                }
            }
        }
        __syncthreads();
    }

    /* ---- epilogue: fp16 store + fused attention dot products ------------- */
    const int g = lane >> 2, tq = lane & 3;
    const int h = (H > 1) ? (colBase >> 8) : 0;   /* head index (256-wide heads) */

    float s_c[8], d_c[8];
    #pragma unroll
    for (int nt = 0; nt < 4; nt++) {
        int colg = colBase + wn * 32 + nt * 8 + 2 * tq;
        s_c[2 * nt]     = att_s[colg];
        s_c[2 * nt + 1] = att_s[colg + 1];
        d_c[2 * nt]     = att_d[colg];
        d_c[2 * nt + 1] = att_d[colg + 1];
    }

    #pragma unroll
    for (int mt = 0; mt < 4; mt++) {
        int r0g = rowBase + wm * 64 + mt * 16 + g;
        float ps0 = 0.f, pd0 = 0.f, ps1 = 0.f, pd1 = 0.f;
        #pragma unroll
        for (int nt = 0; nt < 4; nt++) {
            int col = colBase + wn * 32 + nt * 8 + 2 * tq;
            if (r0g < M)
                *(__half2*)&Ch[(size_t)r0g * N + col] =
                    __floats2half2_rn(acc[mt][nt][0], acc[mt][nt][1]);
            if (r0g + 8 < M)
                *(__half2*)&Ch[(size_t)(r0g + 8) * N + col] =
                    __floats2half2_rn(acc[mt][nt][2], acc[mt][nt][3]);
            ps0 += acc[mt][nt][0] * s_c[2 * nt] + acc[mt][nt][1] * s_c[2 * nt + 1];
            pd0 += acc[mt][nt][0] * d_c[2 * nt] + acc[mt][nt][1] * d_c[2 * nt + 1];
            ps1 += acc[mt][nt][2] * s_c[2 * nt] + acc[mt][nt][3] * s_c[2 * nt + 1];
            pd1 += acc[mt][nt][2] * d_c[2 * nt] + acc[mt][nt][3] * d_c[2 * nt + 1];
        }
        /* reduce over tq lanes (bits 0-1 of lane) */
        #pragma unroll
        for (int o = 1; o <= 2; o <<= 1) {
            ps0 += __shfl_xor_sync(0xffffffffu, ps0, o);
            pd0 += __shfl_xor_sync(0xffffffffu, pd0, o);
            ps1 += __shfl_xor_sync(0xffffffffu, ps1, o);
            pd1 += __shfl_xor_sync(0xffffffffu, pd1, o);
        }
        if (tq == 0) {
            if (r0g < M) {
                atomicAdd(&asrc[r0g * H + h], ps0);
                atomicAdd(&adst[r0g * H + h], pd0);
            }
            if (r0g + 8 < M) {
                atomicAdd(&asrc[(r0g + 8) * H + h], ps1);
                atomicAdd(&adst[(r0g + 8) * H + h], pd1);
            }
        }
    }
}

/* ---------------- fp32 -> bf16 hi/lo elementwise split --------------------- */
__global__ void conv_split_kernel(const float* __restrict__ src,
                                  __nv_bfloat16* __restrict__ hi,
                                  __nv_bfloat16* __restrict__ lo, int n4) {
    int i = blockIdx.x * blockDim.x + threadIdx.x;
    if (i >= n4) return;
    float4 v = ((const float4*)src)[i];
    __nv_bfloat16 h0, h1, h2, h3, l0, l1, l2, l3;
    split2(v.x, h0, l0); split2(v.y, h1, l1);
    split2(v.z, h2, l2); split2(v.w, h3, l3);
    ((uint2*)hi)[i] = make_uint2(pk(h0, h1), pk(h2, h3));
    ((uint2*)lo)[i] = make_uint2(pk(l0, l1), pk(l2, l3));
}

/* ---------------- W[k][n] -> Wt[n][k] transpose + split -------------------- */
__global__ void trans_split_kernel(const float* __restrict__ W,
                                   __nv_bfloat16* __restrict__ Th,
                                   __nv_bfloat16* __restrict__ Tl,
                                   int K, int N) {
    __shared__ float tile[32][33];
    int k0 = blockIdx.y * 32, n0 = blockIdx.x * 32;
    int tx = threadIdx.x, ty = threadIdx.y;   /* 32 x 8 */
    #pragma unroll
    for (int i = 0; i < 32; i += 8)
        tile[ty + i][tx] = W[(size_t)(k0 + ty + i) * N + n0 + tx];
    __syncthreads();
    #pragma unroll
    for (int i = 0; i < 32; i += 8) {
        float v = tile[tx][ty + i];
        __nv_bfloat16 h, l;
        split2(v, h, l);
        size_t o = (size_t)(n0 + ty + i) * K + k0 + tx;
        Th[o] = h;
        Tl[o] = l;
    }
}

/* ---------------- init: zero deg + att accumulators + detect dtype --------- */
__global__ void init_kernel(const int* ei32) {
    int i = blockIdx.x * 256 + threadIdx.x;
    if (i < N_NODES) g_deg[i] = 0;
    for (int j = i; j < N_NODES * H1; j += NBLK * 256) {
        g_asrc1[j] = 0.f;
        g_adst1[j] = 0.f;
    }
    if (i < N_NODES) {
        g_asrc2[i] = 0.f;
        g_adst2[i] = 0.f;
    }
    if (blockIdx.x == 0) {
        __shared__ int any;
        if (threadIdx.x == 0) any = 0;
        __syncthreads();
        int v = 0;
        for (int j = threadIdx.x; j < 1024; j += 256)
            v |= ei32[2 * j + 1];
        if (v) atomicOr(&any, 1);
        __syncthreads();
        if (threadIdx.x == 0) g_is64 = (any == 0) ? 1 : 0;
    }
}
__device__ __forceinline__ int edge_at(const void* ei, long long idx) {
    if (g_is64) return (int)((const long long*)ei)[idx];
    return ((const int*)ei)[idx];
}

/* ---------------- CSR build ------------------------------------------------ */
__global__ void count_kernel(const void* ei) {
    int e = blockIdx.x * blockDim.x + threadIdx.x;
    if (e >= ET) return;
    int d = (e < E_EDGES) ? edge_at(ei, (long long)E_EDGES + e) : (e - E_EDGES);
    atomicAdd(&g_deg[d], 1);
}
__global__ void bsum_kernel() {
    __shared__ int s[256];
    int i = blockIdx.x * 256 + threadIdx.x;
    s[threadIdx.x] = (i < N_NODES) ? g_deg[i] : 0;
    __syncthreads();
    for (int o = 128; o; o >>= 1) {
        if (threadIdx.x < o) s[threadIdx.x] += s[threadIdx.x + o];
        __syncthreads();
    }
    if (threadIdx.x == 0) g_bsum[blockIdx.x] = s[0];
}
__global__ void bscan_kernel() {
    __shared__ int s[128];
    int t = threadIdx.x;
    int v = (t < NBLK) ? g_bsum[t] : 0;
    s[t] = v;
    __syncthreads();
    for (int o = 1; o < 128; o <<= 1) {
        int u = (t >= o) ? s[t - o] : 0;
        __syncthreads();
        s[t] += u;
        __syncthreads();
    }
    g_boff[t] = s[t] - v;
    if (t == 0) g_rowptr[N_NODES] = ET;
}
__global__ void fscan_kernel() {
    __shared__ int s[256];
    int t = threadIdx.x;
    int i = blockIdx.x * 256 + t;
    int d = (i < N_NODES) ? g_deg[i] : 0;
    s[t] = d;
    __syncthreads();
    for (int o = 1; o < 256; o <<= 1) {
        int u = (t >= o) ? s[t - o] : 0;
        __syncthreads();
        s[t] += u;
        __syncthreads();
    }
    if (i < N_NODES) {
        int off = s[t] - d + g_boff[blockIdx.x];
        g_rowptr[i] = off;
        g_cursor[i] = off;
    }
}
__global__ void scatter_kernel(const void* ei) {
    int e = blockIdx.x * blockDim.x + threadIdx.x;
    if (e >= ET) return;
    int s, d;
    if (e < E_EDGES) {
        s = edge_at(ei, e);
        d = edge_at(ei, (long long)E_EDGES + e);
    } else {
        s = d = e - E_EDGES;
    }
    int slot = atomicAdd(&g_cursor[d], 1);
    g_col[slot] = s;
}

/* ---------------- segment softmax, 3 heads fused (warp per node) ----------- */
__global__ void softmax3_kernel(const float* __restrict__ asrc,
                                const float* __restrict__ adst) {
    int n    = (blockIdx.x * blockDim.x + threadIdx.x) >> 5;
    int lane = threadIdx.x & 31;
    if (n >= N_NODES) return;
    int st = g_rowptr[n], en = g_rowptr[n + 1];
    float ad0 = adst[n * 3 + 0], ad1 = adst[n * 3 + 1], ad2 = adst[n * 3 + 2];
    float m0 = -1e30f, m1 = -1e30f, m2 = -1e30f;
    for (int s = st + lane; s < en; s += 32) {
        int col = g_col[s];
        float v0 = asrc[col * 3 + 0] + ad0;
        float v1 = asrc[col * 3 + 1] + ad1;
        float v2 = asrc[col * 3 + 2] + ad2;
        v0 = (v0 > 0.f) ? v0 : 0.2f * v0;
        v1 = (v1 > 0.f) ? v1 : 0.2f * v1;
        v2 = (v2 > 0.f) ? v2 : 0.2f * v2;
        g_alpha[(size_t)s * 3 + 0] = v0;
        g_alpha[(size_t)s * 3 + 1] = v1;
        g_alpha[(size_t)s * 3 + 2] = v2;
        m0 = fmaxf(m0, v0); m1 = fmaxf(m1, v1); m2 = fmaxf(m2, v2);
    }
    m0 = warpMax(m0); m1 = warpMax(m1); m2 = warpMax(m2);
    float s0 = 0.f, s1 = 0.f, s2 = 0.f;
    for (int s = st + lane; s < en; s += 32) {
        float e0 = __expf(g_alpha[(size_t)s * 3 + 0] - m0);
        float e1 = __expf(g_alpha[(size_t)s * 3 + 1] - m1);
        float e2 = __expf(g_alpha[(size_t)s * 3 + 2] - m2);
        g_alpha[(size_t)s * 3 + 0] = e0;
        g_alpha[(size_t)s * 3 + 1] = e1;
        g_alpha[(size_t)s * 3 + 2] = e2;
        s0 += e0; s1 += e1; s2 += e2;
    }
    s0 = warpSum(s0); s1 = warpSum(s1); s2 = warpSum(s2);
    if (lane == 0) {
        g_inv1[n * 3 + 0] = 1.f / s0;
        g_inv1[n * 3 + 1] = 1.f / s1;
        g_inv1[n * 3 + 2] = 1.f / s2;
    }
}

/* single-head version for layer 2 */
__global__ void softmax1_kernel(const float* __restrict__ asrc,
                                const float* __restrict__ adst) {
    int n    = (blockIdx.x * blockDim.x + threadIdx.x) >> 5;
    int lane = threadIdx.x & 31;
    if (n >= N_NODES) return;
    int st = g_rowptr[n], en = g_rowptr[n + 1];
    float ad = adst[n];
    float mx = -1e30f;
    for (int s = st + lane; s < en; s += 32) {
        float v = asrc[g_col[s]] + ad;
        v = (v > 0.f) ? v : 0.2f * v;
        g_alpha[s] = v;
        mx = fmaxf(mx, v);
    }
    mx = warpMax(mx);
    float sum = 0.f;
    for (int s = st + lane; s < en; s += 32) {
        float e = __expf(g_alpha[s] - mx);
        g_alpha[s] = e;
        sum += e;
    }
    sum = warpSum(sum);
    if (lane == 0) g_inv2[n] = 1.f / sum;
}

/* ---------------- layer-1 aggregation (fp16 reads) + bias + ELU ------------ */
__global__ __launch_bounds__(192)
void agg1_kernel(const float* __restrict__ b1) {
    int n = blockIdx.x;
    int t = threadIdx.x;
    int head = t >> 6;
    int base = head * 256 + (t & 63) * 4;
    int st = g_rowptr[n], en = g_rowptr[n + 1];
    float4 a = make_float4(0.f, 0.f, 0.f, 0.f);
    #pragma unroll 4
    for (int s = st; s < en; s++) {
        float w = g_alpha[(size_t)s * 3 + head];
        uint2 u = *(const uint2*)(g_xp1h + (size_t)g_col[s] * F1 + base);
        float2 c0 = __half22float2(*(__half2*)&u.x);
        float2 c1 = __half22float2(*(__half2*)&u.y);
        a.x += w * c0.x; a.y += w * c0.y; a.z += w * c1.x; a.w += w * c1.y;
    }
    float inv = g_inv1[n * 3 + head];
    float4 b = *(const float4*)(b1 + base);
    a.x = a.x * inv + b.x; a.y = a.y * inv + b.y;
    a.z = a.z * inv + b.z; a.w = a.w * inv + b.w;
    a.x = (a.x > 0.f) ? a.x : expm1f(a.x);
    a.y = (a.y > 0.f) ? a.y : expm1f(a.y);
    a.z = (a.z > 0.f) ? a.z : expm1f(a.z);
    a.w = (a.w > 0.f) ? a.w : expm1f(a.w);
    __nv_bfloat16 h0, h1, h2, h3, l0, l1, l2, l3;
    split2(a.x, h0, l0); split2(a.y, h1, l1);
    split2(a.z, h2, l2); split2(a.w, h3, l3);
    size_t o4 = ((size_t)n * F1 + base) / 4;
    ((uint2*)gh_hi)[o4] = make_uint2(pk(h0, h1), pk(h2, h3));
    ((uint2*)gh_lo)[o4] = make_uint2(pk(l0, l1), pk(l2, l3));
}

/* ---------------- layer-2 aggregation (fp16 reads), 4 nodes/block ---------- */
__global__ __launch_bounds__(256)
void agg2_kernel(const float* __restrict__ b2, float* __restrict__ out) {
    int t = threadIdx.x;
    int n = blockIdx.x * 4 + (t >> 6);
    if (n >= N_NODES) return;
    int c4 = (t & 63) * 4;
    int st = g_rowptr[n], en = g_rowptr[n + 1];
    float4 a = make_float4(0.f, 0.f, 0.f, 0.f);
    #pragma unroll 4
    for (int s = st; s < en; s++) {
        float w = g_alpha[s];
        uint2 u = *(const uint2*)(g_xp2h + (size_t)g_col[s] * HID + c4);
        float2 c0 = __half22float2(*(__half2*)&u.x);
        float2 c1 = __half22float2(*(__half2*)&u.y);
        a.x += w * c0.x; a.y += w * c0.y; a.z += w * c1.x; a.w += w * c1.y;
    }
    float inv = g_inv2[n];
    float4 b = *(const float4*)(b2 + c4);
    a.x = a.x * inv + b.x; a.y = a.y * inv + b.y;
    a.z = a.z * inv + b.z; a.w = a.w * inv + b.w;
    *(float4*)(out + (size_t)n * HID + c4) = a;
}

/* ---------------- launch --------------------------------------------------- */
extern "C" void kernel_launch(void* const* d_in, const int* in_sizes, int n_in,
                              void* d_out, int out_size) {
    const float* x   = (const float*)d_in[0];
    const void*  ei  = d_in[1];
    const float* W1  = (const float*)d_in[2];
    const float* as1 = (const float*)d_in[3];
    const float* ad1 = (const float*)d_in[4];
    const float* b1  = (const float*)d_in[5];
    const float* W2  = (const float*)d_in[6];
    const float* as2 = (const float*)d_in[7];
    const float* ad2 = (const float*)d_in[8];
    const float* b2  = (const float*)d_in[9];
    float* out = (float*)d_out;

    void *p_x1h, *p_x2h, *p_as1, *p_ad1, *p_as2, *p_ad2;
    void *p_xhi, *p_xlo, *p_hhi, *p_hlo;
    void *p_w1h, *p_w1l, *p_w2h, *p_w2l;
    cudaGetSymbolAddress(&p_x1h,   g_xp1h);
    cudaGetSymbolAddress(&p_x2h,   g_xp2h);
    cudaGetSymbolAddress(&p_as1,   g_asrc1);
    cudaGetSymbolAddress(&p_ad1,   g_adst1);
    cudaGetSymbolAddress(&p_as2,   g_asrc2);
    cudaGetSymbolAddress(&p_ad2,   g_adst2);
    cudaGetSymbolAddress(&p_xhi,   gx_hi);
    cudaGetSymbolAddress(&p_xlo,   gx_lo);
    cudaGetSymbolAddress(&p_hhi,   gh_hi);
    cudaGetSymbolAddress(&p_hlo,   gh_lo);
    cudaGetSymbolAddress(&p_w1h,   gw1t_hi);
    cudaGetSymbolAddress(&p_w1l,   gw1t_lo);
    cudaGetSymbolAddress(&p_w2h,   gw2t_hi);
    cudaGetSymbolAddress(&p_w2l,   gw2t_lo);

    cudaFuncSetAttribute(mma_gemm_kernel,
                         cudaFuncAttributeMaxDynamicSharedMemorySize, GSMEM);

    /* #1..#3: prerequisites of GEMM1 */
    {
        int n4 = N_NODES * IN_DIM / 4;
        conv_split_kernel<<<(n4 + 255) / 256, 256>>>(
            x, (__nv_bfloat16*)p_xhi, (__nv_bfloat16*)p_xlo, n4);
        trans_split_kernel<<<dim3(F1 / 32, KDIM / 32), dim3(32, 8)>>>(
            W1, (__nv_bfloat16*)p_w1h, (__nv_bfloat16*)p_w1l, KDIM, F1);
    }
    init_kernel<<<NBLK, 256>>>((const int*)ei);

    /* #4: GEMM1 + fused attention (ncu capture target) */
    mma_gemm_kernel<<<dim3(F1 / 128, (N_NODES + 127) / 128), 256, GSMEM>>>(
        (const __nv_bfloat16*)p_xhi, (const __nv_bfloat16*)p_xlo,
        (const __nv_bfloat16*)p_w1h, (const __nv_bfloat16*)p_w1l,
        (__half*)p_x1h, as1, ad1, (float*)p_as1, (float*)p_ad1,
        H1, N_NODES, F1);

    /* CSR build + W2 prep (independent of GEMM1) */
    trans_split_kernel<<<dim3(HID / 32, KDIM / 32), dim3(32, 8)>>>(
        W2, (__nv_bfloat16*)p_w2h, (__nv_bfloat16*)p_w2l, KDIM, HID);
    count_kernel<<<(ET + 255) / 256, 256>>>(ei);
    bsum_kernel<<<NBLK, 256>>>();
    bscan_kernel<<<1, 128>>>();
    fscan_kernel<<<NBLK, 256>>>();
    scatter_kernel<<<(ET + 255) / 256, 256>>>(ei);

    /* layer 1 edge phase */
    softmax3_kernel<<<(N_NODES * 32 + 255) / 256, 256>>>(
        (const float*)p_as1, (const float*)p_ad1);
    agg1_kernel<<<N_NODES, 192>>>(b1);

    /* layer 2 */
    mma_gemm_kernel<<<dim3(HID / 128, (N_NODES + 127) / 128), 256, GSMEM>>>(
        (const __nv_bfloat16*)p_hhi, (const __nv_bfloat16*)p_hlo,
        (const __nv_bfloat16*)p_w2h, (const __nv_bfloat16*)p_w2l,
        (__half*)p_x2h, as2, ad2, (float*)p_as2, (float*)p_ad2,
        1, N_NODES, HID);
    softmax1_kernel<<<(N_NODES * 32 + 255) / 256, 256>>>(
        (const float*)p_as2, (const float*)p_ad2);
    agg2_kernel<<<(N_NODES + 3) / 4, 256>>>(b2, out);
}

// round 8
// speedup vs baseline: 2.3575x; 1.0110x over previous
#include <cuda_runtime.h>
#include <cuda_bf16.h>
#include <cuda_fp16.h>
#include <math.h>
#include <stdint.h>

#define N_NODES 20000
#define E_EDGES 320000
#define ET      (E_EDGES + N_NODES)   /* 340000 with self loops */
#define IN_DIM  768
#define HID     256
#define H1      3
#define F1      (H1 * HID)            /* 768 */
#define KDIM    768
#define NBLK    ((N_NODES + 255) / 256)   /* 79 */
#define NPERS   296                   /* 2 CTAs x 148 SMs */

/* ---------------- scratch (device globals, no allocs allowed) ------------- */
__device__ __half g_xp1h[(size_t)N_NODES * F1];
__device__ __half g_xp2h[(size_t)N_NODES * HID];
__device__ __nv_bfloat16 gx_hi[(size_t)N_NODES * IN_DIM];
__device__ __nv_bfloat16 gx_lo[(size_t)N_NODES * IN_DIM];
__device__ __nv_bfloat16 gh_hi[(size_t)N_NODES * F1];
__device__ __nv_bfloat16 gh_lo[(size_t)N_NODES * F1];
__device__ __nv_bfloat16 gw1t_hi[F1 * KDIM];     /* [n][k] */
__device__ __nv_bfloat16 gw1t_lo[F1 * KDIM];
__device__ __nv_bfloat16 gw2t_hi[HID * KDIM];
__device__ __nv_bfloat16 gw2t_lo[HID * KDIM];
__device__ float g_asrc1[N_NODES * H1];
__device__ float g_adst1[N_NODES * H1];
__device__ float g_asrc2[N_NODES];
__device__ float g_adst2[N_NODES];
__device__ float g_inv1[N_NODES * H1];
__device__ float g_inv2[N_NODES];
__device__ int   g_deg[N_NODES];
__device__ int   g_rowptr[N_NODES + 1];
__device__ int   g_cursor[N_NODES];
__device__ int   g_col[ET];
__device__ float g_alpha[(size_t)ET * H1];
__device__ int   g_bsum[128];
__device__ int   g_boff[128];
__device__ int   g_is64;

/* ---------------- helpers ------------------------------------------------- */
__device__ __forceinline__ float warpSum(float v) {
    #pragma unroll
    for (int o = 16; o; o >>= 1) v += __shfl_xor_sync(0xffffffffu, v, o);
    return v;
}
__device__ __forceinline__ float warpMax(float v) {
    #pragma unroll
    for (int o = 16; o; o >>= 1) v = fmaxf(v, __shfl_xor_sync(0xffffffffu, v, o));
    return v;
}
__device__ __forceinline__ uint32_t smem_u32(const void* p) {
    uint32_t a;
    asm("{ .reg .u64 t; cvta.to.shared.u64 t, %1; cvt.u32.u64 %0, t; }"
        : "=r"(a) : "l"(p));
    return a;
}
__device__ __forceinline__ uint32_t pk(__nv_bfloat16 a, __nv_bfloat16 b) {
    uint16_t ua = *(uint16_t*)&a, ub = *(uint16_t*)&b;
    return (uint32_t)ua | ((uint32_t)ub << 16);
}
__device__ __forceinline__ void split2(float v, __nv_bfloat16& h, __nv_bfloat16& l) {
    h = __float2bfloat16(v);
    l = __float2bfloat16(v - __bfloat162float(h));
}

/* ---------------- mma.sync / ldmatrix / cp.async wrappers ----------------- */
__device__ __forceinline__ void ldsm_x4(uint32_t* r, uint32_t addr) {
    asm volatile("ldmatrix.sync.aligned.m8n8.x4.shared.b16 {%0,%1,%2,%3}, [%4];"
        : "=r"(r[0]), "=r"(r[1]), "=r"(r[2]), "=r"(r[3]) : "r"(addr));
}
__device__ __forceinline__ void ldsm_x2(uint32_t* r, uint32_t addr) {
    asm volatile("ldmatrix.sync.aligned.m8n8.x2.shared.b16 {%0,%1}, [%2];"
        : "=r"(r[0]), "=r"(r[1]) : "r"(addr));
}
__device__ __forceinline__ void mma_bf16(float* c, const uint32_t* a, const uint32_t* b) {
    asm volatile(
        "mma.sync.aligned.m16n8k16.row.col.f32.bf16.bf16.f32 "
        "{%0,%1,%2,%3}, {%4,%5,%6,%7}, {%8,%9}, {%0,%1,%2,%3};"
        : "+f"(c[0]), "+f"(c[1]), "+f"(c[2]), "+f"(c[3])
        : "r"(a[0]), "r"(a[1]), "r"(a[2]), "r"(a[3]), "r"(b[0]), "r"(b[1]));
}
__device__ __forceinline__ void cp16(uint32_t dst, const void* src, int sz) {
    asm volatile("cp.async.cg.shared.global [%0], [%1], 16, %2;"
        :: "r"(dst), "l"(src), "r"(sz) : "memory");
}
__device__ __forceinline__ void cp_commit() {
    asm volatile("cp.async.commit_group;" ::: "memory");
}
template <int W> __device__ __forceinline__ void cp_wait() {
    asm volatile("cp.async.wait_group %0;" :: "n"(W) : "memory");
}

/* ======================================================================== */
/*  Persistent HMMA GEMM: Ch[M,N](fp16) = A[M,768] @ Bt[N,768]^T            */
/*  bf16x3 split, cp.async 2-stage, fused attention epilogue                 */
/* ======================================================================== */
#define LDA 40
#define ARR_B (128 * LDA * 2)     /* 10240 B per array */
#define STG_B (4 * ARR_B)         /* 40960 B per stage */
#define GSMEM (2 * STG_B)         /* 81920 B */
#define NCHUNK (KDIM / 32)        /* 24 */

__global__ __launch_bounds__(256, 2)
void mma_gemm_kernel(const __nv_bfloat16* __restrict__ Ahi,
                     const __nv_bfloat16* __restrict__ Alo,
                     const __nv_bfloat16* __restrict__ Bhi,
                     const __nv_bfloat16* __restrict__ Blo,
                     __half* __restrict__ Ch,
                     const float* __restrict__ att_s,
                     const float* __restrict__ att_d,
                     float* __restrict__ asrc,
                     float* __restrict__ adst,
                     int H, int M, int N, int nTilesX, int nTiles) {
    extern __shared__ char smem[];
    const int t = threadIdx.x, lane = t & 31, wid = t >> 5;
    const int wm = wid >> 2, wn = wid & 3;
    const uint32_t sb = smem_u32(smem);

    const int r0 = (2 * t) >> 2,     s0 = ((2 * t) & 3) * 8;
    const int r1 = (2 * t + 1) >> 2, s1 = ((2 * t + 1) & 3) * 8;
    const uint32_t d0 = (uint32_t)(r0 * LDA + s0) * 2;
    const uint32_t d1 = (uint32_t)(r1 * LDA + s1) * 2;
    const int g = lane >> 2, tq = lane & 3;

    for (int tile = blockIdx.x; tile < nTiles; tile += gridDim.x) {
        const int rowBase = (tile / nTilesX) * 128;
        const int colBase = (tile % nTilesX) * 128;

        const int av0 = (rowBase + r0) < M ? 16 : 0;
        const int av1 = (rowBase + r1) < M ? 16 : 0;
        const __nv_bfloat16* pAhi0 = Ahi + (size_t)(rowBase + r0) * KDIM + s0;
        const __nv_bfloat16* pAhi1 = Ahi + (size_t)(rowBase + r1) * KDIM + s1;
        const __nv_bfloat16* pAlo0 = Alo + (size_t)(rowBase + r0) * KDIM + s0;
        const __nv_bfloat16* pAlo1 = Alo + (size_t)(rowBase + r1) * KDIM + s1;
        const __nv_bfloat16* pBhi0 = Bhi + (size_t)(colBase + r0) * KDIM + s0;
        const __nv_bfloat16* pBhi1 = Bhi + (size_t)(colBase + r1) * KDIM + s1;
        const __nv_bfloat16* pBlo0 = Blo + (size_t)(colBase + r0) * KDIM + s0;
        const __nv_bfloat16* pBlo1 = Blo + (size_t)(colBase + r1) * KDIM + s1;

        float acc[4][4][4];
        #pragma unroll
        for (int i = 0; i < 4; i++)
            #pragma unroll
            for (int j = 0; j < 4; j++)
                #pragma unroll
                for (int q = 0; q < 4; q++) acc[i][j][q] = 0.f;

        /* prologue: stage 0 <- chunk 0 */
        {
            const uint32_t b = sb;
            cp16(b + d0, pAhi0, av0);               cp16(b + d1, pAhi1, av1);
            cp16(b + ARR_B + d0, pAlo0, av0);       cp16(b + ARR_B + d1, pAlo1, av1);
            cp16(b + 2 * ARR_B + d0, pBhi0, 16);    cp16(b + 2 * ARR_B + d1, pBhi1, 16);
            cp16(b + 3 * ARR_B + d0, pBlo0, 16);    cp16(b + 3 * ARR_B + d1, pBlo1, 16);
            cp_commit();
        }

        for (int c = 0; c < NCHUNK; c++) {
            const int st = c & 1;
            if (c + 1 < NCHUNK) {
                const int k0 = (c + 1) * 32;
                const uint32_t b = sb + ((c + 1) & 1) * STG_B;
                cp16(b + d0, pAhi0 + k0, av0);               cp16(b + d1, pAhi1 + k0, av1);
                cp16(b + ARR_B + d0, pAlo0 + k0, av0);       cp16(b + ARR_B + d1, pAlo1 + k0, av1);
                cp16(b + 2 * ARR_B + d0, pBhi0 + k0, 16);    cp16(b + 2 * ARR_B + d1, pBhi1 + k0, 16);
                cp16(b + 3 * ARR_B + d0, pBlo0 + k0, 16);    cp16(b + 3 * ARR_B + d1, pBlo1 + k0, 16);
                cp_commit();
                cp_wait<1>();
            } else {
                cp_wait<0>();
            }
            __syncthreads();

            const uint32_t sAhi = sb + st * STG_B;
            const uint32_t sAlo = sAhi + ARR_B;
            const uint32_t sBhi = sAhi + 2 * ARR_B;
            const uint32_t sBlo = sAhi + 3 * ARR_B;

            #pragma unroll
            for (int ks = 0; ks < 2; ks++) {
                const int kk = ks * 16;
                uint32_t ah[4][4], al[4][4];
                {
                    const int r  = wm * 64 + (lane & 15);
                    const int kc = kk + ((lane >> 4) << 3);
                    #pragma unroll
                    for (int mt = 0; mt < 4; mt++) {
                        uint32_t off = (uint32_t)((r + mt * 16) * LDA + kc) * 2;
                        ldsm_x4(ah[mt], sAhi + off);
                        ldsm_x4(al[mt], sAlo + off);
                    }
                }
                {
                    const int nr = wn * 32 + (lane & 7);
                    const int kc = kk + (((lane >> 3) & 1) << 3);
                    #pragma unroll
                    for (int nt = 0; nt < 4; nt++) {
                        uint32_t bh[2], bl[2];
                        uint32_t off = (uint32_t)((nr + nt * 8) * LDA + kc) * 2;
                        ldsm_x2(bh, sBhi + off);
                        ldsm_x2(bl, sBlo + off);
                        #pragma unroll
                        for (int mt = 0; mt < 4; mt++) {
                            mma_bf16(acc[mt][nt], ah[mt], bh);
                            mma_bf16(acc[mt][nt], ah[mt], bl);
                            mma_bf16(acc[mt][nt], al[mt], bh);
                        }
                    }
                }
            }
            __syncthreads();
        }

        /* ---- epilogue: fp16 store + fused attention dot products --------- */
        const int h = (H > 1) ? (colBase >> 8) : 0;

        float s_c[8], d_c[8];
        #pragma unroll
        for (int nt = 0; nt < 4; nt++) {
            int colg = colBase + wn * 32 + nt * 8 + 2 * tq;
            s_c[2 * nt]     = att_s[colg];
            s_c[2 * nt + 1] = att_s[colg + 1];
            d_c[2 * nt]     = att_d[colg];
            d_c[2 * nt + 1] = att_d[colg + 1];
        }

        #pragma unroll
        for (int mt = 0; mt < 4; mt++) {
            int r0g = rowBase + wm * 64 + mt * 16 + g;
            float ps0 = 0.f, pd0 = 0.f, ps1 = 0.f, pd1 = 0.f;
            #pragma unroll
            for (int nt = 0; nt < 4; nt++) {
                int col = colBase + wn * 32 + nt * 8 + 2 * tq;
                if (r0g < M)
                    *(__half2*)&Ch[(size_t)r0g * N + col] =
                        __floats2half2_rn(acc[mt][nt][0], acc[mt][nt][1]);
                if (r0g + 8 < M)
                    *(__half2*)&Ch[(size_t)(r0g + 8) * N + col] =
                        __floats2half2_rn(acc[mt][nt][2], acc[mt][nt][3]);
                ps0 += acc[mt][nt][0] * s_c[2 * nt] + acc[mt][nt][1] * s_c[2 * nt + 1];
                pd0 += acc[mt][nt][0] * d_c[2 * nt] + acc[mt][nt][1] * d_c[2 * nt + 1];
                ps1 += acc[mt][nt][2] * s_c[2 * nt] + acc[mt][nt][3] * s_c[2 * nt + 1];
                pd1 += acc[mt][nt][2] * d_c[2 * nt] + acc[mt][nt][3] * d_c[2 * nt + 1];
            }
            #pragma unroll
            for (int o = 1; o <= 2; o <<= 1) {
                ps0 += __shfl_xor_sync(0xffffffffu, ps0, o);
                pd0 += __shfl_xor_sync(0xffffffffu, pd0, o);
                ps1 += __shfl_xor_sync(0xffffffffu, ps1, o);
                pd1 += __shfl_xor_sync(0xffffffffu, pd1, o);
            }
            if (tq == 0) {
                if (r0g < M) {
                    atomicAdd(&asrc[r0g * H + h], ps0);
                    atomicAdd(&adst[r0g * H + h], pd0);
                }
                if (r0g + 8 < M) {
                    atomicAdd(&asrc[(r0g + 8) * H + h], ps1);
                    atomicAdd(&adst[(r0g + 8) * H + h], pd1);
                }
            }
        }
    }
}

/* ---------------- fp32 -> bf16 hi/lo elementwise split --------------------- */
__global__ void conv_split_kernel(const float* __restrict__ src,
                                  __nv_bfloat16* __restrict__ hi,
                                  __nv_bfloat16* __restrict__ lo, int n4) {
    int i = blockIdx.x * blockDim.x + threadIdx.x;
    if (i >= n4) return;
    float4 v = ((const float4*)src)[i];
    __nv_bfloat16 h0, h1, h2, h3, l0, l1, l2, l3;
    split2(v.x, h0, l0); split2(v.y, h1, l1);
    split2(v.z, h2, l2); split2(v.w, h3, l3);
    ((uint2*)hi)[i] = make_uint2(pk(h0, h1), pk(h2, h3));
    ((uint2*)lo)[i] = make_uint2(pk(l0, l1), pk(l2, l3));
}

/* ---------------- W[k][n] -> Wt[n][k] transpose + split -------------------- */
__global__ void trans_split_kernel(const float* __restrict__ W,
                                   __nv_bfloat16* __restrict__ Th,
                                   __nv_bfloat16* __restrict__ Tl,
                                   int K, int N) {
    __shared__ float tile[32][33];
    int k0 = blockIdx.y * 32, n0 = blockIdx.x * 32;
    int tx = threadIdx.x, ty = threadIdx.y;   /* 32 x 8 */
    #pragma unroll
    for (int i = 0; i < 32; i += 8)
        tile[ty + i][tx] = W[(size_t)(k0 + ty + i) * N + n0 + tx];
    __syncthreads();
    #pragma unroll
    for (int i = 0; i < 32; i += 8) {
        float v = tile[tx][ty + i];
        __nv_bfloat16 h, l;
        split2(v, h, l);
        size_t o = (size_t)(n0 + ty + i) * K + k0 + tx;
        Th[o] = h;
        Tl[o] = l;
    }
}

/* ---------------- init: zero deg + att accumulators + detect dtype --------- */
__global__ void init_kernel(const int* ei32) {
    int i = blockIdx.x * 256 + threadIdx.x;
    if (i < N_NODES) g_deg[i] = 0;
    for (int j = i; j < N_NODES * H1; j += NBLK * 256) {
        g_asrc1[j] = 0.f;
        g_adst1[j] = 0.f;
    }
    if (i < N_NODES) {
        g_asrc2[i] = 0.f;
        g_adst2[i] = 0.f;
    }
    if (blockIdx.x == 0) {
        __shared__ int any;
        if (threadIdx.x == 0) any = 0;
        __syncthreads();
        int v = 0;
        for (int j = threadIdx.x; j < 1024; j += 256)
            v |= ei32[2 * j + 1];
        if (v) atomicOr(&any, 1);
        __syncthreads();
        if (threadIdx.x == 0) g_is64 = (any == 0) ? 1 : 0;
    }
}
__device__ __forceinline__ int edge_at(const void* ei, long long idx) {
    if (g_is64) return (int)((const long long*)ei)[idx];
    return ((const int*)ei)[idx];
}

/* ---------------- CSR build ------------------------------------------------ */
__global__ void count_kernel(const void* ei) {
    int e = blockIdx.x * blockDim.x + threadIdx.x;
    if (e >= ET) return;
    int d = (e < E_EDGES) ? edge_at(ei, (long long)E_EDGES + e) : (e - E_EDGES);
    atomicAdd(&g_deg[d], 1);
}
__global__ void bsum_kernel() {
    __shared__ int s[256];
    int i = blockIdx.x * 256 + threadIdx.x;
    s[threadIdx.x] = (i < N_NODES) ? g_deg[i] : 0;
    __syncthreads();
    for (int o = 128; o; o >>= 1) {
        if (threadIdx.x < o) s[threadIdx.x] += s[threadIdx.x + o];
        __syncthreads();
    }
    if (threadIdx.x == 0) g_bsum[blockIdx.x] = s[0];
}
__global__ void bscan_kernel() {
    __shared__ int s[128];
    int t = threadIdx.x;
    int v = (t < NBLK) ? g_bsum[t] : 0;
    s[t] = v;
    __syncthreads();
    for (int o = 1; o < 128; o <<= 1) {
        int u = (t >= o) ? s[t - o] : 0;
        __syncthreads();
        s[t] += u;
        __syncthreads();
    }
    g_boff[t] = s[t] - v;
    if (t == 0) g_rowptr[N_NODES] = ET;
}
__global__ void fscan_kernel() {
    __shared__ int s[256];
    int t = threadIdx.x;
    int i = blockIdx.x * 256 + t;
    int d = (i < N_NODES) ? g_deg[i] : 0;
    s[t] = d;
    __syncthreads();
    for (int o = 1; o < 256; o <<= 1) {
        int u = (t >= o) ? s[t - o] : 0;
        __syncthreads();
        s[t] += u;
        __syncthreads();
    }
    if (i < N_NODES) {
        int off = s[t] - d + g_boff[blockIdx.x];
        g_rowptr[i] = off;
        g_cursor[i] = off;
    }
}
__global__ void scatter_kernel(const void* ei) {
    int e = blockIdx.x * blockDim.x + threadIdx.x;
    if (e >= ET) return;
    int s, d;
    if (e < E_EDGES) {
        s = edge_at(ei, e);
        d = edge_at(ei, (long long)E_EDGES + e);
    } else {
        s = d = e - E_EDGES;
    }
    int slot = atomicAdd(&g_cursor[d], 1);
    g_col[slot] = s;
}

/* ---------------- segment softmax, 3 heads fused (warp per node) ----------- */
__global__ void softmax3_kernel(const float* __restrict__ asrc,
                                const float* __restrict__ adst) {
    int n    = (blockIdx.x * blockDim.x + threadIdx.x) >> 5;
    int lane = threadIdx.x & 31;
    if (n >= N_NODES) return;
    int st = g_rowptr[n], en = g_rowptr[n + 1];
    float ad0 = adst[n * 3 + 0], ad1 = adst[n * 3 + 1], ad2 = adst[n * 3 + 2];
    float m0 = -1e30f, m1 = -1e30f, m2 = -1e30f;
    for (int s = st + lane; s < en; s += 32) {
        int col = g_col[s];
        float v0 = asrc[col * 3 + 0] + ad0;
        float v1 = asrc[col * 3 + 1] + ad1;
        float v2 = asrc[col * 3 + 2] + ad2;
        v0 = (v0 > 0.f) ? v0 : 0.2f * v0;
        v1 = (v1 > 0.f) ? v1 : 0.2f * v1;
        v2 = (v2 > 0.f) ? v2 : 0.2f * v2;
        g_alpha[(size_t)s * 3 + 0] = v0;
        g_alpha[(size_t)s * 3 + 1] = v1;
        g_alpha[(size_t)s * 3 + 2] = v2;
        m0 = fmaxf(m0, v0); m1 = fmaxf(m1, v1); m2 = fmaxf(m2, v2);
    }
    m0 = warpMax(m0); m1 = warpMax(m1); m2 = warpMax(m2);
    float s0 = 0.f, s1 = 0.f, s2 = 0.f;
    for (int s = st + lane; s < en; s += 32) {
        float e0 = __expf(g_alpha[(size_t)s * 3 + 0] - m0);
        float e1 = __expf(g_alpha[(size_t)s * 3 + 1] - m1);
        float e2 = __expf(g_alpha[(size_t)s * 3 + 2] - m2);
        g_alpha[(size_t)s * 3 + 0] = e0;
        g_alpha[(size_t)s * 3 + 1] = e1;
        g_alpha[(size_t)s * 3 + 2] = e2;
        s0 += e0; s1 += e1; s2 += e2;
    }
    s0 = warpSum(s0); s1 = warpSum(s1); s2 = warpSum(s2);
    if (lane == 0) {
        g_inv1[n * 3 + 0] = 1.f / s0;
        g_inv1[n * 3 + 1] = 1.f / s1;
        g_inv1[n * 3 + 2] = 1.f / s2;
    }
}

/* single-head version for layer 2 */
__global__ void softmax1_kernel(const float* __restrict__ asrc,
                                const float* __restrict__ adst) {
    int n    = (blockIdx.x * blockDim.x + threadIdx.x) >> 5;
    int lane = threadIdx.x & 31;
    if (n >= N_NODES) return;
    int st = g_rowptr[n], en = g_rowptr[n + 1];
    float ad = adst[n];
    float mx = -1e30f;
    for (int s = st + lane; s < en; s += 32) {
        float v = asrc[g_col[s]] + ad;
        v = (v > 0.f) ? v : 0.2f * v;
        g_alpha[s] = v;
        mx = fmaxf(mx, v);
    }
    mx = warpMax(mx);
    float sum = 0.f;
    for (int s = st + lane; s < en; s += 32) {
        float e = __expf(g_alpha[s] - mx);
        g_alpha[s] = e;
        sum += e;
    }
    sum = warpSum(sum);
    if (lane == 0) g_inv2[n] = 1.f / sum;
}

/* ---------------- layer-1 aggregation (fp16 reads) + bias + ELU ------------ */
__global__ __launch_bounds__(192)
void agg1_kernel(const float* __restrict__ b1) {
    int n = blockIdx.x;
    int t = threadIdx.x;
    int head = t >> 6;
    int base = head * 256 + (t & 63) * 4;
    int st = g_rowptr[n], en = g_rowptr[n + 1];
    float4 a = make_float4(0.f, 0.f, 0.f, 0.f);
    #pragma unroll 4
    for (int s = st; s < en; s++) {
        float w = g_alpha[(size_t)s * 3 + head];
        uint2 u = *(const uint2*)(g_xp1h + (size_t)g_col[s] * F1 + base);
        float2 c0 = __half22float2(*(__half2*)&u.x);
        float2 c1 = __half22float2(*(__half2*)&u.y);
        a.x += w * c0.x; a.y += w * c0.y; a.z += w * c1.x; a.w += w * c1.y;
    }
    float inv = g_inv1[n * 3 + head];
    float4 b = *(const float4*)(b1 + base);
    a.x = a.x * inv + b.x; a.y = a.y * inv + b.y;
    a.z = a.z * inv + b.z; a.w = a.w * inv + b.w;
    a.x = (a.x > 0.f) ? a.x : expm1f(a.x);
    a.y = (a.y > 0.f) ? a.y : expm1f(a.y);
    a.z = (a.z > 0.f) ? a.z : expm1f(a.z);
    a.w = (a.w > 0.f) ? a.w : expm1f(a.w);
    __nv_bfloat16 h0, h1, h2, h3, l0, l1, l2, l3;
    split2(a.x, h0, l0); split2(a.y, h1, l1);
    split2(a.z, h2, l2); split2(a.w, h3, l3);
    size_t o4 = ((size_t)n * F1 + base) / 4;
    ((uint2*)gh_hi)[o4] = make_uint2(pk(h0, h1), pk(h2, h3));
    ((uint2*)gh_lo)[o4] = make_uint2(pk(l0, l1), pk(l2, l3));
}

/* ---------------- layer-2 aggregation (fp16 reads), 4 nodes/block ---------- */
__global__ __launch_bounds__(256)
void agg2_kernel(const float* __restrict__ b2, float* __restrict__ out) {
    int t = threadIdx.x;
    int n = blockIdx.x * 4 + (t >> 6);
    if (n >= N_NODES) return;
    int c4 = (t & 63) * 4;
    int st = g_rowptr[n], en = g_rowptr[n + 1];
    float4 a = make_float4(0.f, 0.f, 0.f, 0.f);
    #pragma unroll 4
    for (int s = st; s < en; s++) {
        float w = g_alpha[s];
        uint2 u = *(const uint2*)(g_xp2h + (size_t)g_col[s] * HID + c4);
        float2 c0 = __half22float2(*(__half2*)&u.x);
        float2 c1 = __half22float2(*(__half2*)&u.y);
        a.x += w * c0.x; a.y += w * c0.y; a.z += w * c1.x; a.w += w * c1.y;
    }
    float inv = g_inv2[n];
    float4 b = *(const float4*)(b2 + c4);
    a.x = a.x * inv + b.x; a.y = a.y * inv + b.y;
    a.z = a.z * inv + b.z; a.w = a.w * inv + b.w;
    *(float4*)(out + (size_t)n * HID + c4) = a;
}

/* ---------------- launch --------------------------------------------------- */
extern "C" void kernel_launch(void* const* d_in, const int* in_sizes, int n_in,
                              void* d_out, int out_size) {
    const float* x   = (const float*)d_in[0];
    const void*  ei  = d_in[1];
    const float* W1  = (const float*)d_in[2];
    const float* as1 = (const float*)d_in[3];
    const float* ad1 = (const float*)d_in[4];
    const float* b1  = (const float*)d_in[5];
    const float* W2  = (const float*)d_in[6];
    const float* as2 = (const float*)d_in[7];
    const float* ad2 = (const float*)d_in[8];
    const float* b2  = (const float*)d_in[9];
    float* out = (float*)d_out;

    void *p_x1h, *p_x2h, *p_as1, *p_ad1, *p_as2, *p_ad2;
    void *p_xhi, *p_xlo, *p_hhi, *p_hlo;
    void *p_w1h, *p_w1l, *p_w2h, *p_w2l;
    cudaGetSymbolAddress(&p_x1h,   g_xp1h);
    cudaGetSymbolAddress(&p_x2h,   g_xp2h);
    cudaGetSymbolAddress(&p_as1,   g_asrc1);
    cudaGetSymbolAddress(&p_ad1,   g_adst1);
    cudaGetSymbolAddress(&p_as2,   g_asrc2);
    cudaGetSymbolAddress(&p_ad2,   g_adst2);
    cudaGetSymbolAddress(&p_xhi,   gx_hi);
    cudaGetSymbolAddress(&p_xlo,   gx_lo);
    cudaGetSymbolAddress(&p_hhi,   gh_hi);
    cudaGetSymbolAddress(&p_hlo,   gh_lo);
    cudaGetSymbolAddress(&p_w1h,   gw1t_hi);
    cudaGetSymbolAddress(&p_w1l,   gw1t_lo);
    cudaGetSymbolAddress(&p_w2h,   gw2t_hi);
    cudaGetSymbolAddress(&p_w2l,   gw2t_lo);

    cudaFuncSetAttribute(mma_gemm_kernel,
                         cudaFuncAttributeMaxDynamicSharedMemorySize, GSMEM);

    /* #1..#3: prerequisites of GEMM1 */
    {
        int n4 = N_NODES * IN_DIM / 4;
        conv_split_kernel<<<(n4 + 255) / 256, 256>>>(
            x, (__nv_bfloat16*)p_xhi, (__nv_bfloat16*)p_xlo, n4);
        trans_split_kernel<<<dim3(F1 / 32, KDIM / 32), dim3(32, 8)>>>(
            W1, (__nv_bfloat16*)p_w1h, (__nv_bfloat16*)p_w1l, KDIM, F1);
    }
    init_kernel<<<NBLK, 256>>>((const int*)ei);

    /* #4: GEMM1 + fused attention, persistent (ncu capture target) */
    {
        int nTilesX = F1 / 128;                       /* 6 */
        int nTilesY = (N_NODES + 127) / 128;          /* 157 */
        int nTiles  = nTilesX * nTilesY;              /* 942 */
        int grid = nTiles < NPERS ? nTiles : NPERS;
        mma_gemm_kernel<<<grid, 256, GSMEM>>>(
            (const __nv_bfloat16*)p_xhi, (const __nv_bfloat16*)p_xlo,
            (const __nv_bfloat16*)p_w1h, (const __nv_bfloat16*)p_w1l,
            (__half*)p_x1h, as1, ad1, (float*)p_as1, (float*)p_ad1,
            H1, N_NODES, F1, nTilesX, nTiles);
    }

    /* CSR build + W2 prep (independent of GEMM1) */
    trans_split_kernel<<<dim3(HID / 32, KDIM / 32), dim3(32, 8)>>>(
        W2, (__nv_bfloat16*)p_w2h, (__nv_bfloat16*)p_w2l, KDIM, HID);
    count_kernel<<<(ET + 255) / 256, 256>>>(ei);
    bsum_kernel<<<NBLK, 256>>>();
    bscan_kernel<<<1, 128>>>();
    fscan_kernel<<<NBLK, 256>>>();
    scatter_kernel<<<(ET + 255) / 256, 256>>>(ei);

    /* layer 1 edge phase */
    softmax3_kernel<<<(N_NODES * 32 + 255) / 256, 256>>>(
        (const float*)p_as1, (const float*)p_ad1);
    agg1_kernel<<<N_NODES, 192>>>(b1);

    /* layer 2 */
    {
        int nTilesX = HID / 128;                      /* 2 */
        int nTilesY = (N_NODES + 127) / 128;          /* 157 */
        int nTiles  = nTilesX * nTilesY;              /* 314 */
        int grid = nTiles < NPERS ? nTiles : NPERS;
        mma_gemm_kernel<<<grid, 256, GSMEM>>>(
            (const __nv_bfloat16*)p_hhi, (const __nv_bfloat16*)p_hlo,
            (const __nv_bfloat16*)p_w2h, (const __nv_bfloat16*)p_w2l,
            (__half*)p_x2h, as2, ad2, (float*)p_as2, (float*)p_ad2,
            1, N_NODES, HID, nTilesX, nTiles);
    }
    softmax1_kernel<<<(N_NODES * 32 + 255) / 256, 256>>>(
        (const float*)p_as2, (const float*)p_ad2);
    agg2_kernel<<<(N_NODES + 3) / 4, 256>>>(b2, out);
}

// round 9
// speedup vs baseline: 3.7567x; 1.5935x over previous
#include <cuda_runtime.h>
#include <cuda_fp16.h>
#include <math.h>
#include <stdint.h>

#define N_NODES 20000
#define E_EDGES 320000
#define ET      (E_EDGES + N_NODES)   /* 340000 with self loops */
#define IN_DIM  768
#define HID     256
#define H1      3
#define F1      (H1 * HID)            /* 768 */
#define KDIM    768
#define NBLK    ((N_NODES + 255) / 256)   /* 79 */
#define NPERS   296                   /* 2 CTAs x 148 SMs */

/* ---------------- scratch (device globals, no allocs allowed) ------------- */
__device__ __half g_xp1h[(size_t)N_NODES * F1];    /* GEMM1 out (fp16)   */
__device__ __half g_xp2h[(size_t)N_NODES * HID];   /* GEMM2 out (fp16)   */
__device__ __half gx_h [(size_t)N_NODES * IN_DIM]; /* x in fp16          */
__device__ __half g_hh [(size_t)N_NODES * F1];     /* h in fp16          */
__device__ __half gw1t_h[F1 * KDIM];               /* W1^T [n][k] fp16   */
__device__ __half gw2t_h[HID * KDIM];
__device__ float g_asrc1[N_NODES * H1];
__device__ float g_adst1[N_NODES * H1];
__device__ float g_asrc2[N_NODES];
__device__ float g_adst2[N_NODES];
__device__ float g_inv1[N_NODES * H1];
__device__ float g_inv2[N_NODES];
__device__ int   g_deg[N_NODES];
__device__ int   g_rowptr[N_NODES + 1];
__device__ int   g_cursor[N_NODES];
__device__ int   g_col[ET];
__device__ float g_alpha[(size_t)ET * H1];
__device__ int   g_bsum[128];
__device__ int   g_boff[128];
__device__ int   g_is64;

/* ---------------- helpers ------------------------------------------------- */
__device__ __forceinline__ float warpSum(float v) {
    #pragma unroll
    for (int o = 16; o; o >>= 1) v += __shfl_xor_sync(0xffffffffu, v, o);
    return v;
}
__device__ __forceinline__ float warpMax(float v) {
    #pragma unroll
    for (int o = 16; o; o >>= 1) v = fmaxf(v, __shfl_xor_sync(0xffffffffu, v, o));
    return v;
}
__device__ __forceinline__ uint32_t smem_u32(const void* p) {
    uint32_t a;
    asm("{ .reg .u64 t; cvta.to.shared.u64 t, %1; cvt.u32.u64 %0, t; }"
        : "=r"(a) : "l"(p));
    return a;
}

/* ---------------- mma.sync / ldmatrix / cp.async wrappers ----------------- */
__device__ __forceinline__ void ldsm_x4(uint32_t* r, uint32_t addr) {
    asm volatile("ldmatrix.sync.aligned.m8n8.x4.shared.b16 {%0,%1,%2,%3}, [%4];"
        : "=r"(r[0]), "=r"(r[1]), "=r"(r[2]), "=r"(r[3]) : "r"(addr));
}
__device__ __forceinline__ void ldsm_x2(uint32_t* r, uint32_t addr) {
    asm volatile("ldmatrix.sync.aligned.m8n8.x2.shared.b16 {%0,%1}, [%2];"
        : "=r"(r[0]), "=r"(r[1]) : "r"(addr));
}
__device__ __forceinline__ void mma_f16(float* c, const uint32_t* a, const uint32_t* b) {
    asm volatile(
        "mma.sync.aligned.m16n8k16.row.col.f32.f16.f16.f32 "
        "{%0,%1,%2,%3}, {%4,%5,%6,%7}, {%8,%9}, {%0,%1,%2,%3};"
        : "+f"(c[0]), "+f"(c[1]), "+f"(c[2]), "+f"(c[3])
        : "r"(a[0]), "r"(a[1]), "r"(a[2]), "r"(a[3]), "r"(b[0]), "r"(b[1]));
}
__device__ __forceinline__ void cp16(uint32_t dst, const void* src, int sz) {
    asm volatile("cp.async.cg.shared.global [%0], [%1], 16, %2;"
        :: "r"(dst), "l"(src), "r"(sz) : "memory");
}
__device__ __forceinline__ void cp_commit() {
    asm volatile("cp.async.commit_group;" ::: "memory");
}
template <int W> __device__ __forceinline__ void cp_wait() {
    asm volatile("cp.async.wait_group %0;" :: "n"(W) : "memory");
}

/* ======================================================================== */
/*  Persistent HMMA GEMM (fp16 single-pass):                                 */
/*  Ch[M,N](fp16) = A[M,768] @ Bt[N,768]^T, 4-stage cp.async, 1 bar/chunk   */
/*  Fused attention dot-product epilogue (atomics)                           */
/* ======================================================================== */
#define LDA 40
#define ARR_B (128 * LDA * 2)     /* 10240 B per array */
#define STG_B (2 * ARR_B)         /* 20480 B per stage (A + B) */
#define NSTG  4
#define GSMEM (NSTG * STG_B)      /* 81920 B */
#define NCHUNK (KDIM / 32)        /* 24 */

__global__ __launch_bounds__(256, 2)
void mma_gemm_kernel(const __half* __restrict__ Ah,
                     const __half* __restrict__ Bh,
                     __half* __restrict__ Ch,
                     const float* __restrict__ att_s,
                     const float* __restrict__ att_d,
                     float* __restrict__ asrc,
                     float* __restrict__ adst,
                     int H, int M, int N, int nTilesX, int nTiles) {
    extern __shared__ char smem[];
    const int t = threadIdx.x, lane = t & 31, wid = t >> 5;
    const int wm = wid >> 2, wn = wid & 3;
    const uint32_t sb = smem_u32(smem);

    const int r0 = (2 * t) >> 2,     s0 = ((2 * t) & 3) * 8;
    const int r1 = (2 * t + 1) >> 2, s1 = ((2 * t + 1) & 3) * 8;
    const uint32_t d0 = (uint32_t)(r0 * LDA + s0) * 2;
    const uint32_t d1 = (uint32_t)(r1 * LDA + s1) * 2;
    const int g = lane >> 2, tq = lane & 3;

    for (int tile = blockIdx.x; tile < nTiles; tile += gridDim.x) {
        const int rowBase = (tile / nTilesX) * 128;
        const int colBase = (tile % nTilesX) * 128;

        const int av0 = (rowBase + r0) < M ? 16 : 0;
        const int av1 = (rowBase + r1) < M ? 16 : 0;
        const __half* pA0 = Ah + (size_t)(rowBase + r0) * KDIM + s0;
        const __half* pA1 = Ah + (size_t)(rowBase + r1) * KDIM + s1;
        const __half* pB0 = Bh + (size_t)(colBase + r0) * KDIM + s0;
        const __half* pB1 = Bh + (size_t)(colBase + r1) * KDIM + s1;

        float acc[4][4][4];
        #pragma unroll
        for (int i = 0; i < 4; i++)
            #pragma unroll
            for (int j = 0; j < 4; j++)
                #pragma unroll
                for (int q = 0; q < 4; q++) acc[i][j][q] = 0.f;

        /* prologue: issue chunks 0,1,2 into stages 0,1,2 */
        #pragma unroll
        for (int p = 0; p < 3; p++) {
            const uint32_t b = sb + p * STG_B;
            const int k0 = p * 32;
            cp16(b + d0, pA0 + k0, av0);           cp16(b + d1, pA1 + k0, av1);
            cp16(b + ARR_B + d0, pB0 + k0, 16);    cp16(b + ARR_B + d1, pB1 + k0, 16);
            cp_commit();
        }

        for (int c = 0; c < NCHUNK; c++) {
            /* complete chunk c (tail-aware wait depth) */
            if (c < NCHUNK - 2)       cp_wait<2>();
            else if (c == NCHUNK - 2) cp_wait<1>();
            else                      cp_wait<0>();
            __syncthreads();

            /* prefetch chunk c+3 into stage (c+3)&3 (safe: its last readers
               were iteration c-1, closed by the barrier above) */
            if (c + 3 < NCHUNK) {
                const int k0 = (c + 3) * 32;
                const uint32_t b = sb + ((c + 3) & 3) * STG_B;
                cp16(b + d0, pA0 + k0, av0);           cp16(b + d1, pA1 + k0, av1);
                cp16(b + ARR_B + d0, pB0 + k0, 16);    cp16(b + ARR_B + d1, pB1 + k0, 16);
                cp_commit();
            }

            const uint32_t sA = sb + (c & 3) * STG_B;
            const uint32_t sB = sA + ARR_B;

            #pragma unroll
            for (int ks = 0; ks < 2; ks++) {
                const int kk = ks * 16;
                uint32_t ah[4][4];
                {
                    const int r  = wm * 64 + (lane & 15);
                    const int kc = kk + ((lane >> 4) << 3);
                    #pragma unroll
                    for (int mt = 0; mt < 4; mt++)
                        ldsm_x4(ah[mt], sA + (uint32_t)((r + mt * 16) * LDA + kc) * 2);
                }
                {
                    const int nr = wn * 32 + (lane & 7);
                    const int kc = kk + (((lane >> 3) & 1) << 3);
                    #pragma unroll
                    for (int nt = 0; nt < 4; nt++) {
                        uint32_t bh[2];
                        ldsm_x2(bh, sB + (uint32_t)((nr + nt * 8) * LDA + kc) * 2);
                        #pragma unroll
                        for (int mt = 0; mt < 4; mt++)
                            mma_f16(acc[mt][nt], ah[mt], bh);
                    }
                }
            }
        }

        /* ---- epilogue: fp16 store + fused attention dot products --------- */
        const int h = (H > 1) ? (colBase >> 8) : 0;

        float s_c[8], d_c[8];
        #pragma unroll
        for (int nt = 0; nt < 4; nt++) {
            int colg = colBase + wn * 32 + nt * 8 + 2 * tq;
            s_c[2 * nt]     = att_s[colg];
            s_c[2 * nt + 1] = att_s[colg + 1];
            d_c[2 * nt]     = att_d[colg];
            d_c[2 * nt + 1] = att_d[colg + 1];
        }

        #pragma unroll
        for (int mt = 0; mt < 4; mt++) {
            int r0g = rowBase + wm * 64 + mt * 16 + g;
            float ps0 = 0.f, pd0 = 0.f, ps1 = 0.f, pd1 = 0.f;
            #pragma unroll
            for (int nt = 0; nt < 4; nt++) {
                int col = colBase + wn * 32 + nt * 8 + 2 * tq;
                if (r0g < M)
                    *(__half2*)&Ch[(size_t)r0g * N + col] =
                        __floats2half2_rn(acc[mt][nt][0], acc[mt][nt][1]);
                if (r0g + 8 < M)
                    *(__half2*)&Ch[(size_t)(r0g + 8) * N + col] =
                        __floats2half2_rn(acc[mt][nt][2], acc[mt][nt][3]);
                ps0 += acc[mt][nt][0] * s_c[2 * nt] + acc[mt][nt][1] * s_c[2 * nt + 1];
                pd0 += acc[mt][nt][0] * d_c[2 * nt] + acc[mt][nt][1] * d_c[2 * nt + 1];
                ps1 += acc[mt][nt][2] * s_c[2 * nt] + acc[mt][nt][3] * s_c[2 * nt + 1];
                pd1 += acc[mt][nt][2] * d_c[2 * nt] + acc[mt][nt][3] * d_c[2 * nt + 1];
            }
            #pragma unroll
            for (int o = 1; o <= 2; o <<= 1) {
                ps0 += __shfl_xor_sync(0xffffffffu, ps0, o);
                pd0 += __shfl_xor_sync(0xffffffffu, pd0, o);
                ps1 += __shfl_xor_sync(0xffffffffu, ps1, o);
                pd1 += __shfl_xor_sync(0xffffffffu, pd1, o);
            }
            if (tq == 0) {
                if (r0g < M) {
                    atomicAdd(&asrc[r0g * H + h], ps0);
                    atomicAdd(&adst[r0g * H + h], pd0);
                }
                if (r0g + 8 < M) {
                    atomicAdd(&asrc[(r0g + 8) * H + h], ps1);
                    atomicAdd(&adst[(r0g + 8) * H + h], pd1);
                }
            }
        }
        /* next tile's prologue writes stages 0..2; their last readers in this
           tile were chunks 20..22, closed by the barrier at chunk 23 top.
           One extra barrier isolates slow warps still on chunk 23 (stage 3)
           from nothing (prologue writes 0..2) — not needed. */
    }
}

/* ---------------- fp32 -> fp16 elementwise ---------------------------------- */
__global__ void conv_half_kernel(const float* __restrict__ src,
                                 __half* __restrict__ dst, int n4) {
    int i = blockIdx.x * blockDim.x + threadIdx.x;
    if (i >= n4) return;
    float4 v = ((const float4*)src)[i];
    __half2 a = __floats2half2_rn(v.x, v.y);
    __half2 b = __floats2half2_rn(v.z, v.w);
    ((uint2*)dst)[i] = make_uint2(*(uint32_t*)&a, *(uint32_t*)&b);
}

/* ---------------- W[k][n] -> Wt[n][k] transpose -> fp16 -------------------- */
__global__ void trans_half_kernel(const float* __restrict__ W,
                                  __half* __restrict__ Th, int K, int N) {
    __shared__ float tile[32][33];
    int k0 = blockIdx.y * 32, n0 = blockIdx.x * 32;
    int tx = threadIdx.x, ty = threadIdx.y;   /* 32 x 8 */
    #pragma unroll
    for (int i = 0; i < 32; i += 8)
        tile[ty + i][tx] = W[(size_t)(k0 + ty + i) * N + n0 + tx];
    __syncthreads();
    #pragma unroll
    for (int i = 0; i < 32; i += 8) {
        float v = tile[tx][ty + i];
        Th[(size_t)(n0 + ty + i) * K + k0 + tx] = __float2half_rn(v);
    }
}

/* ---------------- init: zero deg + att accumulators + detect dtype --------- */
__global__ void init_kernel(const int* ei32) {
    int i = blockIdx.x * 256 + threadIdx.x;
    if (i < N_NODES) g_deg[i] = 0;
    for (int j = i; j < N_NODES * H1; j += NBLK * 256) {
        g_asrc1[j] = 0.f;
        g_adst1[j] = 0.f;
    }
    if (i < N_NODES) {
        g_asrc2[i] = 0.f;
        g_adst2[i] = 0.f;
    }
    if (blockIdx.x == 0) {
        __shared__ int any;
        if (threadIdx.x == 0) any = 0;
        __syncthreads();
        int v = 0;
        for (int j = threadIdx.x; j < 1024; j += 256)
            v |= ei32[2 * j + 1];
        if (v) atomicOr(&any, 1);
        __syncthreads();
        if (threadIdx.x == 0) g_is64 = (any == 0) ? 1 : 0;
    }
}
__device__ __forceinline__ int edge_at(const void* ei, long long idx) {
    if (g_is64) return (int)((const long long*)ei)[idx];
    return ((const int*)ei)[idx];
}

/* ---------------- CSR build ------------------------------------------------ */
__global__ void count_kernel(const void* ei) {
    int e = blockIdx.x * blockDim.x + threadIdx.x;
    if (e >= ET) return;
    int d = (e < E_EDGES) ? edge_at(ei, (long long)E_EDGES + e) : (e - E_EDGES);
    atomicAdd(&g_deg[d], 1);
}
__global__ void bsum_kernel() {
    __shared__ int s[256];
    int i = blockIdx.x * 256 + threadIdx.x;
    s[threadIdx.x] = (i < N_NODES) ? g_deg[i] : 0;
    __syncthreads();
    for (int o = 128; o; o >>= 1) {
        if (threadIdx.x < o) s[threadIdx.x] += s[threadIdx.x + o];
        __syncthreads();
    }
    if (threadIdx.x == 0) g_bsum[blockIdx.x] = s[0];
}
__global__ void bscan_kernel() {
    __shared__ int s[128];
    int t = threadIdx.x;
    int v = (t < NBLK) ? g_bsum[t] : 0;
    s[t] = v;
    __syncthreads();
    for (int o = 1; o < 128; o <<= 1) {
        int u = (t >= o) ? s[t - o] : 0;
        __syncthreads();
        s[t] += u;
        __syncthreads();
    }
    g_boff[t] = s[t] - v;
    if (t == 0) g_rowptr[N_NODES] = ET;
}
__global__ void fscan_kernel() {
    __shared__ int s[256];
    int t = threadIdx.x;
    int i = blockIdx.x * 256 + t;
    int d = (i < N_NODES) ? g_deg[i] : 0;
    s[t] = d;
    __syncthreads();
    for (int o = 1; o < 256; o <<= 1) {
        int u = (t >= o) ? s[t - o] : 0;
        __syncthreads();
        s[t] += u;
        __syncthreads();
    }
    if (i < N_NODES) {
        int off = s[t] - d + g_boff[blockIdx.x];
        g_rowptr[i] = off;
        g_cursor[i] = off;
    }
}
__global__ void scatter_kernel(const void* ei) {
    int e = blockIdx.x * blockDim.x + threadIdx.x;
    if (e >= ET) return;
    int s, d;
    if (e < E_EDGES) {
        s = edge_at(ei, e);
        d = edge_at(ei, (long long)E_EDGES + e);
    } else {
        s = d = e - E_EDGES;
    }
    int slot = atomicAdd(&g_cursor[d], 1);
    g_col[slot] = s;
}

/* ---------------- segment softmax, 3 heads fused (warp per node) ----------- */
__global__ void softmax3_kernel(const float* __restrict__ asrc,
                                const float* __restrict__ adst) {
    int n    = (blockIdx.x * blockDim.x + threadIdx.x) >> 5;
    int lane = threadIdx.x & 31;
    if (n >= N_NODES) return;
    int st = g_rowptr[n], en = g_rowptr[n + 1];
    float ad0 = adst[n * 3 + 0], ad1 = adst[n * 3 + 1], ad2 = adst[n * 3 + 2];
    float m0 = -1e30f, m1 = -1e30f, m2 = -1e30f;
    for (int s = st + lane; s < en; s += 32) {
        int col = g_col[s];
        float v0 = asrc[col * 3 + 0] + ad0;
        float v1 = asrc[col * 3 + 1] + ad1;
        float v2 = asrc[col * 3 + 2] + ad2;
        v0 = (v0 > 0.f) ? v0 : 0.2f * v0;
        v1 = (v1 > 0.f) ? v1 : 0.2f * v1;
        v2 = (v2 > 0.f) ? v2 : 0.2f * v2;
        g_alpha[(size_t)s * 3 + 0] = v0;
        g_alpha[(size_t)s * 3 + 1] = v1;
        g_alpha[(size_t)s * 3 + 2] = v2;
        m0 = fmaxf(m0, v0); m1 = fmaxf(m1, v1); m2 = fmaxf(m2, v2);
    }
    m0 = warpMax(m0); m1 = warpMax(m1); m2 = warpMax(m2);
    float s0 = 0.f, s1 = 0.f, s2 = 0.f;
    for (int s = st + lane; s < en; s += 32) {
        float e0 = __expf(g_alpha[(size_t)s * 3 + 0] - m0);
        float e1 = __expf(g_alpha[(size_t)s * 3 + 1] - m1);
        float e2 = __expf(g_alpha[(size_t)s * 3 + 2] - m2);
        g_alpha[(size_t)s * 3 + 0] = e0;
        g_alpha[(size_t)s * 3 + 1] = e1;
        g_alpha[(size_t)s * 3 + 2] = e2;
        s0 += e0; s1 += e1; s2 += e2;
    }
    s0 = warpSum(s0); s1 = warpSum(s1); s2 = warpSum(s2);
    if (lane == 0) {
        g_inv1[n * 3 + 0] = 1.f / s0;
        g_inv1[n * 3 + 1] = 1.f / s1;
        g_inv1[n * 3 + 2] = 1.f / s2;
    }
}

/* single-head version for layer 2 */
__global__ void softmax1_kernel(const float* __restrict__ asrc,
                                const float* __restrict__ adst) {
    int n    = (blockIdx.x * blockDim.x + threadIdx.x) >> 5;
    int lane = threadIdx.x & 31;
    if (n >= N_NODES) return;
    int st = g_rowptr[n], en = g_rowptr[n + 1];
    float ad = adst[n];
    float mx = -1e30f;
    for (int s = st + lane; s < en; s += 32) {
        float v = asrc[g_col[s]] + ad;
        v = (v > 0.f) ? v : 0.2f * v;
        g_alpha[s] = v;
        mx = fmaxf(mx, v);
    }
    mx = warpMax(mx);
    float sum = 0.f;
    for (int s = st + lane; s < en; s += 32) {
        float e = __expf(g_alpha[s] - mx);
        g_alpha[s] = e;
        sum += e;
    }
    sum = warpSum(sum);
    if (lane == 0) g_inv2[n] = 1.f / sum;
}

/* ---------------- layer-1 aggregation (fp16 reads) + bias + ELU ------------ */
__global__ __launch_bounds__(192)
void agg1_kernel(const float* __restrict__ b1) {
    int n = blockIdx.x;
    int t = threadIdx.x;
    int head = t >> 6;
    int base = head * 256 + (t & 63) * 4;
    int st = g_rowptr[n], en = g_rowptr[n + 1];
    float4 a = make_float4(0.f, 0.f, 0.f, 0.f);
    #pragma unroll 4
    for (int s = st; s < en; s++) {
        float w = g_alpha[(size_t)s * 3 + head];
        uint2 u = *(const uint2*)(g_xp1h + (size_t)g_col[s] * F1 + base);
        float2 c0 = __half22float2(*(__half2*)&u.x);
        float2 c1 = __half22float2(*(__half2*)&u.y);
        a.x += w * c0.x; a.y += w * c0.y; a.z += w * c1.x; a.w += w * c1.y;
    }
    float inv = g_inv1[n * 3 + head];
    float4 b = *(const float4*)(b1 + base);
    a.x = a.x * inv + b.x; a.y = a.y * inv + b.y;
    a.z = a.z * inv + b.z; a.w = a.w * inv + b.w;
    a.x = (a.x > 0.f) ? a.x : expm1f(a.x);
    a.y = (a.y > 0.f) ? a.y : expm1f(a.y);
    a.z = (a.z > 0.f) ? a.z : expm1f(a.z);
    a.w = (a.w > 0.f) ? a.w : expm1f(a.w);
    __half2 h0 = __floats2half2_rn(a.x, a.y);
    __half2 h1 = __floats2half2_rn(a.z, a.w);
    size_t o4 = ((size_t)n * F1 + base) / 4;
    ((uint2*)g_hh)[o4] = make_uint2(*(uint32_t*)&h0, *(uint32_t*)&h1);
}

/* ---------------- layer-2 aggregation (fp16 reads), 4 nodes/block ---------- */
__global__ __launch_bounds__(256)
void agg2_kernel(const float* __restrict__ b2, float* __restrict__ out) {
    int t = threadIdx.x;
    int n = blockIdx.x * 4 + (t >> 6);
    if (n >= N_NODES) return;
    int c4 = (t & 63) * 4;
    int st = g_rowptr[n], en = g_rowptr[n + 1];
    float4 a = make_float4(0.f, 0.f, 0.f, 0.f);
    #pragma unroll 4
    for (int s = st; s < en; s++) {
        float w = g_alpha[s];
        uint2 u = *(const uint2*)(g_xp2h + (size_t)g_col[s] * HID + c4);
        float2 c0 = __half22float2(*(__half2*)&u.x);
        float2 c1 = __half22float2(*(__half2*)&u.y);
        a.x += w * c0.x; a.y += w * c0.y; a.z += w * c1.x; a.w += w * c1.y;
    }
    float inv = g_inv2[n];
    float4 b = *(const float4*)(b2 + c4);
    a.x = a.x * inv + b.x; a.y = a.y * inv + b.y;
    a.z = a.z * inv + b.z; a.w = a.w * inv + b.w;
    *(float4*)(out + (size_t)n * HID + c4) = a;
}

/* ---------------- launch --------------------------------------------------- */
extern "C" void kernel_launch(void* const* d_in, const int* in_sizes, int n_in,
                              void* d_out, int out_size) {
    const float* x   = (const float*)d_in[0];
    const void*  ei  = d_in[1];
    const float* W1  = (const float*)d_in[2];
    const float* as1 = (const float*)d_in[3];
    const float* ad1 = (const float*)d_in[4];
    const float* b1  = (const float*)d_in[5];
    const float* W2  = (const float*)d_in[6];
    const float* as2 = (const float*)d_in[7];
    const float* ad2 = (const float*)d_in[8];
    const float* b2  = (const float*)d_in[9];
    float* out = (float*)d_out;

    void *p_x1h, *p_x2h, *p_as1, *p_ad1, *p_as2, *p_ad2;
    void *p_xh, *p_hh, *p_w1h, *p_w2h;
    cudaGetSymbolAddress(&p_x1h, g_xp1h);
    cudaGetSymbolAddress(&p_x2h, g_xp2h);
    cudaGetSymbolAddress(&p_as1, g_asrc1);
    cudaGetSymbolAddress(&p_ad1, g_adst1);
    cudaGetSymbolAddress(&p_as2, g_asrc2);
    cudaGetSymbolAddress(&p_ad2, g_adst2);
    cudaGetSymbolAddress(&p_xh,  gx_h);
    cudaGetSymbolAddress(&p_hh,  g_hh);
    cudaGetSymbolAddress(&p_w1h, gw1t_h);
    cudaGetSymbolAddress(&p_w2h, gw2t_h);

    cudaFuncSetAttribute(mma_gemm_kernel,
                         cudaFuncAttributeMaxDynamicSharedMemorySize, GSMEM);

    /* #1..#3: prerequisites of GEMM1 */
    {
        int n4 = N_NODES * IN_DIM / 4;
        conv_half_kernel<<<(n4 + 255) / 256, 256>>>(x, (__half*)p_xh, n4);
        trans_half_kernel<<<dim3(F1 / 32, KDIM / 32), dim3(32, 8)>>>(
            W1, (__half*)p_w1h, KDIM, F1);
    }
    init_kernel<<<NBLK, 256>>>((const int*)ei);

    /* #4: GEMM1 + fused attention, persistent (ncu capture target) */
    {
        int nTilesX = F1 / 128;                       /* 6 */
        int nTiles  = nTilesX * ((N_NODES + 127) / 128);   /* 942 */
        int grid = nTiles < NPERS ? nTiles : NPERS;
        mma_gemm_kernel<<<grid, 256, GSMEM>>>(
            (const __half*)p_xh, (const __half*)p_w1h,
            (__half*)p_x1h, as1, ad1, (float*)p_as1, (float*)p_ad1,
            H1, N_NODES, F1, nTilesX, nTiles);
    }

    /* CSR build + W2 prep (independent of GEMM1) */
    trans_half_kernel<<<dim3(HID / 32, KDIM / 32), dim3(32, 8)>>>(
        W2, (__half*)p_w2h, KDIM, HID);
    count_kernel<<<(ET + 255) / 256, 256>>>(ei);
    bsum_kernel<<<NBLK, 256>>>();
    bscan_kernel<<<1, 128>>>();
    fscan_kernel<<<NBLK, 256>>>();
    scatter_kernel<<<(ET + 255) / 256, 256>>>(ei);

    /* layer 1 edge phase */
    softmax3_kernel<<<(N_NODES * 32 + 255) / 256, 256>>>(
        (const float*)p_as1, (const float*)p_ad1);
    agg1_kernel<<<N_NODES, 192>>>(b1);

    /* layer 2 */
    {
        int nTilesX = HID / 128;                      /* 2 */
        int nTiles  = nTilesX * ((N_NODES + 127) / 128);   /* 314 */
        int grid = nTiles < NPERS ? nTiles : NPERS;
        mma_gemm_kernel<<<grid, 256, GSMEM>>>(
            (const __half*)p_hh, (const __half*)p_w2h,
            (__half*)p_x2h, as2, ad2, (float*)p_as2, (float*)p_ad2,
            1, N_NODES, HID, nTilesX, nTiles);
    }
    softmax1_kernel<<<(N_NODES * 32 + 255) / 256, 256>>>(
        (const float*)p_as2, (const float*)p_ad2);
    agg2_kernel<<<(N_NODES + 3) / 4, 256>>>(b2, out);
}

// round 10
// speedup vs baseline: 4.4538x; 1.1855x over previous
#include <cuda_runtime.h>
#include <cuda_fp16.h>
#include <math.h>
#include <stdint.h>

#define N_NODES 20000
#define E_EDGES 320000
#define ET      (E_EDGES + N_NODES)   /* 340000 with self loops */
#define IN_DIM  768
#define HID     256
#define H1      3
#define F1      (H1 * HID)            /* 768 */
#define KDIM    768
#define NBLK    ((N_NODES + 255) / 256)   /* 79 */
#define NPERS   296                   /* 2 CTAs x 148 SMs */

/* ---------------- scratch (device globals, no allocs allowed) ------------- */
__device__ __half g_xp1h[(size_t)N_NODES * F1];    /* GEMM1 out (fp16)   */
__device__ __half g_xp2h[(size_t)N_NODES * HID];   /* GEMM2 out (fp16)   */
__device__ __half gx_h [(size_t)N_NODES * IN_DIM]; /* x in fp16          */
__device__ __half g_hh [(size_t)N_NODES * F1];     /* h in fp16          */
__device__ __half gw1t_h[F1 * KDIM];               /* W1^T [n][k] fp16   */
__device__ __half gw2t_h[HID * KDIM];
__device__ float g_asrc1[N_NODES * H1];
__device__ float g_adst1[N_NODES * H1];
__device__ float g_asrc2[N_NODES];
__device__ float g_adst2[N_NODES];
__device__ float g_inv1[N_NODES * H1];
__device__ float g_inv2[N_NODES];
__device__ int   g_deg[N_NODES];
__device__ int   g_rowptr[N_NODES + 1];
__device__ int   g_cursor[N_NODES];
__device__ int   g_col[ET];
__device__ float g_alpha[(size_t)ET * H1];
__device__ int   g_bsum[128];
__device__ int   g_boff[128];
__device__ int   g_is64;

/* ---------------- helpers ------------------------------------------------- */
__device__ __forceinline__ float warpSum(float v) {
    #pragma unroll
    for (int o = 16; o; o >>= 1) v += __shfl_xor_sync(0xffffffffu, v, o);
    return v;
}
__device__ __forceinline__ float warpMax(float v) {
    #pragma unroll
    for (int o = 16; o; o >>= 1) v = fmaxf(v, __shfl_xor_sync(0xffffffffu, v, o));
    return v;
}
__device__ __forceinline__ uint32_t smem_u32(const void* p) {
    uint32_t a;
    asm("{ .reg .u64 t; cvta.to.shared.u64 t, %1; cvt.u32.u64 %0, t; }"
        : "=r"(a) : "l"(p));
    return a;
}

/* ---------------- mma.sync / ldmatrix / cp.async wrappers ----------------- */
__device__ __forceinline__ void ldsm_x4(uint32_t* r, uint32_t addr) {
    asm volatile("ldmatrix.sync.aligned.m8n8.x4.shared.b16 {%0,%1,%2,%3}, [%4];"
        : "=r"(r[0]), "=r"(r[1]), "=r"(r[2]), "=r"(r[3]) : "r"(addr));
}
__device__ __forceinline__ void mma_f16(float* c, const uint32_t* a, const uint32_t* b) {
    asm volatile(
        "mma.sync.aligned.m16n8k16.row.col.f32.f16.f16.f32 "
        "{%0,%1,%2,%3}, {%4,%5,%6,%7}, {%8,%9}, {%0,%1,%2,%3};"
        : "+f"(c[0]), "+f"(c[1]), "+f"(c[2]), "+f"(c[3])
        : "r"(a[0]), "r"(a[1]), "r"(a[2]), "r"(a[3]), "r"(b[0]), "r"(b[1]));
}
__device__ __forceinline__ void cp16(uint32_t dst, const void* src, int sz) {
    asm volatile("cp.async.cg.shared.global [%0], [%1], 16, %2;"
        :: "r"(dst), "l"(src), "r"(sz) : "memory");
}
__device__ __forceinline__ void cp_commit() {
    asm volatile("cp.async.commit_group;" ::: "memory");
}
template <int W> __device__ __forceinline__ void cp_wait() {
    asm volatile("cp.async.wait_group %0;" :: "n"(W) : "memory");
}

/* ======================================================================== */
/*  Persistent HMMA GEMM (fp16): Ch[M,N] = A[M,768] @ Bt[N,768]^T            */
/*  BK=64 chunks, 3-stage cp.async, 1 barrier/chunk, full-rate ldsm_x4       */
/*  Fused attention dot-product epilogue (atomics)                           */
/* ======================================================================== */
#define BK    64
#define LDA   72                   /* 144 B rows: bank stride 4 mod 32 */
#define TILE_AB (128 * LDA * 2)    /* 18432 B per tile array */
#define STG_B  (2 * TILE_AB)       /* 36864 B per stage (A + B) */
#define NSTG   3
#define GSMEM  (NSTG * STG_B)      /* 110592 B */
#define NCHUNK (KDIM / BK)         /* 12 */

__global__ __launch_bounds__(256, 2)
void mma_gemm_kernel(const __half* __restrict__ Ah,
                     const __half* __restrict__ Bh,
                     __half* __restrict__ Ch,
                     const float* __restrict__ att_s,
                     const float* __restrict__ att_d,
                     float* __restrict__ asrc,
                     float* __restrict__ adst,
                     int H, int M, int N, int nTilesX, int nTiles) {
    extern __shared__ char smem[];
    const int t = threadIdx.x, lane = t & 31, wid = t >> 5;
    const int wm = wid >> 2, wn = wid & 3;
    const uint32_t sb = smem_u32(smem);

    /* loader mapping: thread owns rows rbase+32i (i=0..3), 16B at col cs */
    const int rbase = t >> 3;            /* 0..31 */
    const int cs    = (t & 7) * 8;       /* fp16 col offset, 0..56 */
    const uint32_t dd = (uint32_t)(rbase * LDA + cs) * 2;
    const int g = lane >> 2, tq = lane & 3;

    for (int tile = blockIdx.x; tile < nTiles; tile += gridDim.x) {
        const int rowBase = (tile / nTilesX) * 128;
        const int colBase = (tile % nTilesX) * 128;

        int av[4];
        #pragma unroll
        for (int i = 0; i < 4; i++)
            av[i] = (rowBase + rbase + 32 * i) < M ? 16 : 0;
        const __half* pA = Ah + (size_t)(rowBase + rbase) * KDIM + cs;
        const __half* pB = Bh + (size_t)(colBase + rbase) * KDIM + cs;

        float acc[4][4][4];
        #pragma unroll
        for (int i = 0; i < 4; i++)
            #pragma unroll
            for (int j = 0; j < 4; j++)
                #pragma unroll
                for (int q = 0; q < 4; q++) acc[i][j][q] = 0.f;

        /* prologue: chunks 0,1 -> stages 0,1 */
        #pragma unroll
        for (int p = 0; p < 2; p++) {
            const uint32_t b = sb + p * STG_B;
            const int k0 = p * BK;
            #pragma unroll
            for (int i = 0; i < 4; i++) {
                cp16(b + dd + i * (32 * LDA * 2), pA + k0 + (size_t)(32 * i) * KDIM, av[i]);
                cp16(b + TILE_AB + dd + i * (32 * LDA * 2), pB + k0 + (size_t)(32 * i) * KDIM, 16);
            }
            cp_commit();
        }

        for (int c = 0; c < NCHUNK; c++) {
            if (c < NCHUNK - 1) cp_wait<1>();
            else                cp_wait<0>();
            __syncthreads();

            /* prefetch chunk c+2 into stage (c+2)%3 (old readers closed by bar) */
            if (c + 2 < NCHUNK) {
                const int k0 = (c + 2) * BK;
                const uint32_t b = sb + ((c + 2) % NSTG) * STG_B;
                #pragma unroll
                for (int i = 0; i < 4; i++) {
                    cp16(b + dd + i * (32 * LDA * 2), pA + k0 + (size_t)(32 * i) * KDIM, av[i]);
                    cp16(b + TILE_AB + dd + i * (32 * LDA * 2), pB + k0 + (size_t)(32 * i) * KDIM, 16);
                }
                cp_commit();
            }

            const uint32_t sA = sb + (c % NSTG) * STG_B;
            const uint32_t sB = sA + TILE_AB;

            #pragma unroll
            for (int ks = 0; ks < 4; ks++) {
                const int kk = ks * 16;
                uint32_t ah[4][4];
                {
                    const int r  = wm * 64 + (lane & 15);
                    const int kc = kk + ((lane >> 4) << 3);
                    #pragma unroll
                    for (int mt = 0; mt < 4; mt++)
                        ldsm_x4(ah[mt], sA + (uint32_t)((r + mt * 16) * LDA + kc) * 2);
                }
                /* B: ldsm_x4 loads two n8k16 fragments (nt pair) at full rate */
                #pragma unroll
                for (int p = 0; p < 2; p++) {
                    uint32_t bb[4];
                    const int row = wn * 32 + p * 16 + ((lane >> 4) << 3) + (lane & 7);
                    const int kc  = kk + (((lane >> 3) & 1) << 3);
                    ldsm_x4(bb, sB + (uint32_t)(row * LDA + kc) * 2);
                    #pragma unroll
                    for (int mt = 0; mt < 4; mt++) {
                        mma_f16(acc[mt][2 * p],     ah[mt], bb);
                        mma_f16(acc[mt][2 * p + 1], ah[mt], bb + 2);
                    }
                }
            }
        }

        /* ---- epilogue: fp16 store + fused attention dot products --------- */
        const int h = (H > 1) ? (colBase >> 8) : 0;

        float s_c[8], d_c[8];
        #pragma unroll
        for (int nt = 0; nt < 4; nt++) {
            int colg = colBase + wn * 32 + nt * 8 + 2 * tq;
            s_c[2 * nt]     = att_s[colg];
            s_c[2 * nt + 1] = att_s[colg + 1];
            d_c[2 * nt]     = att_d[colg];
            d_c[2 * nt + 1] = att_d[colg + 1];
        }

        #pragma unroll
        for (int mt = 0; mt < 4; mt++) {
            int r0g = rowBase + wm * 64 + mt * 16 + g;
            float ps0 = 0.f, pd0 = 0.f, ps1 = 0.f, pd1 = 0.f;
            #pragma unroll
            for (int nt = 0; nt < 4; nt++) {
                int col = colBase + wn * 32 + nt * 8 + 2 * tq;
                if (r0g < M)
                    *(__half2*)&Ch[(size_t)r0g * N + col] =
                        __floats2half2_rn(acc[mt][nt][0], acc[mt][nt][1]);
                if (r0g + 8 < M)
                    *(__half2*)&Ch[(size_t)(r0g + 8) * N + col] =
                        __floats2half2_rn(acc[mt][nt][2], acc[mt][nt][3]);
                ps0 += acc[mt][nt][0] * s_c[2 * nt] + acc[mt][nt][1] * s_c[2 * nt + 1];
                pd0 += acc[mt][nt][0] * d_c[2 * nt] + acc[mt][nt][1] * d_c[2 * nt + 1];
                ps1 += acc[mt][nt][2] * s_c[2 * nt] + acc[mt][nt][3] * s_c[2 * nt + 1];
                pd1 += acc[mt][nt][2] * d_c[2 * nt] + acc[mt][nt][3] * d_c[2 * nt + 1];
            }
            #pragma unroll
            for (int o = 1; o <= 2; o <<= 1) {
                ps0 += __shfl_xor_sync(0xffffffffu, ps0, o);
                pd0 += __shfl_xor_sync(0xffffffffu, pd0, o);
                ps1 += __shfl_xor_sync(0xffffffffu, ps1, o);
                pd1 += __shfl_xor_sync(0xffffffffu, pd1, o);
            }
            if (tq == 0) {
                if (r0g < M) {
                    atomicAdd(&asrc[r0g * H + h], ps0);
                    atomicAdd(&adst[r0g * H + h], pd0);
                }
                if (r0g + 8 < M) {
                    atomicAdd(&asrc[(r0g + 8) * H + h], ps1);
                    atomicAdd(&adst[(r0g + 8) * H + h], pd1);
                }
            }
        }
    }
}

/* ---------------- fp32 -> fp16 elementwise ---------------------------------- */
__global__ void conv_half_kernel(const float* __restrict__ src,
                                 __half* __restrict__ dst, int n4) {
    int i = blockIdx.x * blockDim.x + threadIdx.x;
    if (i >= n4) return;
    float4 v = ((const float4*)src)[i];
    __half2 a = __floats2half2_rn(v.x, v.y);
    __half2 b = __floats2half2_rn(v.z, v.w);
    ((uint2*)dst)[i] = make_uint2(*(uint32_t*)&a, *(uint32_t*)&b);
}

/* ---------------- W[k][n] -> Wt[n][k] transpose -> fp16 -------------------- */
__global__ void trans_half_kernel(const float* __restrict__ W,
                                  __half* __restrict__ Th, int K, int N) {
    __shared__ float tile[32][33];
    int k0 = blockIdx.y * 32, n0 = blockIdx.x * 32;
    int tx = threadIdx.x, ty = threadIdx.y;   /* 32 x 8 */
    #pragma unroll
    for (int i = 0; i < 32; i += 8)
        tile[ty + i][tx] = W[(size_t)(k0 + ty + i) * N + n0 + tx];
    __syncthreads();
    #pragma unroll
    for (int i = 0; i < 32; i += 8) {
        float v = tile[tx][ty + i];
        Th[(size_t)(n0 + ty + i) * K + k0 + tx] = __float2half_rn(v);
    }
}

/* ---------------- init: zero deg + att accumulators + detect dtype --------- */
__global__ void init_kernel(const int* ei32) {
    int i = blockIdx.x * 256 + threadIdx.x;
    if (i < N_NODES) g_deg[i] = 0;
    for (int j = i; j < N_NODES * H1; j += NBLK * 256) {
        g_asrc1[j] = 0.f;
        g_adst1[j] = 0.f;
    }
    if (i < N_NODES) {
        g_asrc2[i] = 0.f;
        g_adst2[i] = 0.f;
    }
    if (blockIdx.x == 0) {
        __shared__ int any;
        if (threadIdx.x == 0) any = 0;
        __syncthreads();
        int v = 0;
        for (int j = threadIdx.x; j < 1024; j += 256)
            v |= ei32[2 * j + 1];
        if (v) atomicOr(&any, 1);
        __syncthreads();
        if (threadIdx.x == 0) g_is64 = (any == 0) ? 1 : 0;
    }
}
__device__ __forceinline__ int edge_at(const void* ei, long long idx) {
    if (g_is64) return (int)((const long long*)ei)[idx];
    return ((const int*)ei)[idx];
}

/* ---------------- CSR build ------------------------------------------------ */
__global__ void count_kernel(const void* ei) {
    int e = blockIdx.x * blockDim.x + threadIdx.x;
    if (e >= ET) return;
    int d = (e < E_EDGES) ? edge_at(ei, (long long)E_EDGES + e) : (e - E_EDGES);
    atomicAdd(&g_deg[d], 1);
}
__global__ void bsum_kernel() {
    __shared__ int s[256];
    int i = blockIdx.x * 256 + threadIdx.x;
    s[threadIdx.x] = (i < N_NODES) ? g_deg[i] : 0;
    __syncthreads();
    for (int o = 128; o; o >>= 1) {
        if (threadIdx.x < o) s[threadIdx.x] += s[threadIdx.x + o];
        __syncthreads();
    }
    if (threadIdx.x == 0) g_bsum[blockIdx.x] = s[0];
}
__global__ void bscan_kernel() {
    __shared__ int s[128];
    int t = threadIdx.x;
    int v = (t < NBLK) ? g_bsum[t] : 0;
    s[t] = v;
    __syncthreads();
    for (int o = 1; o < 128; o <<= 1) {
        int u = (t >= o) ? s[t - o] : 0;
        __syncthreads();
        s[t] += u;
        __syncthreads();
    }
    g_boff[t] = s[t] - v;
    if (t == 0) g_rowptr[N_NODES] = ET;
}
__global__ void fscan_kernel() {
    __shared__ int s[256];
    int t = threadIdx.x;
    int i = blockIdx.x * 256 + t;
    int d = (i < N_NODES) ? g_deg[i] : 0;
    s[t] = d;
    __syncthreads();
    for (int o = 1; o < 256; o <<= 1) {
        int u = (t >= o) ? s[t - o] : 0;
        __syncthreads();
        s[t] += u;
        __syncthreads();
    }
    if (i < N_NODES) {
        int off = s[t] - d + g_boff[blockIdx.x];
        g_rowptr[i] = off;
        g_cursor[i] = off;
    }
}
__global__ void scatter_kernel(const void* ei) {
    int e = blockIdx.x * blockDim.x + threadIdx.x;
    if (e >= ET) return;
    int s, d;
    if (e < E_EDGES) {
        s = edge_at(ei, e);
        d = edge_at(ei, (long long)E_EDGES + e);
    } else {
        s = d = e - E_EDGES;
    }
    int slot = atomicAdd(&g_cursor[d], 1);
    g_col[slot] = s;
}

/* ---------------- segment softmax, 3 heads fused (warp per node) ----------- */
__global__ void softmax3_kernel(const float* __restrict__ asrc,
                                const float* __restrict__ adst) {
    int n    = (blockIdx.x * blockDim.x + threadIdx.x) >> 5;
    int lane = threadIdx.x & 31;
    if (n >= N_NODES) return;
    int st = g_rowptr[n], en = g_rowptr[n + 1];
    float ad0 = adst[n * 3 + 0], ad1 = adst[n * 3 + 1], ad2 = adst[n * 3 + 2];
    float m0 = -1e30f, m1 = -1e30f, m2 = -1e30f;
    for (int s = st + lane; s < en; s += 32) {
        int col = g_col[s];
        float v0 = asrc[col * 3 + 0] + ad0;
        float v1 = asrc[col * 3 + 1] + ad1;
        float v2 = asrc[col * 3 + 2] + ad2;
        v0 = (v0 > 0.f) ? v0 : 0.2f * v0;
        v1 = (v1 > 0.f) ? v1 : 0.2f * v1;
        v2 = (v2 > 0.f) ? v2 : 0.2f * v2;
        g_alpha[(size_t)s * 3 + 0] = v0;
        g_alpha[(size_t)s * 3 + 1] = v1;
        g_alpha[(size_t)s * 3 + 2] = v2;
        m0 = fmaxf(m0, v0); m1 = fmaxf(m1, v1); m2 = fmaxf(m2, v2);
    }
    m0 = warpMax(m0); m1 = warpMax(m1); m2 = warpMax(m2);
    float s0 = 0.f, s1 = 0.f, s2 = 0.f;
    for (int s = st + lane; s < en; s += 32) {
        float e0 = __expf(g_alpha[(size_t)s * 3 + 0] - m0);
        float e1 = __expf(g_alpha[(size_t)s * 3 + 1] - m1);
        float e2 = __expf(g_alpha[(size_t)s * 3 + 2] - m2);
        g_alpha[(size_t)s * 3 + 0] = e0;
        g_alpha[(size_t)s * 3 + 1] = e1;
        g_alpha[(size_t)s * 3 + 2] = e2;
        s0 += e0; s1 += e1; s2 += e2;
    }
    s0 = warpSum(s0); s1 = warpSum(s1); s2 = warpSum(s2);
    if (lane == 0) {
        g_inv1[n * 3 + 0] = 1.f / s0;
        g_inv1[n * 3 + 1] = 1.f / s1;
        g_inv1[n * 3 + 2] = 1.f / s2;
    }
}

/* single-head version for layer 2 */
__global__ void softmax1_kernel(const float* __restrict__ asrc,
                                const float* __restrict__ adst) {
    int n    = (blockIdx.x * blockDim.x + threadIdx.x) >> 5;
    int lane = threadIdx.x & 31;
    if (n >= N_NODES) return;
    int st = g_rowptr[n], en = g_rowptr[n + 1];
    float ad = adst[n];
    float mx = -1e30f;
    for (int s = st + lane; s < en; s += 32) {
        float v = asrc[g_col[s]] + ad;
        v = (v > 0.f) ? v : 0.2f * v;
        g_alpha[s] = v;
        mx = fmaxf(mx, v);
    }
    mx = warpMax(mx);
    float sum = 0.f;
    for (int s = st + lane; s < en; s += 32) {
        float e = __expf(g_alpha[s] - mx);
        g_alpha[s] = e;
        sum += e;
    }
    sum = warpSum(sum);
    if (lane == 0) g_inv2[n] = 1.f / sum;
}

/* ---------------- layer-1 aggregation (fp16 reads) + bias + ELU ------------ */
__global__ __launch_bounds__(192)
void agg1_kernel(const float* __restrict__ b1) {
    int n = blockIdx.x;
    int t = threadIdx.x;
    int head = t >> 6;
    int base = head * 256 + (t & 63) * 4;
    int st = g_rowptr[n], en = g_rowptr[n + 1];
    float4 a = make_float4(0.f, 0.f, 0.f, 0.f);
    #pragma unroll 4
    for (int s = st; s < en; s++) {
        float w = g_alpha[(size_t)s * 3 + head];
        uint2 u = *(const uint2*)(g_xp1h + (size_t)g_col[s] * F1 + base);
        float2 c0 = __half22float2(*(__half2*)&u.x);
        float2 c1 = __half22float2(*(__half2*)&u.y);
        a.x += w * c0.x; a.y += w * c0.y; a.z += w * c1.x; a.w += w * c1.y;
    }
    float inv = g_inv1[n * 3 + head];
    float4 b = *(const float4*)(b1 + base);
    a.x = a.x * inv + b.x; a.y = a.y * inv + b.y;
    a.z = a.z * inv + b.z; a.w = a.w * inv + b.w;
    a.x = (a.x > 0.f) ? a.x : expm1f(a.x);
    a.y = (a.y > 0.f) ? a.y : expm1f(a.y);
    a.z = (a.z > 0.f) ? a.z : expm1f(a.z);
    a.w = (a.w > 0.f) ? a.w : expm1f(a.w);
    __half2 h0 = __floats2half2_rn(a.x, a.y);
    __half2 h1 = __floats2half2_rn(a.z, a.w);
    size_t o4 = ((size_t)n * F1 + base) / 4;
    ((uint2*)g_hh)[o4] = make_uint2(*(uint32_t*)&h0, *(uint32_t*)&h1);
}

/* ---------------- layer-2 aggregation (fp16 reads), 4 nodes/block ---------- */
__global__ __launch_bounds__(256)
void agg2_kernel(const float* __restrict__ b2, float* __restrict__ out) {
    int t = threadIdx.x;
    int n = blockIdx.x * 4 + (t >> 6);
    if (n >= N_NODES) return;
    int c4 = (t & 63) * 4;
    int st = g_rowptr[n], en = g_rowptr[n + 1];
    float4 a = make_float4(0.f, 0.f, 0.f, 0.f);
    #pragma unroll 4
    for (int s = st; s < en; s++) {
        float w = g_alpha[s];
        uint2 u = *(const uint2*)(g_xp2h + (size_t)g_col[s] * HID + c4);
        float2 c0 = __half22float2(*(__half2*)&u.x);
        float2 c1 = __half22float2(*(__half2*)&u.y);
        a.x += w * c0.x; a.y += w * c0.y; a.z += w * c1.x; a.w += w * c1.y;
    }
    float inv = g_inv2[n];
    float4 b = *(const float4*)(b2 + c4);
    a.x = a.x * inv + b.x; a.y = a.y * inv + b.y;
    a.z = a.z * inv + b.z; a.w = a.w * inv + b.w;
    *(float4*)(out + (size_t)n * HID + c4) = a;
}

/* ---------------- launch --------------------------------------------------- */
extern "C" void kernel_launch(void* const* d_in, const int* in_sizes, int n_in,
                              void* d_out, int out_size) {
    const float* x   = (const float*)d_in[0];
    const void*  ei  = d_in[1];
    const float* W1  = (const float*)d_in[2];
    const float* as1 = (const float*)d_in[3];
    const float* ad1 = (const float*)d_in[4];
    const float* b1  = (const float*)d_in[5];
    const float* W2  = (const float*)d_in[6];
    const float* as2 = (const float*)d_in[7];
    const float* ad2 = (const float*)d_in[8];
    const float* b2  = (const float*)d_in[9];
    float* out = (float*)d_out;

    void *p_x1h, *p_x2h, *p_as1, *p_ad1, *p_as2, *p_ad2;
    void *p_xh, *p_hh, *p_w1h, *p_w2h;
    cudaGetSymbolAddress(&p_x1h, g_xp1h);
    cudaGetSymbolAddress(&p_x2h, g_xp2h);
    cudaGetSymbolAddress(&p_as1, g_asrc1);
    cudaGetSymbolAddress(&p_ad1, g_adst1);
    cudaGetSymbolAddress(&p_as2, g_asrc2);
    cudaGetSymbolAddress(&p_ad2, g_adst2);
    cudaGetSymbolAddress(&p_xh,  gx_h);
    cudaGetSymbolAddress(&p_hh,  g_hh);
    cudaGetSymbolAddress(&p_w1h, gw1t_h);
    cudaGetSymbolAddress(&p_w2h, gw2t_h);

    cudaFuncSetAttribute(mma_gemm_kernel,
                         cudaFuncAttributeMaxDynamicSharedMemorySize, GSMEM);

    /* #1..#3: prerequisites of GEMM1 */
    {
        int n4 = N_NODES * IN_DIM / 4;
        conv_half_kernel<<<(n4 + 255) / 256, 256>>>(x, (__half*)p_xh, n4);
        trans_half_kernel<<<dim3(F1 / 32, KDIM / 32), dim3(32, 8)>>>(
            W1, (__half*)p_w1h, KDIM, F1);
    }
    init_kernel<<<NBLK, 256>>>((const int*)ei);

    /* #4: GEMM1 + fused attention, persistent (ncu capture target) */
    {
        int nTilesX = F1 / 128;                       /* 6 */
        int nTiles  = nTilesX * ((N_NODES + 127) / 128);   /* 942 */
        int grid = nTiles < NPERS ? nTiles : NPERS;
        mma_gemm_kernel<<<grid, 256, GSMEM>>>(
            (const __half*)p_xh, (const __half*)p_w1h,
            (__half*)p_x1h, as1, ad1, (float*)p_as1, (float*)p_ad1,
            H1, N_NODES, F1, nTilesX, nTiles);
    }

    /* CSR build + W2 prep (independent of GEMM1) */
    trans_half_kernel<<<dim3(HID / 32, KDIM / 32), dim3(32, 8)>>>(
        W2, (__half*)p_w2h, KDIM, HID);
    count_kernel<<<(ET + 255) / 256, 256>>>(ei);
    bsum_kernel<<<NBLK, 256>>>();
    bscan_kernel<<<1, 128>>>();
    fscan_kernel<<<NBLK, 256>>>();
    scatter_kernel<<<(ET + 255) / 256, 256>>>(ei);

    /* layer 1 edge phase */
    softmax3_kernel<<<(N_NODES * 32 + 255) / 256, 256>>>(
        (const float*)p_as1, (const float*)p_ad1);
    agg1_kernel<<<N_NODES, 192>>>(b1);

    /* layer 2 */
    {
        int nTilesX = HID / 128;                      /* 2 */
        int nTiles  = nTilesX * ((N_NODES + 127) / 128);   /* 314 */
        int grid = nTiles < NPERS ? nTiles : NPERS;
        mma_gemm_kernel<<<grid, 256, GSMEM>>>(
            (const __half*)p_hh, (const __half*)p_w2h,
            (__half*)p_x2h, as2, ad2, (float*)p_as2, (float*)p_ad2,
            1, N_NODES, HID, nTilesX, nTiles);
    }
    softmax1_kernel<<<(N_NODES * 32 + 255) / 256, 256>>>(
        (const float*)p_as2, (const float*)p_ad2);
    agg2_kernel<<<(N_NODES + 3) / 4, 256>>>(b2, out);
}

// round 13
// speedup vs baseline: 4.5940x; 1.0315x over previous
#include <cuda_runtime.h>
#include <cuda_fp16.h>
#include <math.h>
#include <stdint.h>

#define N_NODES 20000
#define E_EDGES 320000
#define ET      (E_EDGES + N_NODES)   /* 340000 with self loops */
#define IN_DIM  768
#define HID     256
#define H1      3
#define F1      (H1 * HID)            /* 768 */
#define KDIM    768
#define NBLK    ((N_NODES + 255) / 256)   /* 79 */
#define NPERS   296                   /* 2 CTAs x 148 SMs */

/* ---------------- scratch (device globals, no allocs allowed) ------------- */
__device__ __half g_xp1h[(size_t)N_NODES * F1];    /* GEMM1 out (fp16)   */
__device__ __half g_xp2h[(size_t)N_NODES * HID];   /* GEMM2 out (fp16)   */
__device__ __half gx_h [(size_t)N_NODES * IN_DIM]; /* x in fp16          */
__device__ __half g_hh [(size_t)N_NODES * F1];     /* h in fp16          */
__device__ __half gw1t_h[F1 * KDIM];               /* W1^T [n][k] fp16   */
__device__ __half gw2t_h[HID * KDIM];
__device__ float g_asrc1[N_NODES * H1];
__device__ float g_adst1[N_NODES * H1];
__device__ float g_asrc2[N_NODES];
__device__ float g_adst2[N_NODES];
__device__ int   g_deg[N_NODES];
__device__ int   g_rowptr[N_NODES + 1];
__device__ int   g_cursor[N_NODES];
__device__ int   g_col[ET];
__device__ int   g_bsum[128];
__device__ int   g_boff[128];
__device__ int   g_is64;

/* ---------------- helpers ------------------------------------------------- */
__device__ __forceinline__ float warpSum(float v) {
    #pragma unroll
    for (int o = 16; o; o >>= 1) v += __shfl_xor_sync(0xffffffffu, v, o);
    return v;
}
__device__ __forceinline__ uint32_t smem_u32(const void* p) {
    uint32_t a;
    asm("{ .reg .u64 t; cvta.to.shared.u64 t, %1; cvt.u32.u64 %0, t; }"
        : "=r"(a) : "l"(p));
    return a;
}

/* ---------------- mma.sync / ldmatrix / cp.async wrappers ----------------- */
__device__ __forceinline__ void ldsm_x4(uint32_t* r, uint32_t addr) {
    asm volatile("ldmatrix.sync.aligned.m8n8.x4.shared.b16 {%0,%1,%2,%3}, [%4];"
        : "=r"(r[0]), "=r"(r[1]), "=r"(r[2]), "=r"(r[3]) : "r"(addr));
}
__device__ __forceinline__ void mma_f16(float* c, const uint32_t* a, const uint32_t* b) {
    asm volatile(
        "mma.sync.aligned.m16n8k16.row.col.f32.f16.f16.f32 "
        "{%0,%1,%2,%3}, {%4,%5,%6,%7}, {%8,%9}, {%0,%1,%2,%3};"
        : "+f"(c[0]), "+f"(c[1]), "+f"(c[2]), "+f"(c[3])
        : "r"(a[0]), "r"(a[1]), "r"(a[2]), "r"(a[3]), "r"(b[0]), "r"(b[1]));
}
__device__ __forceinline__ void cp16(uint32_t dst, const void* src, int sz) {
    asm volatile("cp.async.cg.shared.global [%0], [%1], 16, %2;"
        :: "r"(dst), "l"(src), "r"(sz) : "memory");
}
__device__ __forceinline__ void cp_commit() {
    asm volatile("cp.async.commit_group;" ::: "memory");
}
template <int W> __device__ __forceinline__ void cp_wait() {
    asm volatile("cp.async.wait_group %0;" :: "n"(W) : "memory");
}

/* ======================================================================== */
/*  Persistent HMMA GEMM (fp16): Ch[M,N] = A[M,768] @ Bt[N,768]^T            */
/*  BK=64 chunks, 3-stage cp.async, 1 barrier/chunk, full-rate ldsm_x4       */
/*  Fused attention dot-product epilogue (atomics)                           */
/* ======================================================================== */
#define BK    64
#define LDA   72                   /* 144 B rows: bank stride 4 mod 32 */
#define TILE_AB (128 * LDA * 2)    /* 18432 B per tile array */
#define STG_B  (2 * TILE_AB)       /* 36864 B per stage (A + B) */
#define NSTG   3
#define GSMEM  (NSTG * STG_B)      /* 110592 B */
#define NCHUNK (KDIM / BK)         /* 12 */

__global__ __launch_bounds__(256, 2)
void mma_gemm_kernel(const __half* __restrict__ Ah,
                     const __half* __restrict__ Bh,
                     __half* __restrict__ Ch,
                     const float* __restrict__ att_s,
                     const float* __restrict__ att_d,
                     float* __restrict__ asrc,
                     float* __restrict__ adst,
                     int H, int M, int N, int nTilesX, int nTiles) {
    extern __shared__ char smem[];
    const int t = threadIdx.x, lane = t & 31, wid = t >> 5;
    const int wm = wid >> 2, wn = wid & 3;
    const uint32_t sb = smem_u32(smem);

    const int rbase = t >> 3;            /* 0..31 */
    const int cs    = (t & 7) * 8;       /* fp16 col offset, 0..56 */
    const uint32_t dd = (uint32_t)(rbase * LDA + cs) * 2;
    const int g = lane >> 2, tq = lane & 3;

    for (int tile = blockIdx.x; tile < nTiles; tile += gridDim.x) {
        const int rowBase = (tile / nTilesX) * 128;
        const int colBase = (tile % nTilesX) * 128;

        int av[4];
        #pragma unroll
        for (int i = 0; i < 4; i++)
            av[i] = (rowBase + rbase + 32 * i) < M ? 16 : 0;
        const __half* pA = Ah + (size_t)(rowBase + rbase) * KDIM + cs;
        const __half* pB = Bh + (size_t)(colBase + rbase) * KDIM + cs;

        float acc[4][4][4];
        #pragma unroll
        for (int i = 0; i < 4; i++)
            #pragma unroll
            for (int j = 0; j < 4; j++)
                #pragma unroll
                for (int q = 0; q < 4; q++) acc[i][j][q] = 0.f;

        /* prologue: chunks 0,1 -> stages 0,1 */
        #pragma unroll
        for (int p = 0; p < 2; p++) {
            const uint32_t b = sb + p * STG_B;
            const int k0 = p * BK;
            #pragma unroll
            for (int i = 0; i < 4; i++) {
                cp16(b + dd + i * (32 * LDA * 2), pA + k0 + (size_t)(32 * i) * KDIM, av[i]);
                cp16(b + TILE_AB + dd + i * (32 * LDA * 2), pB + k0 + (size_t)(32 * i) * KDIM, 16);
            }
            cp_commit();
        }

        for (int c = 0; c < NCHUNK; c++) {
            if (c < NCHUNK - 1) cp_wait<1>();
            else                cp_wait<0>();
            __syncthreads();

            if (c + 2 < NCHUNK) {
                const int k0 = (c + 2) * BK;
                const uint32_t b = sb + ((c + 2) % NSTG) * STG_B;
                #pragma unroll
                for (int i = 0; i < 4; i++) {
                    cp16(b + dd + i * (32 * LDA * 2), pA + k0 + (size_t)(32 * i) * KDIM, av[i]);
                    cp16(b + TILE_AB + dd + i * (32 * LDA * 2), pB + k0 + (size_t)(32 * i) * KDIM, 16);
                }
                cp_commit();
            }

            const uint32_t sA = sb + (c % NSTG) * STG_B;
            const uint32_t sB = sA + TILE_AB;

            #pragma unroll
            for (int ks = 0; ks < 4; ks++) {
                const int kk = ks * 16;
                uint32_t ah[4][4];
                {
                    const int r  = wm * 64 + (lane & 15);
                    const int kc = kk + ((lane >> 4) << 3);
                    #pragma unroll
                    for (int mt = 0; mt < 4; mt++)
                        ldsm_x4(ah[mt], sA + (uint32_t)((r + mt * 16) * LDA + kc) * 2);
                }
                #pragma unroll
                for (int p = 0; p < 2; p++) {
                    uint32_t bb[4];
                    const int row = wn * 32 + p * 16 + ((lane >> 4) << 3) + (lane & 7);
                    const int kc  = kk + (((lane >> 3) & 1) << 3);
                    ldsm_x4(bb, sB + (uint32_t)(row * LDA + kc) * 2);
                    #pragma unroll
                    for (int mt = 0; mt < 4; mt++) {
                        mma_f16(acc[mt][2 * p],     ah[mt], bb);
                        mma_f16(acc[mt][2 * p + 1], ah[mt], bb + 2);
                    }
                }
            }
        }

        /* ---- epilogue: fp16 store + fused attention dot products --------- */
        const int h = (H > 1) ? (colBase >> 8) : 0;

        float s_c[8], d_c[8];
        #pragma unroll
        for (int nt = 0; nt < 4; nt++) {
            int colg = colBase + wn * 32 + nt * 8 + 2 * tq;
            s_c[2 * nt]     = att_s[colg];
            s_c[2 * nt + 1] = att_s[colg + 1];
            d_c[2 * nt]     = att_d[colg];
            d_c[2 * nt + 1] = att_d[colg + 1];
        }

        #pragma unroll
        for (int mt = 0; mt < 4; mt++) {
            int r0g = rowBase + wm * 64 + mt * 16 + g;
            float ps0 = 0.f, pd0 = 0.f, ps1 = 0.f, pd1 = 0.f;
            #pragma unroll
            for (int nt = 0; nt < 4; nt++) {
                int col = colBase + wn * 32 + nt * 8 + 2 * tq;
                if (r0g < M)
                    *(__half2*)&Ch[(size_t)r0g * N + col] =
                        __floats2half2_rn(acc[mt][nt][0], acc[mt][nt][1]);
                if (r0g + 8 < M)
                    *(__half2*)&Ch[(size_t)(r0g + 8) * N + col] =
                        __floats2half2_rn(acc[mt][nt][2], acc[mt][nt][3]);
                ps0 += acc[mt][nt][0] * s_c[2 * nt] + acc[mt][nt][1] * s_c[2 * nt + 1];
                pd0 += acc[mt][nt][0] * d_c[2 * nt] + acc[mt][nt][1] * d_c[2 * nt + 1];
                ps1 += acc[mt][nt][2] * s_c[2 * nt] + acc[mt][nt][3] * s_c[2 * nt + 1];
                pd1 += acc[mt][nt][2] * d_c[2 * nt] + acc[mt][nt][3] * d_c[2 * nt + 1];
            }
            #pragma unroll
            for (int o = 1; o <= 2; o <<= 1) {
                ps0 += __shfl_xor_sync(0xffffffffu, ps0, o);
                pd0 += __shfl_xor_sync(0xffffffffu, pd0, o);
                ps1 += __shfl_xor_sync(0xffffffffu, ps1, o);
                pd1 += __shfl_xor_sync(0xffffffffu, pd1, o);
            }
            if (tq == 0) {
                if (r0g < M) {
                    atomicAdd(&asrc[r0g * H + h], ps0);
                    atomicAdd(&adst[r0g * H + h], pd0);
                }
                if (r0g + 8 < M) {
                    atomicAdd(&asrc[(r0g + 8) * H + h], ps1);
                    atomicAdd(&adst[(r0g + 8) * H + h], pd1);
                }
            }
        }
    }
}

/* ---------------- fp32 -> fp16 elementwise --------------------------------- */
__global__ void conv_half_kernel(const float* __restrict__ src,
                                 __half* __restrict__ dst, int n4) {
    int i = blockIdx.x * blockDim.x + threadIdx.x;
    if (i >= n4) return;
    float4 v = ((const float4*)src)[i];
    __half2 a = __floats2half2_rn(v.x, v.y);
    __half2 b = __floats2half2_rn(v.z, v.w);
    ((uint2*)dst)[i] = make_uint2(*(uint32_t*)&a, *(uint32_t*)&b);
}

/* ---------------- W[k][n] -> Wt[n][k] transpose -> fp16 -------------------- */
__global__ void trans_half_kernel(const float* __restrict__ W,
                                  __half* __restrict__ Th, int K, int N) {
    __shared__ float tile[32][33];
    int k0 = blockIdx.y * 32, n0 = blockIdx.x * 32;
    int tx = threadIdx.x, ty = threadIdx.y;   /* 32 x 8 */
    #pragma unroll
    for (int i = 0; i < 32; i += 8)
        tile[ty + i][tx] = W[(size_t)(k0 + ty + i) * N + n0 + tx];
    __syncthreads();
    #pragma unroll
    for (int i = 0; i < 32; i += 8) {
        float v = tile[tx][ty + i];
        Th[(size_t)(n0 + ty + i) * K + k0 + tx] = __float2half_rn(v);
    }
}

/* ---------------- init: zero deg + att accumulators + detect dtype --------- */
__global__ void init_kernel(const int* ei32) {
    int i = blockIdx.x * 256 + threadIdx.x;
    if (i < N_NODES) g_deg[i] = 0;
    for (int j = i; j < N_NODES * H1; j += NBLK * 256) {
        g_asrc1[j] = 0.f;
        g_adst1[j] = 0.f;
    }
    if (i < N_NODES) {
        g_asrc2[i] = 0.f;
        g_adst2[i] = 0.f;
    }
    if (blockIdx.x == 0) {
        __shared__ int any;
        if (threadIdx.x == 0) any = 0;
        __syncthreads();
        int v = 0;
        for (int j = threadIdx.x; j < 1024; j += 256)
            v |= ei32[2 * j + 1];
        if (v) atomicOr(&any, 1);
        __syncthreads();
        if (threadIdx.x == 0) g_is64 = (any == 0) ? 1 : 0;
    }
}
__device__ __forceinline__ int edge_at(const void* ei, long long idx) {
    if (g_is64) return (int)((const long long*)ei)[idx];
    return ((const int*)ei)[idx];
}

/* ---------------- CSR build ------------------------------------------------ */
__global__ void count_kernel(const void* ei) {
    int e = blockIdx.x * blockDim.x + threadIdx.x;
    if (e >= ET) return;
    int d = (e < E_EDGES) ? edge_at(ei, (long long)E_EDGES + e) : (e - E_EDGES);
    atomicAdd(&g_deg[d], 1);
}
__global__ void bsum_kernel() {
    __shared__ int s[256];
    int i = blockIdx.x * 256 + threadIdx.x;
    s[threadIdx.x] = (i < N_NODES) ? g_deg[i] : 0;
    __syncthreads();
    for (int o = 128; o; o >>= 1) {
        if (threadIdx.x < o) s[threadIdx.x] += s[threadIdx.x + o];
        __syncthreads();
    }
    if (threadIdx.x == 0) g_bsum[blockIdx.x] = s[0];
}
__global__ void bscan_kernel() {
    __shared__ int s[128];
    int t = threadIdx.x;
    int v = (t < NBLK) ? g_bsum[t] : 0;
    s[t] = v;
    __syncthreads();
    for (int o = 1; o < 128; o <<= 1) {
        int u = (t >= o) ? s[t - o] : 0;
        __syncthreads();
        s[t] += u;
        __syncthreads();
    }
    g_boff[t] = s[t] - v;
    if (t == 0) g_rowptr[N_NODES] = ET;
}
__global__ void fscan_kernel() {
    __shared__ int s[256];
    int t = threadIdx.x;
    int i = blockIdx.x * 256 + t;
    int d = (i < N_NODES) ? g_deg[i] : 0;
    s[t] = d;
    __syncthreads();
    for (int o = 1; o < 256; o <<= 1) {
        int u = (t >= o) ? s[t - o] : 0;
        __syncthreads();
        s[t] += u;
        __syncthreads();
    }
    if (i < N_NODES) {
        int off = s[t] - d + g_boff[blockIdx.x];
        g_rowptr[i] = off;
        g_cursor[i] = off;
    }
}
__global__ void scatter_kernel(const void* ei) {
    int e = blockIdx.x * blockDim.x + threadIdx.x;
    if (e >= ET) return;
    int s, d;
    if (e < E_EDGES) {
        s = edge_at(ei, e);
        d = edge_at(ei, (long long)E_EDGES + e);
    } else {
        s = d = e - E_EDGES;
    }
    int slot = atomicAdd(&g_cursor[d], 1);
    g_col[slot] = s;
}

/* ======================================================================== */
/*  Fused softmax + aggregation, layer 1 (3 heads). Warp per node.          */
/*  Pass A: w = exp(leaky(asrc+adst)) -> SMEM (deg<=128 fast path);         */
/*  Pass B: stream edges from SMEM (broadcast LDS), 24 chans per lane.      */
/* ======================================================================== */
__global__ __launch_bounds__(256)
void fused_agg1_kernel(const float* __restrict__ b1) {
    __shared__ float sw0[8][128];
    __shared__ float sw1[8][128];
    __shared__ float sw2[8][128];
    __shared__ int   scl[8][128];
    int wrp = threadIdx.x >> 5;
    int n = blockIdx.x * 8 + wrp;
    if (n >= N_NODES) return;
    int lane = threadIdx.x & 31;
    int st = g_rowptr[n], en = g_rowptr[n + 1];
    int deg = en - st;

    float ad0 = g_adst1[n * 3 + 0];
    float ad1 = g_adst1[n * 3 + 1];
    float ad2 = g_adst1[n * 3 + 2];

    /* pass A */
    float s0 = 0.f, s1 = 0.f, s2 = 0.f;
    #pragma unroll
    for (int r = 0; r < 4; r++) {
        int idx = r * 32 + lane;
        if (idx < deg) {
            int col = g_col[st + idx];
            float v0 = g_asrc1[col * 3 + 0] + ad0;
            float v1 = g_asrc1[col * 3 + 1] + ad1;
            float v2 = g_asrc1[col * 3 + 2] + ad2;
            v0 = (v0 > 0.f) ? v0 : 0.2f * v0;
            v1 = (v1 > 0.f) ? v1 : 0.2f * v1;
            v2 = (v2 > 0.f) ? v2 : 0.2f * v2;
            float e0 = __expf(v0), e1 = __expf(v1), e2 = __expf(v2);
            sw0[wrp][idx] = e0;
            sw1[wrp][idx] = e1;
            sw2[wrp][idx] = e2;
            scl[wrp][idx] = col;
            s0 += e0; s1 += e1; s2 += e2;
        }
    }
    for (int idx = 128 + lane; idx < deg; idx += 32) {
        int col = g_col[st + idx];
        float v0 = g_asrc1[col * 3 + 0] + ad0;
        float v1 = g_asrc1[col * 3 + 1] + ad1;
        float v2 = g_asrc1[col * 3 + 2] + ad2;
        v0 = (v0 > 0.f) ? v0 : 0.2f * v0;
        v1 = (v1 > 0.f) ? v1 : 0.2f * v1;
        v2 = (v2 > 0.f) ? v2 : 0.2f * v2;
        s0 += __expf(v0); s1 += __expf(v1); s2 += __expf(v2);
    }
    s0 = warpSum(s0); s1 = warpSum(s1); s2 = warpSum(s2);
    float inv0 = 1.f / s0, inv1 = 1.f / s1, inv2 = 1.f / s2;
    __syncwarp();

    /* pass B: 24 channels per lane (3 uint4 chunks), head per chunk */
    int ch0 = lane * 24;
    int hd0 = ch0 >> 8, hd1 = (ch0 + 8) >> 8, hd2 = (ch0 + 16) >> 8;

    float acc[24];
    #pragma unroll
    for (int i = 0; i < 24; i++) acc[i] = 0.f;

    int degf = deg < 128 ? deg : 128;
    for (int idx = 0; idx < degf; idx++) {
        float w0 = sw0[wrp][idx];
        float w1 = sw1[wrp][idx];
        float w2 = sw2[wrp][idx];
        int  col = scl[wrp][idx];
        float wa = (hd0 == 0) ? w0 : (hd0 == 1) ? w1 : w2;
        float wb = (hd1 == 0) ? w0 : (hd1 == 1) ? w1 : w2;
        float wc = (hd2 == 0) ? w0 : (hd2 == 1) ? w1 : w2;
        const __half* row = g_xp1h + (size_t)col * F1 + ch0;
        uint4 ua = *(const uint4*)(row);
        uint4 ub = *(const uint4*)(row + 8);
        uint4 uc = *(const uint4*)(row + 16);
        float2 f;
        f = __half22float2(*(__half2*)&ua.x); acc[0]  += wa * f.x; acc[1]  += wa * f.y;
        f = __half22float2(*(__half2*)&ua.y); acc[2]  += wa * f.x; acc[3]  += wa * f.y;
        f = __half22float2(*(__half2*)&ua.z); acc[4]  += wa * f.x; acc[5]  += wa * f.y;
        f = __half22float2(*(__half2*)&ua.w); acc[6]  += wa * f.x; acc[7]  += wa * f.y;
        f = __half22float2(*(__half2*)&ub.x); acc[8]  += wb * f.x; acc[9]  += wb * f.y;
        f = __half22float2(*(__half2*)&ub.y); acc[10] += wb * f.x; acc[11] += wb * f.y;
        f = __half22float2(*(__half2*)&ub.z); acc[12] += wb * f.x; acc[13] += wb * f.y;
        f = __half22float2(*(__half2*)&ub.w); acc[14] += wb * f.x; acc[15] += wb * f.y;
        f = __half22float2(*(__half2*)&uc.x); acc[16] += wc * f.x; acc[17] += wc * f.y;
        f = __half22float2(*(__half2*)&uc.y); acc[18] += wc * f.x; acc[19] += wc * f.y;
        f = __half22float2(*(__half2*)&uc.z); acc[20] += wc * f.x; acc[21] += wc * f.y;
        f = __half22float2(*(__half2*)&uc.w); acc[22] += wc * f.x; acc[23] += wc * f.y;
    }
    /* heavy-node tail: recompute weights per edge */
    for (int idx = 128; idx < deg; idx++) {
        int col = g_col[st + idx];
        float v0 = g_asrc1[col * 3 + 0] + ad0;
        float v1 = g_asrc1[col * 3 + 1] + ad1;
        float v2 = g_asrc1[col * 3 + 2] + ad2;
        v0 = (v0 > 0.f) ? v0 : 0.2f * v0;
        v1 = (v1 > 0.f) ? v1 : 0.2f * v1;
        v2 = (v2 > 0.f) ? v2 : 0.2f * v2;
        float w0 = __expf(v0), w1 = __expf(v1), w2 = __expf(v2);
        float wa = (hd0 == 0) ? w0 : (hd0 == 1) ? w1 : w2;
        float wb = (hd1 == 0) ? w0 : (hd1 == 1) ? w1 : w2;
        float wc = (hd2 == 0) ? w0 : (hd2 == 1) ? w1 : w2;
        const __half* row = g_xp1h + (size_t)col * F1 + ch0;
        uint4 ua = *(const uint4*)(row);
        uint4 ub = *(const uint4*)(row + 8);
        uint4 uc = *(const uint4*)(row + 16);
        float2 f;
        f = __half22float2(*(__half2*)&ua.x); acc[0]  += wa * f.x; acc[1]  += wa * f.y;
        f = __half22float2(*(__half2*)&ua.y); acc[2]  += wa * f.x; acc[3]  += wa * f.y;
        f = __half22float2(*(__half2*)&ua.z); acc[4]  += wa * f.x; acc[5]  += wa * f.y;
        f = __half22float2(*(__half2*)&ua.w); acc[6]  += wa * f.x; acc[7]  += wa * f.y;
        f = __half22float2(*(__half2*)&ub.x); acc[8]  += wb * f.x; acc[9]  += wb * f.y;
        f = __half22float2(*(__half2*)&ub.y); acc[10] += wb * f.x; acc[11] += wb * f.y;
        f = __half22float2(*(__half2*)&ub.z); acc[12] += wb * f.x; acc[13] += wb * f.y;
        f = __half22float2(*(__half2*)&ub.w); acc[14] += wb * f.x; acc[15] += wb * f.y;
        f = __half22float2(*(__half2*)&uc.x); acc[16] += wc * f.x; acc[17] += wc * f.y;
        f = __half22float2(*(__half2*)&uc.y); acc[18] += wc * f.x; acc[19] += wc * f.y;
        f = __half22float2(*(__half2*)&uc.z); acc[20] += wc * f.x; acc[21] += wc * f.y;
        f = __half22float2(*(__half2*)&uc.w); acc[22] += wc * f.x; acc[23] += wc * f.y;
    }

    /* finalize: normalize, bias, ELU, store fp16 h */
    float invv[3];
    invv[0] = (hd0 == 0) ? inv0 : (hd0 == 1) ? inv1 : inv2;
    invv[1] = (hd1 == 0) ? inv0 : (hd1 == 1) ? inv1 : inv2;
    invv[2] = (hd2 == 0) ? inv0 : (hd2 == 1) ? inv1 : inv2;
    __half* outp = g_hh + (size_t)n * F1 + ch0;
    #pragma unroll
    for (int c = 0; c < 3; c++) {
        float inv = invv[c];
        float4 ba = *(const float4*)(b1 + ch0 + c * 8);
        float4 bb = *(const float4*)(b1 + ch0 + c * 8 + 4);
        float o[8];
        o[0] = acc[c*8+0] * inv + ba.x; o[1] = acc[c*8+1] * inv + ba.y;
        o[2] = acc[c*8+2] * inv + ba.z; o[3] = acc[c*8+3] * inv + ba.w;
        o[4] = acc[c*8+4] * inv + bb.x; o[5] = acc[c*8+5] * inv + bb.y;
        o[6] = acc[c*8+6] * inv + bb.z; o[7] = acc[c*8+7] * inv + bb.w;
        #pragma unroll
        for (int i = 0; i < 8; i++)
            o[i] = (o[i] > 0.f) ? o[i] : expm1f(o[i]);
        __half2 h0 = __floats2half2_rn(o[0], o[1]);
        __half2 h1 = __floats2half2_rn(o[2], o[3]);
        __half2 h2 = __floats2half2_rn(o[4], o[5]);
        __half2 h3 = __floats2half2_rn(o[6], o[7]);
        uint4 u;
        u.x = *(uint32_t*)&h0; u.y = *(uint32_t*)&h1;
        u.z = *(uint32_t*)&h2; u.w = *(uint32_t*)&h3;
        *(uint4*)(outp + c * 8) = u;
    }
}

/* ======================================================================== */
/*  Fused softmax + aggregation, layer 2 (1 head). Warp per node.           */
/* ======================================================================== */
__global__ __launch_bounds__(256)
void fused_agg2_kernel(const float* __restrict__ b2, float* __restrict__ out) {
    __shared__ float sw[8][128];
    __shared__ int   scl[8][128];
    int wrp = threadIdx.x >> 5;
    int n = blockIdx.x * 8 + wrp;
    if (n >= N_NODES) return;
    int lane = threadIdx.x & 31;
    int st = g_rowptr[n], en = g_rowptr[n + 1];
    int deg = en - st;

    float ad = g_adst2[n];

    float sum = 0.f;
    #pragma unroll
    for (int r = 0; r < 4; r++) {
        int idx = r * 32 + lane;
        if (idx < deg) {
            int col = g_col[st + idx];
            float v = g_asrc2[col] + ad;
            v = (v > 0.f) ? v : 0.2f * v;
            float e = __expf(v);
            sw[wrp][idx] = e;
            scl[wrp][idx] = col;
            sum += e;
        }
    }
    for (int idx = 128 + lane; idx < deg; idx += 32) {
        int col = g_col[st + idx];
        float v = g_asrc2[col] + ad;
        v = (v > 0.f) ? v : 0.2f * v;
        sum += __expf(v);
    }
    sum = warpSum(sum);
    float inv = 1.f / sum;
    __syncwarp();

    int ch0 = lane * 8;
    float acc[8];
    #pragma unroll
    for (int i = 0; i < 8; i++) acc[i] = 0.f;

    int degf = deg < 128 ? deg : 128;
    for (int idx = 0; idx < degf; idx++) {
        float w  = sw[wrp][idx];
        int  col = scl[wrp][idx];
        uint4 u = *(const uint4*)(g_xp2h + (size_t)col * HID + ch0);
        float2 f0 = __half22float2(*(__half2*)&u.x);
        float2 f1 = __half22float2(*(__half2*)&u.y);
        float2 f2 = __half22float2(*(__half2*)&u.z);
        float2 f3 = __half22float2(*(__half2*)&u.w);
        acc[0] += w * f0.x; acc[1] += w * f0.y;
        acc[2] += w * f1.x; acc[3] += w * f1.y;
        acc[4] += w * f2.x; acc[5] += w * f2.y;
        acc[6] += w * f3.x; acc[7] += w * f3.y;
    }
    for (int idx = 128; idx < deg; idx++) {
        int col = g_col[st + idx];
        float v = g_asrc2[col] + ad;
        v = (v > 0.f) ? v : 0.2f * v;
        float w = __expf(v);
        uint4 u = *(const uint4*)(g_xp2h + (size_t)col * HID + ch0);
        float2 f0 = __half22float2(*(__half2*)&u.x);
        float2 f1 = __half22float2(*(__half2*)&u.y);
        float2 f2 = __half22float2(*(__half2*)&u.z);
        float2 f3 = __half22float2(*(__half2*)&u.w);
        acc[0] += w * f0.x; acc[1] += w * f0.y;
        acc[2] += w * f1.x; acc[3] += w * f1.y;
        acc[4] += w * f2.x; acc[5] += w * f2.y;
        acc[6] += w * f3.x; acc[7] += w * f3.y;
    }

    float4 ba = *(const float4*)(b2 + ch0);
    float4 bb = *(const float4*)(b2 + ch0 + 4);
    float* op = out + (size_t)n * HID + ch0;
    *(float4*)op = make_float4(acc[0] * inv + ba.x, acc[1] * inv + ba.y,
                               acc[2] * inv + ba.z, acc[3] * inv + ba.w);
    *(float4*)(op + 4) = make_float4(acc[4] * inv + bb.x, acc[5] * inv + bb.y,
                                     acc[6] * inv + bb.z, acc[7] * inv + bb.w);
}

/* ---------------- launch --------------------------------------------------- */
extern "C" void kernel_launch(void* const* d_in, const int* in_sizes, int n_in,
                              void* d_out, int out_size) {
    const float* x   = (const float*)d_in[0];
    const void*  ei  = d_in[1];
    const float* W1  = (const float*)d_in[2];
    const float* as1 = (const float*)d_in[3];
    const float* ad1 = (const float*)d_in[4];
    const float* b1  = (const float*)d_in[5];
    const float* W2  = (const float*)d_in[6];
    const float* as2 = (const float*)d_in[7];
    const float* ad2 = (const float*)d_in[8];
    const float* b2  = (const float*)d_in[9];
    float* out = (float*)d_out;

    void *p_x1h, *p_x2h, *p_as1, *p_ad1, *p_as2, *p_ad2;
    void *p_xh, *p_hh, *p_w1h, *p_w2h;
    cudaGetSymbolAddress(&p_x1h, g_xp1h);
    cudaGetSymbolAddress(&p_x2h, g_xp2h);
    cudaGetSymbolAddress(&p_as1, g_asrc1);
    cudaGetSymbolAddress(&p_ad1, g_adst1);
    cudaGetSymbolAddress(&p_as2, g_asrc2);
    cudaGetSymbolAddress(&p_ad2, g_adst2);
    cudaGetSymbolAddress(&p_xh,  gx_h);
    cudaGetSymbolAddress(&p_hh,  g_hh);
    cudaGetSymbolAddress(&p_w1h, gw1t_h);
    cudaGetSymbolAddress(&p_w2h, gw2t_h);

    cudaFuncSetAttribute(mma_gemm_kernel,
                         cudaFuncAttributeMaxDynamicSharedMemorySize, GSMEM);

    /* #1..#3: prerequisites of GEMM1 */
    {
        int n4 = N_NODES * IN_DIM / 4;
        conv_half_kernel<<<(n4 + 255) / 256, 256>>>(x, (__half*)p_xh, n4);
        trans_half_kernel<<<dim3(F1 / 32, KDIM / 32), dim3(32, 8)>>>(
            W1, (__half*)p_w1h, KDIM, F1);
    }
    init_kernel<<<NBLK, 256>>>((const int*)ei);

    /* #4: GEMM1 + fused attention, persistent (ncu capture target) */
    {
        int nTilesX = F1 / 128;
        int nTiles  = nTilesX * ((N_NODES + 127) / 128);
        int grid = nTiles < NPERS ? nTiles : NPERS;
        mma_gemm_kernel<<<grid, 256, GSMEM>>>(
            (const __half*)p_xh, (const __half*)p_w1h,
            (__half*)p_x1h, as1, ad1, (float*)p_as1, (float*)p_ad1,
            H1, N_NODES, F1, nTilesX, nTiles);
    }

    /* CSR build + W2 prep (independent of GEMM1) */
    trans_half_kernel<<<dim3(HID / 32, KDIM / 32), dim3(32, 8)>>>(
        W2, (__half*)p_w2h, KDIM, HID);
    count_kernel<<<(ET + 255) / 256, 256>>>(ei);
    bsum_kernel<<<NBLK, 256>>>();
    bscan_kernel<<<1, 128>>>();
    fscan_kernel<<<NBLK, 256>>>();
    scatter_kernel<<<(ET + 255) / 256, 256>>>(ei);

    /* layer 1 edge phase: fused softmax + aggregation */
    fused_agg1_kernel<<<(N_NODES + 7) / 8, 256>>>(b1);

    /* layer 2 */
    {
        int nTilesX = HID / 128;
        int nTiles  = nTilesX * ((N_NODES + 127) / 128);
        int grid = nTiles < NPERS ? nTiles : NPERS;
        mma_gemm_kernel<<<grid, 256, GSMEM>>>(
            (const __half*)p_hh, (const __half*)p_w2h,
            (__half*)p_x2h, as2, ad2, (float*)p_as2, (float*)p_ad2,
            1, N_NODES, HID, nTilesX, nTiles);
    }
    fused_agg2_kernel<<<(N_NODES + 7) / 8, 256>>>(b2, out);
}